// round 11
// baseline (speedup 1.0000x reference)
#include <cuda_runtime.h>
#include <cuda_bf16.h>
#include <cuda_fp16.h>
#include <math.h>
#include <stdint.h>

#define Bq 8
#define Tq 2048
#define Cq 1024
#define Hq 16
#define BTq (Bq*Tq)
#define WWq (Cq*Cq)

typedef unsigned long long ull;
static const size_t SZq = (size_t)BTq * Cq;

// ---------------------------------------------------------------------------
// Scratch (static device globals — no runtime allocation)
// ---------------------------------------------------------------------------
__device__ float g_dxa [BTq*Cq];
__device__ float g_k   [BTq*Cq];
__device__ float g_v   [BTq*Cq];
__device__ float g_r   [BTq*Cq];
__device__ float g_g   [BTq*Cq];
__device__ float g_w   [BTq*Cq];
__device__ float g_y   [BTq*Cq];

__device__ __nv_bfloat16 g_loraph[BTq*256];  // tanh(xm @ A_lora) bf16 hi/lo (padded 256)
__device__ __nv_bfloat16 g_lorapl[BTq*256];
__device__ __nv_bfloat16 g_BloraTh[5*1024*32]; // B_lora^T per branch bf16 hi/lo
__device__ __nv_bfloat16 g_BloraTl[5*1024*32];

__device__ __nv_bfloat16 g_xmh[BTq*Cq];      // xm hi/lo (bf16 split)
__device__ __nv_bfloat16 g_xml[BTq*Cq];
__device__ __nv_bfloat16 g_abh[4*BTq*Cq];    // k,v,r,g branch inputs hi
__device__ __nv_bfloat16 g_abl[4*BTq*Cq];    // lo
__device__ __nv_bfloat16 g_ygh[BTq*Cq];
__device__ __nv_bfloat16 g_ygl[BTq*Cq];
__device__ __nv_bfloat16 g_wbh[5*WWq];       // Wk,Wv,Wr,Wg,Wo hi
__device__ __nv_bfloat16 g_wbl[5*WWq];       // lo
__device__ __nv_bfloat16 g_AloraTh[256*1024];
__device__ __nv_bfloat16 g_AloraTl[256*1024];

// fp16-split td path (2^-22 residual — precision-safe for the decay scan)
__device__ __half g_xx0h[BTq*Cq];            // w_in branch hi/lo
__device__ __half g_xx0l[BTq*Cq];
__device__ __half g_tdhh[BTq*128];           // tanh(w_in @ td_A) hi/lo (padded 128)
__device__ __half g_tdhl[BTq*128];
__device__ __half g_tdATh[128*1024];
__device__ __half g_tdATl[128*1024];
__device__ __half g_tdBTh[1024*64];
__device__ __half g_tdBTl[1024*64];

// ---------------------------------------------------------------------------
// PTX helpers (sm_80+ — valid on compute_103 virtual arch)
// ---------------------------------------------------------------------------
__device__ __forceinline__ uint32_t sm2u32(const void* p){
    uint32_t a;
    asm("{ .reg .u64 t; cvta.to.shared.u64 t, %1; cvt.u32.u64 %0, t; }" : "=r"(a) : "l"(p));
    return a;
}
__device__ __forceinline__ void cpa16(uint32_t dst, const void* src){
    asm volatile("cp.async.cg.shared.global [%0], [%1], 16;" :: "r"(dst), "l"(src) : "memory");
}
__device__ __forceinline__ void cpa_commit(){
    asm volatile("cp.async.commit_group;" ::: "memory");
}
template<int N>
__device__ __forceinline__ void cpa_wait(){
    asm volatile("cp.async.wait_group %0;" :: "n"(N) : "memory");
}
__device__ __forceinline__ void ldsm_x4(uint32_t* r, uint32_t addr){
    asm volatile("ldmatrix.sync.aligned.m8n8.x4.shared.b16 {%0,%1,%2,%3}, [%4];"
        : "=r"(r[0]), "=r"(r[1]), "=r"(r[2]), "=r"(r[3]) : "r"(addr));
}
template<bool FP16>
__device__ __forceinline__ void mma_any(float* d, const uint32_t* a, const uint32_t* b){
    if (FP16){
        asm volatile("mma.sync.aligned.m16n8k16.row.col.f32.f16.f16.f32 "
            "{%0,%1,%2,%3}, {%4,%5,%6,%7}, {%8,%9}, {%0,%1,%2,%3};"
            : "+f"(d[0]), "+f"(d[1]), "+f"(d[2]), "+f"(d[3])
            : "r"(a[0]), "r"(a[1]), "r"(a[2]), "r"(a[3]), "r"(b[0]), "r"(b[1]));
    } else {
        asm volatile("mma.sync.aligned.m16n8k16.row.col.f32.bf16.bf16.f32 "
            "{%0,%1,%2,%3}, {%4,%5,%6,%7}, {%8,%9}, {%0,%1,%2,%3};"
            : "+f"(d[0]), "+f"(d[1]), "+f"(d[2]), "+f"(d[3])
            : "r"(a[0]), "r"(a[1]), "r"(a[2]), "r"(a[3]), "r"(b[0]), "r"(b[1]));
    }
}
__device__ __forceinline__ void splitv(float v, __nv_bfloat16& h, __nv_bfloat16& l){
    h = __float2bfloat16(v);
    l = __float2bfloat16(v - __bfloat162float(h));
}
__device__ __forceinline__ void splitv(float v, __half& h, __half& l){
    h = __float2half_rn(v);
    l = __float2half_rn(v - __half2float(h));
}
__device__ __forceinline__ uint16_t u16of(__half v){ return *(uint16_t*)&v; }
__device__ __forceinline__ uint16_t u16of(__nv_bfloat16 v){ return *(uint16_t*)&v; }

// ---------------------------------------------------------------------------
// split GEMM core via mma.sync (proven round-9/10 structure)
// epi: 0 none, 1 silu, 2 tanh->fp32, 3 tanh->split OT, 4 bias(e0)->fp32
// ---------------------------------------------------------------------------
#define NSTAGE    4
#define STG_ARR   6144                 // 128 rows * 48B
#define STG_BYTES 24576                // 4 arrays
#define HG_SMEM   (NSTAGE * STG_BYTES) // 98304

template<bool FP16, typename OT>
__device__ __forceinline__ void hg_core(
    const uint16_t* __restrict__ Ah, const uint16_t* __restrict__ Al,
    const uint16_t* __restrict__ Bh, const uint16_t* __restrict__ Bl,
    float* __restrict__ Cp, OT* __restrict__ Ch, OT* __restrict__ Cl,
    const float* __restrict__ e0,
    int N, int K, int lda, int ldb, int m0, int n0, int epi, char* sm)
{
    int tid = threadIdx.x, lane = tid & 31, wid = tid >> 5;
    int wy = wid & 1, wx = wid >> 1;
    uint32_t sb = sm2u32(sm);

    int arr0 = tid >> 7;
    int rowa = tid & 127;
    const uint16_t* p0 = ((arr0 == 0) ? Ah : Al) + (size_t)(m0 + rowa) * lda;
    const uint16_t* p1 = ((arr0 == 0) ? Bh : Bl) + (size_t)(n0 + rowa) * ldb;
    uint32_t so0 = (uint32_t)(arr0 * STG_ARR + rowa * 48);
    uint32_t so1 = so0 + 2 * STG_ARR;

    float acc[4][4][4];
    #pragma unroll
    for (int i = 0; i < 4; i++)
        #pragma unroll
        for (int j = 0; j < 4; j++)
            #pragma unroll
            for (int q = 0; q < 4; q++) acc[i][j][q] = 0.f;

    uint32_t a_row = (uint32_t)(wy * 64 + (lane & 15));
    uint32_t a_kh  = (uint32_t)((lane >> 4) * 8);
    uint32_t b_row0 = (uint32_t)(wx * 32 + (lane & 7) + ((lane >> 4) * 8));
    uint32_t b_kh   = (uint32_t)(((lane >> 3) & 1) * 8);

    const int NC = K >> 4;

    #pragma unroll
    for (int s = 0; s < 3; s++){
        uint32_t d = sb + (uint32_t)s * STG_BYTES;
        int kk = s * 16;
        cpa16(d + so0,      p0 + kk);  cpa16(d + so0 + 16, p0 + kk + 8);
        cpa16(d + so1,      p1 + kk);  cpa16(d + so1 + 16, p1 + kk + 8);
        cpa_commit();
    }

    #pragma unroll 4
    for (int c = 0; c < NC; c++){
        cpa_wait<2>();
        __syncthreads();
        if (c + 3 < NC){
            uint32_t d = sb + (uint32_t)((c + 3) & 3) * STG_BYTES;
            int kk = (c + 3) << 4;
            cpa16(d + so0,      p0 + kk);  cpa16(d + so0 + 16, p0 + kk + 8);
            cpa16(d + so1,      p1 + kk);  cpa16(d + so1 + 16, p1 + kk + 8);
        }
        cpa_commit();

        uint32_t base = sb + (uint32_t)(c & 3) * STG_BYTES;

        uint32_t bh[2][4], bl[2][4];
        #pragma unroll
        for (int bi = 0; bi < 2; bi++){
            uint32_t bo = base + 2*STG_ARR + (b_row0 + bi * 16) * 48 + b_kh * 2;
            ldsm_x4(bh[bi], bo);
            ldsm_x4(bl[bi], bo + STG_ARR);
        }
        #pragma unroll
        for (int mf = 0; mf < 4; mf++){
            uint32_t ah[4], al[4];
            uint32_t ao = base + (a_row + mf * 16) * 48 + a_kh * 2;
            ldsm_x4(ah, ao);
            ldsm_x4(al, ao + STG_ARR);
            #pragma unroll
            for (int nf = 0; nf < 4; nf++){
                const uint32_t* bhp = &bh[nf >> 1][(nf & 1) * 2];
                const uint32_t* blp = &bl[nf >> 1][(nf & 1) * 2];
                mma_any<FP16>(acc[mf][nf], ah, bhp);
                mma_any<FP16>(acc[mf][nf], ah, blp);
                mma_any<FP16>(acc[mf][nf], al, bhp);
            }
        }
    }

    #pragma unroll
    for (int mf = 0; mf < 4; mf++){
        int row0 = m0 + wy * 64 + mf * 16 + (lane >> 2);
        #pragma unroll
        for (int nf = 0; nf < 4; nf++){
            int col = n0 + wx * 32 + nf * 8 + (lane & 3) * 2;
            float v[4] = {acc[mf][nf][0], acc[mf][nf][1], acc[mf][nf][2], acc[mf][nf][3]};
            if (epi == 1){
                #pragma unroll
                for (int q = 0; q < 4; q++) v[q] = v[q] / (1.f + expf(-v[q]));
            } else if (epi == 2 || epi == 3){
                #pragma unroll
                for (int q = 0; q < 4; q++) v[q] = tanhf(v[q]);
            } else if (epi == 4){
                v[0] += e0[col]; v[1] += e0[col+1];
                v[2] += e0[col]; v[3] += e0[col+1];
            }
            size_t i01 = (size_t)row0 * N + col;
            size_t i23 = (size_t)(row0 + 8) * N + col;
            if (epi == 3){
                OT h[4], l[4];
                #pragma unroll
                for (int q = 0; q < 4; q++) splitv(v[q], h[q], l[q]);
                *(uint32_t*)(Ch + i01) = (uint32_t)u16of(h[0]) | ((uint32_t)u16of(h[1]) << 16);
                *(uint32_t*)(Cl + i01) = (uint32_t)u16of(l[0]) | ((uint32_t)u16of(l[1]) << 16);
                *(uint32_t*)(Ch + i23) = (uint32_t)u16of(h[2]) | ((uint32_t)u16of(h[3]) << 16);
                *(uint32_t*)(Cl + i23) = (uint32_t)u16of(l[2]) | ((uint32_t)u16of(l[3]) << 16);
            } else {
                *(float2*)(Cp + i01) = make_float2(v[0], v[1]);
                *(float2*)(Cp + i23) = make_float2(v[2], v[3]);
            }
        }
    }
}

// bf16 kernel: Cp for epi 0/1/2; Ch/Cl for epi 3
__global__ void __launch_bounds__(256, 2) hgemm_one(
    const __nv_bfloat16* __restrict__ Ah, const __nv_bfloat16* __restrict__ Al,
    const __nv_bfloat16* __restrict__ Bh, const __nv_bfloat16* __restrict__ Bl,
    float* __restrict__ Cp, __nv_bfloat16* __restrict__ Ch, __nv_bfloat16* __restrict__ Cl,
    int N, int K, int epi)
{
    extern __shared__ char sm[];
    hg_core<false, __nv_bfloat16>((const uint16_t*)Ah, (const uint16_t*)Al,
        (const uint16_t*)Bh, (const uint16_t*)Bl,
        Cp, Ch, Cl, nullptr,
        N, K, K, K, blockIdx.y * 128, blockIdx.x * 128, epi, sm);
}

__global__ void __launch_bounds__(256, 2) hgemm_kvrg(
    const __nv_bfloat16* __restrict__ abh, const __nv_bfloat16* __restrict__ abl,
    const __nv_bfloat16* __restrict__ wbh, const __nv_bfloat16* __restrict__ wbl,
    float* __restrict__ C0, float* __restrict__ C1,
    float* __restrict__ C2, float* __restrict__ C3)
{
    extern __shared__ char sm[];
    int z = blockIdx.z;
    float* Cp = (z == 0) ? C0 : (z == 1) ? C1 : (z == 2) ? C2 : C3;
    hg_core<false, __nv_bfloat16>(
        (const uint16_t*)(abh + (size_t)z * SZq), (const uint16_t*)(abl + (size_t)z * SZq),
        (const uint16_t*)(wbh + (size_t)z * WWq), (const uint16_t*)(wbl + (size_t)z * WWq),
        Cp, (__nv_bfloat16*)nullptr, (__nv_bfloat16*)nullptr, nullptr,
        Cq, Cq, Cq, Cq, blockIdx.y * 128, blockIdx.x * 128, (z == 3) ? 1 : 0, sm);
}

__global__ void __launch_bounds__(256, 2) hgemm_h(
    const __half* __restrict__ Ah, const __half* __restrict__ Al,
    const __half* __restrict__ Bh, const __half* __restrict__ Bl,
    float* __restrict__ Cp, __half* __restrict__ Ch, __half* __restrict__ Cl,
    const float* __restrict__ e0, int N, int K, int lda, int ldb, int epi)
{
    extern __shared__ char sm[];
    hg_core<true, __half>((const uint16_t*)Ah, (const uint16_t*)Al,
        (const uint16_t*)Bh, (const uint16_t*)Bl,
        Cp, Ch, Cl, e0,
        N, K, lda, ldb, blockIdx.y * 128, blockIdx.x * 128, epi, sm);
}

// ---------------------------------------------------------------------------
// mix via tensor cores: P = lora_f[128x32] @ BloraT_f[128x32]^T (bf16-split),
// fused ddlerp epilogue: out = x + dxa*(lam + P).
// K=32 entirely in smem (one load, ONE barrier), 2 x BK16 mma chunks.
// grid = (5 branches [fastest, L2 reuse of x/dxa], N/128, M/128).
// f=0 -> fp16 hi/lo xx0 (w_in); f=1..4 -> bf16 hi/lo slots 0..3 (k,v,r,g).
// ---------------------------------------------------------------------------
__global__ void __launch_bounds__(256) mix_mma(
    const __nv_bfloat16* __restrict__ lorah, const __nv_bfloat16* __restrict__ loral,
    const __nv_bfloat16* __restrict__ BTh, const __nv_bfloat16* __restrict__ BTl,
    const float* __restrict__ x, const float* __restrict__ dxa,
    const float* __restrict__ lam,
    __half* __restrict__ xx0h, __half* __restrict__ xx0l,
    __nv_bfloat16* __restrict__ abh, __nv_bfloat16* __restrict__ abl)
{
    __shared__ __align__(16) uint16_t smA[2][128*40];  // hi/lo, 80B row stride
    __shared__ __align__(16) uint16_t smB[2][128*40];

    int f = blockIdx.x;
    int n0 = blockIdx.y * 128, m0 = blockIdx.z * 128;
    int tid = threadIdx.x, lane = tid & 31, wid = tid >> 5;
    int wy = wid & 1, wx = wid >> 1;

    // load all 4 arrays: 128 rows x 32 halves each (4 x 16B chunks per row)
    #pragma unroll
    for (int t2 = 0; t2 < 2; t2++){
        int c = tid * 2 + t2;               // 0..511
        int row = c >> 2, ch = c & 3;
        size_t ga = (size_t)(m0 + row) * 256 + f * 32 + ch * 8;
        size_t gb = (size_t)f * 32768 + (size_t)(n0 + row) * 32 + ch * 8;
        uint32_t so = (uint32_t)(row * 40 + ch * 8);
        *(uint4*)(smA[0] + so) = *(const uint4*)(lorah + ga);
        *(uint4*)(smA[1] + so) = *(const uint4*)(loral + ga);
        *(uint4*)(smB[0] + so) = *(const uint4*)(BTh + gb);
        *(uint4*)(smB[1] + so) = *(const uint4*)(BTl + gb);
    }
    __syncthreads();

    float acc[4][4][4];
    #pragma unroll
    for (int i = 0; i < 4; i++)
        #pragma unroll
        for (int j = 0; j < 4; j++)
            #pragma unroll
            for (int q = 0; q < 4; q++) acc[i][j][q] = 0.f;

    uint32_t a_row = (uint32_t)(wy * 64 + (lane & 15));
    uint32_t a_kh  = (uint32_t)((lane >> 4) * 8);
    uint32_t b_row0 = (uint32_t)(wx * 32 + (lane & 7) + ((lane >> 4) * 8));
    uint32_t b_kh   = (uint32_t)(((lane >> 3) & 1) * 8);
    uint32_t bAh = sm2u32(smA[0]), bAl = sm2u32(smA[1]);
    uint32_t bBh = sm2u32(smB[0]), bBl = sm2u32(smB[1]);

    #pragma unroll
    for (int c = 0; c < 2; c++){
        uint32_t kb = (uint32_t)(c * 32);   // 16 halves = 32 bytes per chunk
        uint32_t bh[2][4], bl[2][4];
        #pragma unroll
        for (int bi = 0; bi < 2; bi++){
            uint32_t ro = (b_row0 + bi * 16) * 80 + b_kh * 2 + kb;
            ldsm_x4(bh[bi], bBh + ro);
            ldsm_x4(bl[bi], bBl + ro);
        }
        #pragma unroll
        for (int mf = 0; mf < 4; mf++){
            uint32_t ah[4], al[4];
            uint32_t ro = (a_row + mf * 16) * 80 + a_kh * 2 + kb;
            ldsm_x4(ah, bAh + ro);
            ldsm_x4(al, bAl + ro);
            #pragma unroll
            for (int nf = 0; nf < 4; nf++){
                const uint32_t* bhp = &bh[nf >> 1][(nf & 1) * 2];
                const uint32_t* blp = &bl[nf >> 1][(nf & 1) * 2];
                mma_any<false>(acc[mf][nf], ah, bhp);
                mma_any<false>(acc[mf][nf], ah, blp);
                mma_any<false>(acc[mf][nf], al, bhp);
            }
        }
    }

    const float* e2 = lam + f * Cq;
    #pragma unroll
    for (int mf = 0; mf < 4; mf++){
        int row0 = m0 + wy * 64 + mf * 16 + (lane >> 2);
        #pragma unroll
        for (int nf = 0; nf < 4; nf++){
            int col = n0 + wx * 32 + nf * 8 + (lane & 3) * 2;
            float2 lamv = *(const float2*)(e2 + col);
            size_t i01 = (size_t)row0 * Cq + col;
            size_t i23 = (size_t)(row0 + 8) * Cq + col;
            float2 x01 = *(const float2*)(x + i01);
            float2 d01 = *(const float2*)(dxa + i01);
            float2 x23 = *(const float2*)(x + i23);
            float2 d23 = *(const float2*)(dxa + i23);
            float v0 = x01.x + d01.x * (lamv.x + acc[mf][nf][0]);
            float v1 = x01.y + d01.y * (lamv.y + acc[mf][nf][1]);
            float v2 = x23.x + d23.x * (lamv.x + acc[mf][nf][2]);
            float v3 = x23.y + d23.y * (lamv.y + acc[mf][nf][3]);
            if (f == 0){
                __half h[4], l[4];
                splitv(v0, h[0], l[0]); splitv(v1, h[1], l[1]);
                splitv(v2, h[2], l[2]); splitv(v3, h[3], l[3]);
                *(uint32_t*)(xx0h + i01) = (uint32_t)u16of(h[0]) | ((uint32_t)u16of(h[1]) << 16);
                *(uint32_t*)(xx0l + i01) = (uint32_t)u16of(l[0]) | ((uint32_t)u16of(l[1]) << 16);
                *(uint32_t*)(xx0h + i23) = (uint32_t)u16of(h[2]) | ((uint32_t)u16of(h[3]) << 16);
                *(uint32_t*)(xx0l + i23) = (uint32_t)u16of(l[2]) | ((uint32_t)u16of(l[3]) << 16);
            } else {
                size_t o01 = (size_t)(f-1) * SZq + i01;
                size_t o23 = (size_t)(f-1) * SZq + i23;
                __nv_bfloat16 h[4], l[4];
                splitv(v0, h[0], l[0]); splitv(v1, h[1], l[1]);
                splitv(v2, h[2], l[2]); splitv(v3, h[3], l[3]);
                *(uint32_t*)(abh + o01) = (uint32_t)u16of(h[0]) | ((uint32_t)u16of(h[1]) << 16);
                *(uint32_t*)(abl + o01) = (uint32_t)u16of(l[0]) | ((uint32_t)u16of(l[1]) << 16);
                *(uint32_t*)(abh + o23) = (uint32_t)u16of(h[2]) | ((uint32_t)u16of(h[3]) << 16);
                *(uint32_t*)(abl + o23) = (uint32_t)u16of(l[2]) | ((uint32_t)u16of(l[3]) << 16);
            }
        }
    }
}

// ---------------------------------------------------------------------------
// prep: dxa = shift(x) - x (fp32) ; xm = x + dxa * miu_x -> bf16 hi/lo
// ---------------------------------------------------------------------------
__global__ void __launch_bounds__(256) prep_kernel(
    const float4* __restrict__ x4, const float4* __restrict__ mu4,
    float4* __restrict__ dxa4,
    __nv_bfloat16* __restrict__ xmh, __nv_bfloat16* __restrict__ xml)
{
    size_t i = (size_t)blockIdx.x * 256 + threadIdx.x;
    int m = (int)(i >> 8);
    int t = m & (Tq - 1);
    float4 xv = x4[i];
    float4 xl = make_float4(0.f, 0.f, 0.f, 0.f);
    if (t) xl = x4[i - 256];
    float4 mu = mu4[i & 255];
    float4 d  = make_float4(xl.x - xv.x, xl.y - xv.y, xl.z - xv.z, xl.w - xv.w);
    float xm0 = fmaf(d.x, mu.x, xv.x), xm1 = fmaf(d.y, mu.y, xv.y);
    float xm2 = fmaf(d.z, mu.z, xv.z), xm3 = fmaf(d.w, mu.w, xv.w);
    dxa4[i] = d;
    __nv_bfloat162 h0, l0, h1, l1;
    splitv(xm0, h0.x, l0.x); splitv(xm1, h0.y, l0.y);
    splitv(xm2, h1.x, l1.x); splitv(xm3, h1.y, l1.y);
    ((__nv_bfloat162*)xmh)[i*2]   = h0;
    ((__nv_bfloat162*)xmh)[i*2+1] = h1;
    ((__nv_bfloat162*)xml)[i*2]   = l0;
    ((__nv_bfloat162*)xml)[i*2+1] = l1;
}

// ---------------------------------------------------------------------------
// transposes: AloraT -> bf16 hi/lo; tdAT, tdBT -> fp16 hi/lo; BloraT bf16 hi/lo
// ---------------------------------------------------------------------------
__global__ void __launch_bounds__(256) transpose_all(
    __nv_bfloat16* __restrict__ AloraTh, __nv_bfloat16* __restrict__ AloraTl,
    const float* __restrict__ A_lora,
    __half* __restrict__ tdATh, __half* __restrict__ tdATl,
    const float* __restrict__ td_A,
    __half* __restrict__ tdBTh, __half* __restrict__ tdBTl,
    const float* __restrict__ td_B,
    __nv_bfloat16* __restrict__ BloraTh, __nv_bfloat16* __restrict__ BloraTl,
    const float* __restrict__ B_lora)
{
    int i = blockIdx.x * 256 + threadIdx.x;
    if (i < 262144) {
        int n = i >> 10, k = i & 1023;
        float v = (n < 160) ? A_lora[k*160 + n] : 0.f;
        __nv_bfloat16 h, l; splitv(v, h, l);
        AloraTh[i] = h; AloraTl[i] = l;
    } else if (i < 393216) {
        int j = i - 262144; int n = j >> 10, k = j & 1023;
        float v = (n < 64) ? td_A[k*64 + n] : 0.f;
        __half h, l; splitv(v, h, l);
        tdATh[j] = h; tdATl[j] = l;
    } else if (i < 458752) {
        int j = i - 393216; int n = j >> 6, k = j & 63;
        float v = td_B[k*1024 + n];
        __half h, l; splitv(v, h, l);
        tdBTh[j] = h; tdBTl[j] = l;
    } else if (i < 622592) {
        int j = i - 458752;
        int f = j >> 15, rr = j & 32767, n = rr >> 5, k = rr & 31;
        float v = B_lora[(f*32 + k)*1024 + n];
        __nv_bfloat16 h, l; splitv(v, h, l);
        BloraTh[j] = h; BloraTl[j] = l;
    }
}

// ---------------------------------------------------------------------------
// Weight bf16 hi/lo conversion (Wk,Wv,Wr,Wg,Wo)
// ---------------------------------------------------------------------------
__global__ void __launch_bounds__(256) wconv_kernel(
    const float* __restrict__ w0, const float* __restrict__ w1,
    const float* __restrict__ w2, const float* __restrict__ w3,
    const float* __restrict__ w4,
    __nv_bfloat16* __restrict__ h, __nv_bfloat16* __restrict__ l)
{
    int i = blockIdx.x * 256 + threadIdx.x;
    int w = i >> 20;
    int j = i & 1048575;
    const float* src = (w == 0) ? w0 : (w == 1) ? w1 : (w == 2) ? w2 : (w == 3) ? w3 : w4;
    float x = src[j];
    __nv_bfloat16 hh, ll; splitv(x, hh, ll);
    h[i] = hh;
    l[i] = ll;
}

// ---------------------------------------------------------------------------
// WKV6 scan — 4-buffer ring, ONE barrier per TWO timesteps (proven round-10)
// ---------------------------------------------------------------------------
__global__ void __launch_bounds__(256) wkv6_kernel(
    const float* __restrict__ rp, const float* __restrict__ kp,
    const float* __restrict__ vp, const float* __restrict__ wp,
    const float* __restrict__ up, float* __restrict__ yp)
{
    __shared__ float4 pk[4][4][17];
    __shared__ float  sv[4][64];
    int bh = blockIdx.x;
    int b = bh >> 4, h = bh & 15;
    size_t base = ((size_t)b * Tq) * Cq + h * 64;
    int tid = threadIdx.x;
    int j = tid >> 2, rg = tid & 3;
    float uu = 0.f;
    if (tid < 64) uu = up[h * 64 + tid];
    float S[16];
    #pragma unroll
    for (int i = 0; i < 16; i++) S[i] = 0.f;

    float lk0 = 0.f, lr0 = 0.f, lw0 = 0.f, lv0 = 0.f;
    float lk1 = 0.f, lr1 = 0.f, lw1 = 0.f, lv1 = 0.f;
    if (tid < 64){
        size_t o0 = base + tid;
        lk0 = kp[o0]; lr0 = rp[o0]; lw0 = wp[o0]; lv0 = vp[o0];
        size_t o1 = o0 + Cq;
        lk1 = kp[o1]; lr1 = rp[o1]; lw1 = wp[o1]; lv1 = vp[o1];
    }

    for (int t = 0; t < Tq; t += 2) {
        int b0 = t & 3, b1 = (t + 1) & 3;
        size_t off = base + (size_t)t * Cq;
        if (tid < 64) {
            sv[b0][tid] = lv0;
            pk[b0][tid >> 4][tid & 15] = make_float4(lk0, uu * lk0, lr0, expf(-expf(lw0)));
            sv[b1][tid] = lv1;
            pk[b1][tid >> 4][tid & 15] = make_float4(lk1, uu * lk1, lr1, expf(-expf(lw1)));
        }
        __syncthreads();
        if (t + 2 < Tq && tid < 64){
            size_t o2 = off + 2 * Cq + tid;
            lk0 = kp[o2]; lr0 = rp[o2]; lw0 = wp[o2]; lv0 = vp[o2];
            size_t o3 = o2 + Cq;
            lk1 = kp[o3]; lr1 = rp[o3]; lw1 = wp[o3]; lv1 = vp[o3];
        }
        {
            float vj = sv[b0][j];
            float yv = 0.f;
            #pragma unroll
            for (int ii = 0; ii < 16; ii++) {
                float4 p = pk[b0][rg][ii];
                float s = S[ii];
                yv = fmaf(p.z, fmaf(p.y, vj, s), yv);
                S[ii] = fmaf(p.w, s, p.x * vj);
            }
            yv += __shfl_xor_sync(0xffffffffu, yv, 1);
            yv += __shfl_xor_sync(0xffffffffu, yv, 2);
            if (rg == 0) yp[off + j] = yv;
        }
        {
            float vj = sv[b1][j];
            float yv = 0.f;
            #pragma unroll
            for (int ii = 0; ii < 16; ii++) {
                float4 p = pk[b1][rg][ii];
                float s = S[ii];
                yv = fmaf(p.z, fmaf(p.y, vj, s), yv);
                S[ii] = fmaf(p.w, s, p.x * vj);
            }
            yv += __shfl_xor_sync(0xffffffffu, yv, 1);
            yv += __shfl_xor_sync(0xffffffffu, yv, 2);
            if (rg == 0) yp[off + Cq + j] = yv;
        }
    }
}

// ---------------------------------------------------------------------------
// GroupNorm * gate -> bf16 hi/lo
// ---------------------------------------------------------------------------
__global__ void __launch_bounds__(256) gnorm_kernel(
    const float* __restrict__ y, const float* __restrict__ g,
    const float* __restrict__ gamma, const float* __restrict__ beta,
    __nv_bfloat16* __restrict__ ygh, __nv_bfloat16* __restrict__ ygl)
{
    int m = blockIdx.x, tid = threadIdx.x;
    size_t i4 = (size_t)m * 256 + tid;
    float4 yv = ((const float4*)y)[i4];
    float s  = yv.x + yv.y + yv.z + yv.w;
    float ss = yv.x*yv.x + yv.y*yv.y + yv.z*yv.z + yv.w*yv.w;
    #pragma unroll
    for (int o = 1; o < 16; o <<= 1) {
        s  += __shfl_xor_sync(0xffffffffu, s,  o);
        ss += __shfl_xor_sync(0xffffffffu, ss, o);
    }
    float mean = s * (1.f / 64.f);
    float var  = ss * (1.f / 64.f) - mean * mean;
    float rstd = rsqrtf(fmaxf(var, 0.f) + 1.6e-4f);
    float4 ga = ((const float4*)gamma)[tid];
    float4 be = ((const float4*)beta)[tid];
    float4 gv = ((const float4*)g)[i4];
    float o0 = ((yv.x - mean) * rstd * ga.x + be.x) * gv.x;
    float o1 = ((yv.y - mean) * rstd * ga.y + be.y) * gv.y;
    float o2 = ((yv.z - mean) * rstd * ga.z + be.z) * gv.z;
    float o3 = ((yv.w - mean) * rstd * ga.w + be.w) * gv.w;

    __nv_bfloat162 hp0, lp0, hp1, lp1;
    splitv(o0, hp0.x, lp0.x); splitv(o1, hp0.y, lp0.y);
    splitv(o2, hp1.x, lp1.x); splitv(o3, hp1.y, lp1.y);
    ((__nv_bfloat162*)ygh)[i4*2]   = hp0;
    ((__nv_bfloat162*)ygh)[i4*2+1] = hp1;
    ((__nv_bfloat162*)ygl)[i4*2]   = lp0;
    ((__nv_bfloat162*)ygl)[i4*2+1] = lp1;
}

// ---------------------------------------------------------------------------
// Launch
// ---------------------------------------------------------------------------
extern "C" void kernel_launch(void* const* d_in, const int* in_sizes, int n_in,
                              void* d_out, int out_size)
{
    (void)in_sizes; (void)n_in; (void)out_size;
    const float* x       = (const float*)d_in[0];
    const float* miu_x   = (const float*)d_in[1];
    const float* lambda_ = (const float*)d_in[2];
    const float* A_lora  = (const float*)d_in[3];
    const float* B_lora  = (const float*)d_in[4];
    const float* td_miu  = (const float*)d_in[5];
    const float* td_A    = (const float*)d_in[6];
    const float* td_B    = (const float*)d_in[7];
    const float* u       = (const float*)d_in[8];
    const float* Wr      = (const float*)d_in[9];
    const float* Wk      = (const float*)d_in[10];
    const float* Wv      = (const float*)d_in[11];
    const float* Wg      = (const float*)d_in[12];
    const float* Wo      = (const float*)d_in[13];
    const float* gamma   = (const float*)d_in[14];
    const float* beta    = (const float*)d_in[15];
    float* out = (float*)d_out;

    float *p_dxa,*p_k,*p_v,*p_r,*p_g,*p_w,*p_y;
    __nv_bfloat16 *p_xmh,*p_xml,*p_abh,*p_abl,*p_ygh,*p_ygl,*p_wbh,*p_wbl,
                  *p_AloraTh,*p_AloraTl,*p_loraph,*p_lorapl,*p_BloraTh,*p_BloraTl;
    __half *p_xx0h,*p_xx0l,*p_tdhh,*p_tdhl,*p_tdATh,*p_tdATl,*p_tdBTh,*p_tdBTl;
    { void* t;
      cudaGetSymbolAddress(&t, g_dxa);      p_dxa      = (float*)t;
      cudaGetSymbolAddress(&t, g_k);        p_k        = (float*)t;
      cudaGetSymbolAddress(&t, g_v);        p_v        = (float*)t;
      cudaGetSymbolAddress(&t, g_r);        p_r        = (float*)t;
      cudaGetSymbolAddress(&t, g_g);        p_g        = (float*)t;
      cudaGetSymbolAddress(&t, g_w);        p_w        = (float*)t;
      cudaGetSymbolAddress(&t, g_y);        p_y        = (float*)t;
      cudaGetSymbolAddress(&t, g_loraph);   p_loraph   = (__nv_bfloat16*)t;
      cudaGetSymbolAddress(&t, g_lorapl);   p_lorapl   = (__nv_bfloat16*)t;
      cudaGetSymbolAddress(&t, g_BloraTh);  p_BloraTh  = (__nv_bfloat16*)t;
      cudaGetSymbolAddress(&t, g_BloraTl);  p_BloraTl  = (__nv_bfloat16*)t;
      cudaGetSymbolAddress(&t, g_xmh);      p_xmh      = (__nv_bfloat16*)t;
      cudaGetSymbolAddress(&t, g_xml);      p_xml      = (__nv_bfloat16*)t;
      cudaGetSymbolAddress(&t, g_abh);      p_abh      = (__nv_bfloat16*)t;
      cudaGetSymbolAddress(&t, g_abl);      p_abl      = (__nv_bfloat16*)t;
      cudaGetSymbolAddress(&t, g_ygh);      p_ygh      = (__nv_bfloat16*)t;
      cudaGetSymbolAddress(&t, g_ygl);      p_ygl      = (__nv_bfloat16*)t;
      cudaGetSymbolAddress(&t, g_wbh);      p_wbh      = (__nv_bfloat16*)t;
      cudaGetSymbolAddress(&t, g_wbl);      p_wbl      = (__nv_bfloat16*)t;
      cudaGetSymbolAddress(&t, g_AloraTh);  p_AloraTh  = (__nv_bfloat16*)t;
      cudaGetSymbolAddress(&t, g_AloraTl);  p_AloraTl  = (__nv_bfloat16*)t;
      cudaGetSymbolAddress(&t, g_xx0h);     p_xx0h     = (__half*)t;
      cudaGetSymbolAddress(&t, g_xx0l);     p_xx0l     = (__half*)t;
      cudaGetSymbolAddress(&t, g_tdhh);     p_tdhh     = (__half*)t;
      cudaGetSymbolAddress(&t, g_tdhl);     p_tdhl     = (__half*)t;
      cudaGetSymbolAddress(&t, g_tdATh);    p_tdATh    = (__half*)t;
      cudaGetSymbolAddress(&t, g_tdATl);    p_tdATl    = (__half*)t;
      cudaGetSymbolAddress(&t, g_tdBTh);    p_tdBTh    = (__half*)t;
      cudaGetSymbolAddress(&t, g_tdBTl);    p_tdBTl    = (__half*)t;
    }

    cudaFuncSetAttribute(hgemm_one,  cudaFuncAttributeMaxDynamicSharedMemorySize, HG_SMEM);
    cudaFuncSetAttribute(hgemm_kvrg, cudaFuncAttributeMaxDynamicSharedMemorySize, HG_SMEM);
    cudaFuncSetAttribute(hgemm_h,    cudaFuncAttributeMaxDynamicSharedMemorySize, HG_SMEM);

    // 0: token shift + static lerp (xm -> bf16 hi/lo)
    prep_kernel<<<BTq * Cq / 4 / 256, 256>>>((const float4*)x, (const float4*)miu_x,
                                             (float4*)p_dxa, p_xmh, p_xml);
    // 1: weight transposes
    transpose_all<<<(622592 + 255) / 256, 256>>>(p_AloraTh, p_AloraTl, A_lora,
                                                 p_tdATh, p_tdATl, td_A,
                                                 p_tdBTh, p_tdBTl, td_B,
                                                 p_BloraTh, p_BloraTl, B_lora);
    // 2: lora_h = tanh(xm @ A_lora) -> bf16 hi/lo
    hgemm_one<<<dim3(2, 128), 256, HG_SMEM>>>(p_xmh, p_xml, p_AloraTh, p_AloraTl,
                                              nullptr, p_loraph, p_lorapl, 256, Cq, 3);
    // 3: ddlerp mix on tensor cores (f=0 -> fp16 xx0; f=1..4 -> bf16 k,v,r,g)
    mix_mma<<<dim3(5, 8, 128), 256>>>(p_loraph, p_lorapl, p_BloraTh, p_BloraTl,
                                      x, p_dxa, lambda_,
                                      p_xx0h, p_xx0l, p_abh, p_abl);
    // 4: big weight hi/lo
    wconv_kernel<<<5 * 1048576 / 256, 256>>>(Wk, Wv, Wr, Wg, Wo, p_wbh, p_wbl);
    // 5: merged projections k, v, r, g
    hgemm_kvrg<<<dim3(8, 128, 4), 256, HG_SMEM>>>(p_abh, p_abl, p_wbh, p_wbl,
                                                  p_k, p_v, p_r, p_g);
    // 6: tdh = tanh(w_in @ td_A) -> fp16 hi/lo (padded N=128)
    hgemm_h<<<dim3(1, 128), 256, HG_SMEM>>>(p_xx0h, p_xx0l, p_tdATh, p_tdATl,
                                            nullptr, p_tdhh, p_tdhl, nullptr,
                                            128, Cq, Cq, Cq, 3);
    // 7: w = td_miu + tdh @ td_B   (A stride 128, K=64)
    hgemm_h<<<dim3(8, 128), 256, HG_SMEM>>>(p_tdhh, p_tdhl, p_tdBTh, p_tdBTl,
                                            p_w, nullptr, nullptr, td_miu,
                                            Cq, 64, 128, 64, 4);
    // 8: WKV6 scan
    wkv6_kernel<<<Bq * Hq, 256>>>(p_r, p_k, p_v, p_w, u, p_y);
    // 9: GroupNorm * gate -> bf16 hi/lo
    gnorm_kernel<<<BTq, 256>>>(p_y, p_g, gamma, beta, p_ygh, p_ygl);
    // 10: output projection
    hgemm_one<<<dim3(8, 128), 256, HG_SMEM>>>(p_ygh, p_ygl, p_wbh + 4*WWq, p_wbl + 4*WWq,
                                              out, nullptr, nullptr, Cq, Cq, 0);
}

// round 12
// speedup vs baseline: 1.4811x; 1.4811x over previous
#include <cuda_runtime.h>
#include <cuda_bf16.h>
#include <cuda_fp16.h>
#include <math.h>
#include <stdint.h>

#define Bq 8
#define Tq 2048
#define Cq 1024
#define Hq 16
#define BTq (Bq*Tq)
#define WWq (Cq*Cq)

typedef unsigned long long ull;
static const size_t SZq = (size_t)BTq * Cq;

// ---------------------------------------------------------------------------
// Scratch (static device globals — no runtime allocation)
// ---------------------------------------------------------------------------
__device__ float g_dxa [BTq*Cq];
__device__ float g_k   [BTq*Cq];
__device__ float g_v   [BTq*Cq];
__device__ float g_r   [BTq*Cq];
__device__ float g_g   [BTq*Cq];
__device__ float g_w   [BTq*Cq];
__device__ float g_y   [BTq*Cq];
__device__ float g_lorap [BTq*256];          // tanh(xm @ A_lora) fp32 (padded 256)
__device__ float g_BloraT[5*1024*32];        // B_lora^T per branch, fp32

__device__ __nv_bfloat16 g_xmh[BTq*Cq];      // xm hi/lo (bf16 split)
__device__ __nv_bfloat16 g_xml[BTq*Cq];
__device__ __nv_bfloat16 g_abh[4*BTq*Cq];    // k,v,r,g branch inputs hi
__device__ __nv_bfloat16 g_abl[4*BTq*Cq];    // lo
__device__ __nv_bfloat16 g_ygh[BTq*Cq];
__device__ __nv_bfloat16 g_ygl[BTq*Cq];
__device__ __nv_bfloat16 g_wbh[5*WWq];       // Wk,Wv,Wr,Wg,Wo hi
__device__ __nv_bfloat16 g_wbl[5*WWq];       // lo
__device__ __nv_bfloat16 g_AloraTh[256*1024];
__device__ __nv_bfloat16 g_AloraTl[256*1024];

// fp16-split td path (2^-22 residual — precision-safe for the decay scan)
__device__ __half g_xx0h[BTq*Cq];            // w_in branch hi/lo
__device__ __half g_xx0l[BTq*Cq];
__device__ __half g_tdhh[BTq*128];           // tanh(w_in @ td_A) hi/lo (padded 128)
__device__ __half g_tdhl[BTq*128];
__device__ __half g_tdATh[128*1024];
__device__ __half g_tdATl[128*1024];
__device__ __half g_tdBTh[1024*64];
__device__ __half g_tdBTl[1024*64];

// ---------------------------------------------------------------------------
// PTX helpers (sm_80+ — valid on compute_103 virtual arch)
// ---------------------------------------------------------------------------
__device__ __forceinline__ uint32_t sm2u32(const void* p){
    uint32_t a;
    asm("{ .reg .u64 t; cvta.to.shared.u64 t, %1; cvt.u32.u64 %0, t; }" : "=r"(a) : "l"(p));
    return a;
}
__device__ __forceinline__ void cpa16(uint32_t dst, const void* src){
    asm volatile("cp.async.cg.shared.global [%0], [%1], 16;" :: "r"(dst), "l"(src) : "memory");
}
__device__ __forceinline__ void cpa_commit(){
    asm volatile("cp.async.commit_group;" ::: "memory");
}
template<int N>
__device__ __forceinline__ void cpa_wait(){
    asm volatile("cp.async.wait_group %0;" :: "n"(N) : "memory");
}
__device__ __forceinline__ void ldsm_x4(uint32_t* r, uint32_t addr){
    asm volatile("ldmatrix.sync.aligned.m8n8.x4.shared.b16 {%0,%1,%2,%3}, [%4];"
        : "=r"(r[0]), "=r"(r[1]), "=r"(r[2]), "=r"(r[3]) : "r"(addr));
}
template<bool FP16>
__device__ __forceinline__ void mma_any(float* d, const uint32_t* a, const uint32_t* b){
    if (FP16){
        asm volatile("mma.sync.aligned.m16n8k16.row.col.f32.f16.f16.f32 "
            "{%0,%1,%2,%3}, {%4,%5,%6,%7}, {%8,%9}, {%0,%1,%2,%3};"
            : "+f"(d[0]), "+f"(d[1]), "+f"(d[2]), "+f"(d[3])
            : "r"(a[0]), "r"(a[1]), "r"(a[2]), "r"(a[3]), "r"(b[0]), "r"(b[1]));
    } else {
        asm volatile("mma.sync.aligned.m16n8k16.row.col.f32.bf16.bf16.f32 "
            "{%0,%1,%2,%3}, {%4,%5,%6,%7}, {%8,%9}, {%0,%1,%2,%3};"
            : "+f"(d[0]), "+f"(d[1]), "+f"(d[2]), "+f"(d[3])
            : "r"(a[0]), "r"(a[1]), "r"(a[2]), "r"(a[3]), "r"(b[0]), "r"(b[1]));
    }
}
__device__ __forceinline__ void splitv(float v, __nv_bfloat16& h, __nv_bfloat16& l){
    h = __float2bfloat16(v);
    l = __float2bfloat16(v - __bfloat162float(h));
}
__device__ __forceinline__ void splitv(float v, __half& h, __half& l){
    h = __float2half_rn(v);
    l = __float2half_rn(v - __half2float(h));
}
__device__ __forceinline__ uint16_t u16of(__half v){ return *(uint16_t*)&v; }
__device__ __forceinline__ uint16_t u16of(__nv_bfloat16 v){ return *(uint16_t*)&v; }

// ---------------------------------------------------------------------------
// split GEMM core via mma.sync (proven round-9 structure)
// ---------------------------------------------------------------------------
#define NSTAGE    4
#define STG_ARR   6144                 // 128 rows * 48B
#define STG_BYTES 24576                // 4 arrays
#define HG_SMEM   (NSTAGE * STG_BYTES) // 98304

template<bool FP16, typename OT>
__device__ __forceinline__ void hg_core(
    const uint16_t* __restrict__ Ah, const uint16_t* __restrict__ Al,
    const uint16_t* __restrict__ Bh, const uint16_t* __restrict__ Bl,
    float* __restrict__ Cp, OT* __restrict__ Ch, OT* __restrict__ Cl,
    const float* __restrict__ e0,
    int N, int K, int lda, int ldb, int m0, int n0, int epi, char* sm)
{
    int tid = threadIdx.x, lane = tid & 31, wid = tid >> 5;
    int wy = wid & 1, wx = wid >> 1;
    uint32_t sb = sm2u32(sm);

    int arr0 = tid >> 7;
    int rowa = tid & 127;
    const uint16_t* p0 = ((arr0 == 0) ? Ah : Al) + (size_t)(m0 + rowa) * lda;
    const uint16_t* p1 = ((arr0 == 0) ? Bh : Bl) + (size_t)(n0 + rowa) * ldb;
    uint32_t so0 = (uint32_t)(arr0 * STG_ARR + rowa * 48);
    uint32_t so1 = so0 + 2 * STG_ARR;

    float acc[4][4][4];
    #pragma unroll
    for (int i = 0; i < 4; i++)
        #pragma unroll
        for (int j = 0; j < 4; j++)
            #pragma unroll
            for (int q = 0; q < 4; q++) acc[i][j][q] = 0.f;

    uint32_t a_row = (uint32_t)(wy * 64 + (lane & 15));
    uint32_t a_kh  = (uint32_t)((lane >> 4) * 8);
    uint32_t b_row0 = (uint32_t)(wx * 32 + (lane & 7) + ((lane >> 4) * 8));
    uint32_t b_kh   = (uint32_t)(((lane >> 3) & 1) * 8);

    const int NC = K >> 4;

    #pragma unroll
    for (int s = 0; s < 3; s++){
        uint32_t d = sb + (uint32_t)s * STG_BYTES;
        int kk = s * 16;
        cpa16(d + so0,      p0 + kk);  cpa16(d + so0 + 16, p0 + kk + 8);
        cpa16(d + so1,      p1 + kk);  cpa16(d + so1 + 16, p1 + kk + 8);
        cpa_commit();
    }

    #pragma unroll 4
    for (int c = 0; c < NC; c++){
        cpa_wait<2>();
        __syncthreads();
        if (c + 3 < NC){
            uint32_t d = sb + (uint32_t)((c + 3) & 3) * STG_BYTES;
            int kk = (c + 3) << 4;
            cpa16(d + so0,      p0 + kk);  cpa16(d + so0 + 16, p0 + kk + 8);
            cpa16(d + so1,      p1 + kk);  cpa16(d + so1 + 16, p1 + kk + 8);
        }
        cpa_commit();

        uint32_t base = sb + (uint32_t)(c & 3) * STG_BYTES;

        uint32_t bh[2][4], bl[2][4];
        #pragma unroll
        for (int bi = 0; bi < 2; bi++){
            uint32_t bo = base + 2*STG_ARR + (b_row0 + bi * 16) * 48 + b_kh * 2;
            ldsm_x4(bh[bi], bo);
            ldsm_x4(bl[bi], bo + STG_ARR);
        }
        #pragma unroll
        for (int mf = 0; mf < 4; mf++){
            uint32_t ah[4], al[4];
            uint32_t ao = base + (a_row + mf * 16) * 48 + a_kh * 2;
            ldsm_x4(ah, ao);
            ldsm_x4(al, ao + STG_ARR);
            #pragma unroll
            for (int nf = 0; nf < 4; nf++){
                const uint32_t* bhp = &bh[nf >> 1][(nf & 1) * 2];
                const uint32_t* blp = &bl[nf >> 1][(nf & 1) * 2];
                mma_any<FP16>(acc[mf][nf], ah, bhp);
                mma_any<FP16>(acc[mf][nf], ah, blp);
                mma_any<FP16>(acc[mf][nf], al, bhp);
            }
        }
    }

    #pragma unroll
    for (int mf = 0; mf < 4; mf++){
        int row0 = m0 + wy * 64 + mf * 16 + (lane >> 2);
        #pragma unroll
        for (int nf = 0; nf < 4; nf++){
            int col = n0 + wx * 32 + nf * 8 + (lane & 3) * 2;
            float v[4] = {acc[mf][nf][0], acc[mf][nf][1], acc[mf][nf][2], acc[mf][nf][3]};
            if (epi == 1){
                #pragma unroll
                for (int q = 0; q < 4; q++) v[q] = v[q] / (1.f + expf(-v[q]));
            } else if (epi == 2 || epi == 3){
                #pragma unroll
                for (int q = 0; q < 4; q++) v[q] = tanhf(v[q]);
            } else if (epi == 4){
                v[0] += e0[col]; v[1] += e0[col+1];
                v[2] += e0[col]; v[3] += e0[col+1];
            }
            size_t i01 = (size_t)row0 * N + col;
            size_t i23 = (size_t)(row0 + 8) * N + col;
            if (epi == 3){
                OT h[4], l[4];
                #pragma unroll
                for (int q = 0; q < 4; q++) splitv(v[q], h[q], l[q]);
                *(uint32_t*)(Ch + i01) = (uint32_t)u16of(h[0]) | ((uint32_t)u16of(h[1]) << 16);
                *(uint32_t*)(Cl + i01) = (uint32_t)u16of(l[0]) | ((uint32_t)u16of(l[1]) << 16);
                *(uint32_t*)(Ch + i23) = (uint32_t)u16of(h[2]) | ((uint32_t)u16of(h[3]) << 16);
                *(uint32_t*)(Cl + i23) = (uint32_t)u16of(l[2]) | ((uint32_t)u16of(l[3]) << 16);
            } else {
                *(float2*)(Cp + i01) = make_float2(v[0], v[1]);
                *(float2*)(Cp + i23) = make_float2(v[2], v[3]);
            }
        }
    }
}

__global__ void __launch_bounds__(256, 2) hgemm_one(
    const __nv_bfloat16* __restrict__ Ah, const __nv_bfloat16* __restrict__ Al,
    const __nv_bfloat16* __restrict__ Bh, const __nv_bfloat16* __restrict__ Bl,
    float* __restrict__ Cp, int N, int K, int epi)
{
    extern __shared__ char sm[];
    hg_core<false, __nv_bfloat16>((const uint16_t*)Ah, (const uint16_t*)Al,
        (const uint16_t*)Bh, (const uint16_t*)Bl,
        Cp, (__nv_bfloat16*)nullptr, (__nv_bfloat16*)nullptr, nullptr,
        N, K, K, K, blockIdx.y * 128, blockIdx.x * 128, epi, sm);
}

__global__ void __launch_bounds__(256, 2) hgemm_kvrg(
    const __nv_bfloat16* __restrict__ abh, const __nv_bfloat16* __restrict__ abl,
    const __nv_bfloat16* __restrict__ wbh, const __nv_bfloat16* __restrict__ wbl,
    float* __restrict__ C0, float* __restrict__ C1,
    float* __restrict__ C2, float* __restrict__ C3)
{
    extern __shared__ char sm[];
    int z = blockIdx.z;
    float* Cp = (z == 0) ? C0 : (z == 1) ? C1 : (z == 2) ? C2 : C3;
    hg_core<false, __nv_bfloat16>(
        (const uint16_t*)(abh + (size_t)z * SZq), (const uint16_t*)(abl + (size_t)z * SZq),
        (const uint16_t*)(wbh + (size_t)z * WWq), (const uint16_t*)(wbl + (size_t)z * WWq),
        Cp, (__nv_bfloat16*)nullptr, (__nv_bfloat16*)nullptr, nullptr,
        Cq, Cq, Cq, Cq, blockIdx.y * 128, blockIdx.x * 128, (z == 3) ? 1 : 0, sm);
}

__global__ void __launch_bounds__(256, 2) hgemm_h(
    const __half* __restrict__ Ah, const __half* __restrict__ Al,
    const __half* __restrict__ Bh, const __half* __restrict__ Bl,
    float* __restrict__ Cp, __half* __restrict__ Ch, __half* __restrict__ Cl,
    const float* __restrict__ e0, int N, int K, int lda, int ldb, int epi)
{
    extern __shared__ char sm[];
    hg_core<true, __half>((const uint16_t*)Ah, (const uint16_t*)Al,
        (const uint16_t*)Bh, (const uint16_t*)Bl,
        Cp, Ch, Cl, e0,
        N, K, lda, ldb, blockIdx.y * 128, blockIdx.x * 128, epi, sm);
}

// ---------------------------------------------------------------------------
// FFMA2 helpers
// ---------------------------------------------------------------------------
__device__ __forceinline__ void fma2(ull& d, ull a, ull b){
    asm("fma.rn.f32x2 %0, %1, %2, %0;" : "+l"(d) : "l"(a), "l"(b));
}
__device__ __forceinline__ float2 unp(ull v){
    float2 r; asm("mov.b64 {%0, %1}, %2;" : "=f"(r.x), "=f"(r.y) : "l"(v)); return r;
}

// ---------------------------------------------------------------------------
// ddlerp MIX GEMM (K=32), SINGLE load phase (all K in smem), ONE barrier.
// f = blockIdx.x (fastest) for L2 reuse of x/dxa.
// f=0 -> fp16 hi/lo xx0 (w_in); f=1..4 -> bf16 hi/lo slots 0..3 (k,v,r,g).
// ---------------------------------------------------------------------------
__global__ void __launch_bounds__(256) mix_gemm(
    const float* __restrict__ lorap, const float* __restrict__ BloraT,
    const float* __restrict__ x, const float* __restrict__ dxa,
    const float* __restrict__ lam,
    __half* __restrict__ xx0h, __half* __restrict__ xx0l,
    __nv_bfloat16* __restrict__ abh, __nv_bfloat16* __restrict__ abl)
{
    __shared__ __align__(16) float As2[32][256];   // 32 KB (A duplicated)
    __shared__ __align__(16) float Bs [32][128];   // 16 KB

    int f = blockIdx.x;
    const float* A  = lorap  + f*32;
    const float* Bm = BloraT + f*32768;
    const float* e2 = lam    + f*Cq;

    int tid  = threadIdx.x;
    int m0   = blockIdx.y * 128, n0 = blockIdx.z * 128;
    int ty = tid >> 4, tx = tid & 15;

    // single load phase: 4 float4 of A + 4 float4 of B per thread
    #pragma unroll
    for (int t2 = 0; t2 < 4; t2++){
        int i = t2 * 256 + tid;          // 0..1023
        int row = i >> 3, q = (i & 7) * 4;
        float4 av = *(const float4*)(A + (size_t)(m0 + row) * 256 + q);
        *(float2*)&As2[q+0][2*row] = make_float2(av.x, av.x);
        *(float2*)&As2[q+1][2*row] = make_float2(av.y, av.y);
        *(float2*)&As2[q+2][2*row] = make_float2(av.z, av.z);
        *(float2*)&As2[q+3][2*row] = make_float2(av.w, av.w);
        float4 bv = *(const float4*)(Bm + (size_t)(n0 + row) * 32 + q);
        Bs[q+0][row] = bv.x;
        Bs[q+1][row] = bv.y;
        Bs[q+2][row] = bv.z;
        Bs[q+3][row] = bv.w;
    }
    __syncthreads();

    ull acc[8][4];
    #pragma unroll
    for (int i = 0; i < 8; i++)
        #pragma unroll
        for (int p = 0; p < 4; p++) acc[i][p] = 0ull;

    #pragma unroll 8
    for (int kk = 0; kk < 32; kk++) {
        const ull* ar = (const ull*)As2[kk];
        const ull* br = (const ull*)Bs[kk];
        ull a_[8], b_[4];
        #pragma unroll
        for (int i = 0; i < 8; i++) a_[i] = ar[ty*8 + i];
        #pragma unroll
        for (int p = 0; p < 4; p++) b_[p] = br[tx*4 + p];
        #pragma unroll
        for (int i = 0; i < 8; i++)
            #pragma unroll
            for (int p = 0; p < 4; p++) fma2(acc[i][p], a_[i], b_[p]);
    }

    #pragma unroll
    for (int i = 0; i < 8; i++) {
        size_t m = (size_t)(m0 + ty*8 + i);
        #pragma unroll
        for (int p = 0; p < 4; p++) {
            float2 vv = unp(acc[i][p]);
            int n = n0 + tx*8 + 2*p;
            size_t idx = m * (size_t)Cq + n;
            float vx = x[idx]   + dxa[idx]   * (e2[n]   + vv.x);
            float vy = x[idx+1] + dxa[idx+1] * (e2[n+1] + vv.y);
            if (f == 0) {
                __half hx, lx, hy, ly;
                splitv(vx, hx, lx); splitv(vy, hy, ly);
                __half2 hp; hp.x = hx; hp.y = hy;
                __half2 lp; lp.x = lx; lp.y = ly;
                *(__half2*)(xx0h + idx) = hp;
                *(__half2*)(xx0l + idx) = lp;
            } else {
                size_t o = (size_t)(f-1) * SZq + idx;
                __nv_bfloat162 hp, lp;
                splitv(vx, hp.x, lp.x);
                splitv(vy, hp.y, lp.y);
                *(__nv_bfloat162*)(abh + o) = hp;
                *(__nv_bfloat162*)(abl + o) = lp;
            }
        }
    }
}

// ---------------------------------------------------------------------------
// prep: dxa = shift(x) - x (fp32) ; xm = x + dxa * miu_x -> bf16 hi/lo
// ---------------------------------------------------------------------------
__global__ void __launch_bounds__(256) prep_kernel(
    const float4* __restrict__ x4, const float4* __restrict__ mu4,
    float4* __restrict__ dxa4,
    __nv_bfloat16* __restrict__ xmh, __nv_bfloat16* __restrict__ xml)
{
    size_t i = (size_t)blockIdx.x * 256 + threadIdx.x;
    int m = (int)(i >> 8);
    int t = m & (Tq - 1);
    float4 xv = x4[i];
    float4 xl = make_float4(0.f, 0.f, 0.f, 0.f);
    if (t) xl = x4[i - 256];
    float4 mu = mu4[i & 255];
    float4 d  = make_float4(xl.x - xv.x, xl.y - xv.y, xl.z - xv.z, xl.w - xv.w);
    float xm0 = fmaf(d.x, mu.x, xv.x), xm1 = fmaf(d.y, mu.y, xv.y);
    float xm2 = fmaf(d.z, mu.z, xv.z), xm3 = fmaf(d.w, mu.w, xv.w);
    dxa4[i] = d;
    __nv_bfloat162 h0, l0, h1, l1;
    splitv(xm0, h0.x, l0.x); splitv(xm1, h0.y, l0.y);
    splitv(xm2, h1.x, l1.x); splitv(xm3, h1.y, l1.y);
    ((__nv_bfloat162*)xmh)[i*2]   = h0;
    ((__nv_bfloat162*)xmh)[i*2+1] = h1;
    ((__nv_bfloat162*)xml)[i*2]   = l0;
    ((__nv_bfloat162*)xml)[i*2+1] = l1;
}

// ---------------------------------------------------------------------------
// transposes: AloraT -> bf16 hi/lo; tdAT, tdBT -> fp16 hi/lo; BloraT fp32
// ---------------------------------------------------------------------------
__global__ void __launch_bounds__(256) transpose_all(
    __nv_bfloat16* __restrict__ AloraTh, __nv_bfloat16* __restrict__ AloraTl,
    const float* __restrict__ A_lora,
    __half* __restrict__ tdATh, __half* __restrict__ tdATl,
    const float* __restrict__ td_A,
    __half* __restrict__ tdBTh, __half* __restrict__ tdBTl,
    const float* __restrict__ td_B,
    float* __restrict__ BloraT, const float* __restrict__ B_lora)
{
    int i = blockIdx.x * 256 + threadIdx.x;
    if (i < 262144) {
        int n = i >> 10, k = i & 1023;
        float v = (n < 160) ? A_lora[k*160 + n] : 0.f;
        __nv_bfloat16 h, l; splitv(v, h, l);
        AloraTh[i] = h; AloraTl[i] = l;
    } else if (i < 393216) {
        int j = i - 262144; int n = j >> 10, k = j & 1023;
        float v = (n < 64) ? td_A[k*64 + n] : 0.f;
        __half h, l; splitv(v, h, l);
        tdATh[j] = h; tdATl[j] = l;
    } else if (i < 458752) {
        int j = i - 393216; int n = j >> 6, k = j & 63;
        float v = td_B[k*1024 + n];
        __half h, l; splitv(v, h, l);
        tdBTh[j] = h; tdBTl[j] = l;
    } else if (i < 622592) {
        int j = i - 458752;
        int f = j >> 15, rr = j & 32767, n = rr >> 5, k = rr & 31;
        BloraT[j] = B_lora[(f*32 + k)*1024 + n];
    }
}

// ---------------------------------------------------------------------------
// Weight bf16 hi/lo conversion (Wk,Wv,Wr,Wg,Wo)
// ---------------------------------------------------------------------------
__global__ void __launch_bounds__(256) wconv_kernel(
    const float* __restrict__ w0, const float* __restrict__ w1,
    const float* __restrict__ w2, const float* __restrict__ w3,
    const float* __restrict__ w4,
    __nv_bfloat16* __restrict__ h, __nv_bfloat16* __restrict__ l)
{
    int i = blockIdx.x * 256 + threadIdx.x;
    int w = i >> 20;
    int j = i & 1048575;
    const float* src = (w == 0) ? w0 : (w == 1) ? w1 : (w == 2) ? w2 : (w == 3) ? w3 : w4;
    float x = src[j];
    __nv_bfloat16 hh, ll; splitv(x, hh, ll);
    h[i] = hh;
    l[i] = ll;
}

// ---------------------------------------------------------------------------
// WKV6 scan — 4-buffer ring, ONE barrier per TWO timesteps; t+2/t+3 loads
// overlap compute of t/t+1.
// ---------------------------------------------------------------------------
__global__ void __launch_bounds__(256) wkv6_kernel(
    const float* __restrict__ rp, const float* __restrict__ kp,
    const float* __restrict__ vp, const float* __restrict__ wp,
    const float* __restrict__ up, float* __restrict__ yp)
{
    __shared__ float4 pk[4][4][17];
    __shared__ float  sv[4][64];
    int bh = blockIdx.x;
    int b = bh >> 4, h = bh & 15;
    size_t base = ((size_t)b * Tq) * Cq + h * 64;
    int tid = threadIdx.x;
    int j = tid >> 2, rg = tid & 3;
    float uu = 0.f;
    if (tid < 64) uu = up[h * 64 + tid];
    float S[16];
    #pragma unroll
    for (int i = 0; i < 16; i++) S[i] = 0.f;

    float lk0 = 0.f, lr0 = 0.f, lw0 = 0.f, lv0 = 0.f;
    float lk1 = 0.f, lr1 = 0.f, lw1 = 0.f, lv1 = 0.f;
    if (tid < 64){
        size_t o0 = base + tid;
        lk0 = kp[o0]; lr0 = rp[o0]; lw0 = wp[o0]; lv0 = vp[o0];
        size_t o1 = o0 + Cq;
        lk1 = kp[o1]; lr1 = rp[o1]; lw1 = wp[o1]; lv1 = vp[o1];
    }

    for (int t = 0; t < Tq; t += 2) {
        int b0 = t & 3, b1 = (t + 1) & 3;
        size_t off = base + (size_t)t * Cq;
        if (tid < 64) {
            sv[b0][tid] = lv0;
            pk[b0][tid >> 4][tid & 15] = make_float4(lk0, uu * lk0, lr0, expf(-expf(lw0)));
            sv[b1][tid] = lv1;
            pk[b1][tid >> 4][tid & 15] = make_float4(lk1, uu * lk1, lr1, expf(-expf(lw1)));
        }
        __syncthreads();
        if (t + 2 < Tq && tid < 64){
            size_t o2 = off + 2 * Cq + tid;
            lk0 = kp[o2]; lr0 = rp[o2]; lw0 = wp[o2]; lv0 = vp[o2];
            size_t o3 = o2 + Cq;
            lk1 = kp[o3]; lr1 = rp[o3]; lw1 = wp[o3]; lv1 = vp[o3];
        }
        // step t
        {
            float vj = sv[b0][j];
            float yv = 0.f;
            #pragma unroll
            for (int ii = 0; ii < 16; ii++) {
                float4 p = pk[b0][rg][ii];
                float s = S[ii];
                yv = fmaf(p.z, fmaf(p.y, vj, s), yv);
                S[ii] = fmaf(p.w, s, p.x * vj);
            }
            yv += __shfl_xor_sync(0xffffffffu, yv, 1);
            yv += __shfl_xor_sync(0xffffffffu, yv, 2);
            if (rg == 0) yp[off + j] = yv;
        }
        // step t+1
        {
            float vj = sv[b1][j];
            float yv = 0.f;
            #pragma unroll
            for (int ii = 0; ii < 16; ii++) {
                float4 p = pk[b1][rg][ii];
                float s = S[ii];
                yv = fmaf(p.z, fmaf(p.y, vj, s), yv);
                S[ii] = fmaf(p.w, s, p.x * vj);
            }
            yv += __shfl_xor_sync(0xffffffffu, yv, 1);
            yv += __shfl_xor_sync(0xffffffffu, yv, 2);
            if (rg == 0) yp[off + Cq + j] = yv;
        }
    }
}

// ---------------------------------------------------------------------------
// GroupNorm * gate -> bf16 hi/lo
// ---------------------------------------------------------------------------
__global__ void __launch_bounds__(256) gnorm_kernel(
    const float* __restrict__ y, const float* __restrict__ g,
    const float* __restrict__ gamma, const float* __restrict__ beta,
    __nv_bfloat16* __restrict__ ygh, __nv_bfloat16* __restrict__ ygl)
{
    int m = blockIdx.x, tid = threadIdx.x;
    size_t i4 = (size_t)m * 256 + tid;
    float4 yv = ((const float4*)y)[i4];
    float s  = yv.x + yv.y + yv.z + yv.w;
    float ss = yv.x*yv.x + yv.y*yv.y + yv.z*yv.z + yv.w*yv.w;
    #pragma unroll
    for (int o = 1; o < 16; o <<= 1) {
        s  += __shfl_xor_sync(0xffffffffu, s,  o);
        ss += __shfl_xor_sync(0xffffffffu, ss, o);
    }
    float mean = s * (1.f / 64.f);
    float var  = ss * (1.f / 64.f) - mean * mean;
    float rstd = rsqrtf(fmaxf(var, 0.f) + 1.6e-4f);
    float4 ga = ((const float4*)gamma)[tid];
    float4 be = ((const float4*)beta)[tid];
    float4 gv = ((const float4*)g)[i4];
    float o0 = ((yv.x - mean) * rstd * ga.x + be.x) * gv.x;
    float o1 = ((yv.y - mean) * rstd * ga.y + be.y) * gv.y;
    float o2 = ((yv.z - mean) * rstd * ga.z + be.z) * gv.z;
    float o3 = ((yv.w - mean) * rstd * ga.w + be.w) * gv.w;

    __nv_bfloat162 hp0, lp0, hp1, lp1;
    splitv(o0, hp0.x, lp0.x); splitv(o1, hp0.y, lp0.y);
    splitv(o2, hp1.x, lp1.x); splitv(o3, hp1.y, lp1.y);
    ((__nv_bfloat162*)ygh)[i4*2]   = hp0;
    ((__nv_bfloat162*)ygh)[i4*2+1] = hp1;
    ((__nv_bfloat162*)ygl)[i4*2]   = lp0;
    ((__nv_bfloat162*)ygl)[i4*2+1] = lp1;
}

// ---------------------------------------------------------------------------
// Launch
// ---------------------------------------------------------------------------
extern "C" void kernel_launch(void* const* d_in, const int* in_sizes, int n_in,
                              void* d_out, int out_size)
{
    (void)in_sizes; (void)n_in; (void)out_size;
    const float* x       = (const float*)d_in[0];
    const float* miu_x   = (const float*)d_in[1];
    const float* lambda_ = (const float*)d_in[2];
    const float* A_lora  = (const float*)d_in[3];
    const float* B_lora  = (const float*)d_in[4];
    const float* td_miu  = (const float*)d_in[5];
    const float* td_A    = (const float*)d_in[6];
    const float* td_B    = (const float*)d_in[7];
    const float* u       = (const float*)d_in[8];
    const float* Wr      = (const float*)d_in[9];
    const float* Wk      = (const float*)d_in[10];
    const float* Wv      = (const float*)d_in[11];
    const float* Wg      = (const float*)d_in[12];
    const float* Wo      = (const float*)d_in[13];
    const float* gamma   = (const float*)d_in[14];
    const float* beta    = (const float*)d_in[15];
    float* out = (float*)d_out;

    float *p_dxa,*p_k,*p_v,*p_r,*p_g,*p_w,*p_y,*p_lorap,*p_BloraT;
    __nv_bfloat16 *p_xmh,*p_xml,*p_abh,*p_abl,*p_ygh,*p_ygl,*p_wbh,*p_wbl,
                  *p_AloraTh,*p_AloraTl;
    __half *p_xx0h,*p_xx0l,*p_tdhh,*p_tdhl,*p_tdATh,*p_tdATl,*p_tdBTh,*p_tdBTl;
    { void* t;
      cudaGetSymbolAddress(&t, g_dxa);     p_dxa     = (float*)t;
      cudaGetSymbolAddress(&t, g_k);       p_k       = (float*)t;
      cudaGetSymbolAddress(&t, g_v);       p_v       = (float*)t;
      cudaGetSymbolAddress(&t, g_r);       p_r       = (float*)t;
      cudaGetSymbolAddress(&t, g_g);       p_g       = (float*)t;
      cudaGetSymbolAddress(&t, g_w);       p_w       = (float*)t;
      cudaGetSymbolAddress(&t, g_y);       p_y       = (float*)t;
      cudaGetSymbolAddress(&t, g_lorap);   p_lorap   = (float*)t;
      cudaGetSymbolAddress(&t, g_BloraT);  p_BloraT  = (float*)t;
      cudaGetSymbolAddress(&t, g_xmh);     p_xmh     = (__nv_bfloat16*)t;
      cudaGetSymbolAddress(&t, g_xml);     p_xml     = (__nv_bfloat16*)t;
      cudaGetSymbolAddress(&t, g_abh);     p_abh     = (__nv_bfloat16*)t;
      cudaGetSymbolAddress(&t, g_abl);     p_abl     = (__nv_bfloat16*)t;
      cudaGetSymbolAddress(&t, g_ygh);     p_ygh     = (__nv_bfloat16*)t;
      cudaGetSymbolAddress(&t, g_ygl);     p_ygl     = (__nv_bfloat16*)t;
      cudaGetSymbolAddress(&t, g_wbh);     p_wbh     = (__nv_bfloat16*)t;
      cudaGetSymbolAddress(&t, g_wbl);     p_wbl     = (__nv_bfloat16*)t;
      cudaGetSymbolAddress(&t, g_AloraTh); p_AloraTh = (__nv_bfloat16*)t;
      cudaGetSymbolAddress(&t, g_AloraTl); p_AloraTl = (__nv_bfloat16*)t;
      cudaGetSymbolAddress(&t, g_xx0h);    p_xx0h    = (__half*)t;
      cudaGetSymbolAddress(&t, g_xx0l);    p_xx0l    = (__half*)t;
      cudaGetSymbolAddress(&t, g_tdhh);    p_tdhh    = (__half*)t;
      cudaGetSymbolAddress(&t, g_tdhl);    p_tdhl    = (__half*)t;
      cudaGetSymbolAddress(&t, g_tdATh);   p_tdATh   = (__half*)t;
      cudaGetSymbolAddress(&t, g_tdATl);   p_tdATl   = (__half*)t;
      cudaGetSymbolAddress(&t, g_tdBTh);   p_tdBTh   = (__half*)t;
      cudaGetSymbolAddress(&t, g_tdBTl);   p_tdBTl   = (__half*)t;
    }

    cudaFuncSetAttribute(hgemm_one,  cudaFuncAttributeMaxDynamicSharedMemorySize, HG_SMEM);
    cudaFuncSetAttribute(hgemm_kvrg, cudaFuncAttributeMaxDynamicSharedMemorySize, HG_SMEM);
    cudaFuncSetAttribute(hgemm_h,    cudaFuncAttributeMaxDynamicSharedMemorySize, HG_SMEM);

    // 0: token shift + static lerp (xm -> bf16 hi/lo)
    prep_kernel<<<BTq * Cq / 4 / 256, 256>>>((const float4*)x, (const float4*)miu_x,
                                             (float4*)p_dxa, p_xmh, p_xml);
    // 1: weight transposes
    transpose_all<<<(622592 + 255) / 256, 256>>>(p_AloraTh, p_AloraTl, A_lora,
                                                 p_tdATh, p_tdATl, td_A,
                                                 p_tdBTh, p_tdBTl, td_B,
                                                 p_BloraT, B_lora);
    // 2: lora_h = tanh(xm @ A_lora)
    hgemm_one<<<dim3(2, 128), 256, HG_SMEM>>>(p_xmh, p_xml, p_AloraTh, p_AloraTl,
                                              p_lorap, 256, Cq, 2);
    // 3: ddlerp mix (f=0 -> fp16 hi/lo xx0; f=1..4 -> bf16 hi/lo k,v,r,g)
    mix_gemm<<<dim3(5, 128, 8), 256>>>(p_lorap, p_BloraT, x, p_dxa, lambda_,
                                       p_xx0h, p_xx0l, p_abh, p_abl);
    // 4: big weight hi/lo (moved here — only needed before kvrg)
    wconv_kernel<<<5 * 1048576 / 256, 256>>>(Wk, Wv, Wr, Wg, Wo, p_wbh, p_wbl);
    // 5: merged projections k, v, r, g
    hgemm_kvrg<<<dim3(8, 128, 4), 256, HG_SMEM>>>(p_abh, p_abl, p_wbh, p_wbl,
                                                  p_k, p_v, p_r, p_g);
    // 6: tdh = tanh(w_in @ td_A) -> fp16 hi/lo (padded N=128)
    hgemm_h<<<dim3(1, 128), 256, HG_SMEM>>>(p_xx0h, p_xx0l, p_tdATh, p_tdATl,
                                            nullptr, p_tdhh, p_tdhl, nullptr,
                                            128, Cq, Cq, Cq, 3);
    // 7: w = td_miu + tdh @ td_B   (A stride 128, K=64)
    hgemm_h<<<dim3(8, 128), 256, HG_SMEM>>>(p_tdhh, p_tdhl, p_tdBTh, p_tdBTl,
                                            p_w, nullptr, nullptr, td_miu,
                                            Cq, 64, 128, 64, 4);
    // 8: WKV6 scan
    wkv6_kernel<<<Bq * Hq, 256>>>(p_r, p_k, p_v, p_w, u, p_y);
    // 9: GroupNorm * gate -> bf16 hi/lo
    gnorm_kernel<<<BTq, 256>>>(p_y, p_g, gamma, beta, p_ygh, p_ygl);
    // 10: output projection
    hgemm_one<<<dim3(8, 128), 256, HG_SMEM>>>(p_ygh, p_ygl, p_wbh + 4*WWq, p_wbl + 4*WWq,
                                              out, Cq, Cq, 0);
}

// round 13
// speedup vs baseline: 1.4996x; 1.0125x over previous
#include <cuda_runtime.h>
#include <cuda_bf16.h>
#include <cuda_fp16.h>
#include <math.h>
#include <stdint.h>

#define Bq 8
#define Tq 2048
#define Cq 1024
#define Hq 16
#define BTq (Bq*Tq)
#define WWq (Cq*Cq)

typedef unsigned long long ull;
static const size_t SZq = (size_t)BTq * Cq;

// ---------------------------------------------------------------------------
// Scratch (static device globals — no runtime allocation)
// ---------------------------------------------------------------------------
__device__ float g_dxa [BTq*Cq];
__device__ float g_k   [BTq*Cq];
__device__ float g_v   [BTq*Cq];
__device__ float g_r   [BTq*Cq];
__device__ float g_g   [BTq*Cq];
__device__ float g_w   [BTq*Cq];
__device__ float g_y   [BTq*Cq];
__device__ float g_lorap [BTq*256];          // tanh(xm @ A_lora) fp32 (padded 256)
__device__ float g_BloraT[5*1024*32];        // B_lora^T per branch, fp32

__device__ __nv_bfloat16 g_xmh[BTq*Cq];      // xm hi/lo (bf16 split)
__device__ __nv_bfloat16 g_xml[BTq*Cq];
__device__ __nv_bfloat16 g_abh[4*BTq*Cq];    // k,v,r,g branch inputs hi
__device__ __nv_bfloat16 g_abl[4*BTq*Cq];    // lo
__device__ __nv_bfloat16 g_ygh[BTq*Cq];
__device__ __nv_bfloat16 g_ygl[BTq*Cq];
__device__ __nv_bfloat16 g_wbh[5*WWq];       // Wk,Wv,Wr,Wg,Wo hi
__device__ __nv_bfloat16 g_wbl[5*WWq];       // lo
__device__ __nv_bfloat16 g_AloraTh[256*1024];
__device__ __nv_bfloat16 g_AloraTl[256*1024];

// fp16-split td path (2^-22 residual — precision-safe for the decay scan)
__device__ __half g_xx0h[BTq*Cq];            // w_in branch hi/lo
__device__ __half g_xx0l[BTq*Cq];
__device__ __half g_tdhh[BTq*128];           // tanh(w_in @ td_A) hi/lo (padded 128)
__device__ __half g_tdhl[BTq*128];
__device__ __half g_tdATh[128*1024];
__device__ __half g_tdATl[128*1024];
__device__ __half g_tdBTh[1024*64];
__device__ __half g_tdBTl[1024*64];

// ---------------------------------------------------------------------------
// PTX helpers (sm_80+ — valid on compute_103 virtual arch)
// ---------------------------------------------------------------------------
__device__ __forceinline__ uint32_t sm2u32(const void* p){
    uint32_t a;
    asm("{ .reg .u64 t; cvta.to.shared.u64 t, %1; cvt.u32.u64 %0, t; }" : "=r"(a) : "l"(p));
    return a;
}
__device__ __forceinline__ void cpa16(uint32_t dst, const void* src){
    asm volatile("cp.async.cg.shared.global [%0], [%1], 16;" :: "r"(dst), "l"(src) : "memory");
}
__device__ __forceinline__ void cpa_commit(){
    asm volatile("cp.async.commit_group;" ::: "memory");
}
template<int N>
__device__ __forceinline__ void cpa_wait(){
    asm volatile("cp.async.wait_group %0;" :: "n"(N) : "memory");
}
__device__ __forceinline__ void ldsm_x4(uint32_t* r, uint32_t addr){
    asm volatile("ldmatrix.sync.aligned.m8n8.x4.shared.b16 {%0,%1,%2,%3}, [%4];"
        : "=r"(r[0]), "=r"(r[1]), "=r"(r[2]), "=r"(r[3]) : "r"(addr));
}
template<bool FP16>
__device__ __forceinline__ void mma_any(float* d, const uint32_t* a, const uint32_t* b){
    if (FP16){
        asm volatile("mma.sync.aligned.m16n8k16.row.col.f32.f16.f16.f32 "
            "{%0,%1,%2,%3}, {%4,%5,%6,%7}, {%8,%9}, {%0,%1,%2,%3};"
            : "+f"(d[0]), "+f"(d[1]), "+f"(d[2]), "+f"(d[3])
            : "r"(a[0]), "r"(a[1]), "r"(a[2]), "r"(a[3]), "r"(b[0]), "r"(b[1]));
    } else {
        asm volatile("mma.sync.aligned.m16n8k16.row.col.f32.bf16.bf16.f32 "
            "{%0,%1,%2,%3}, {%4,%5,%6,%7}, {%8,%9}, {%0,%1,%2,%3};"
            : "+f"(d[0]), "+f"(d[1]), "+f"(d[2]), "+f"(d[3])
            : "r"(a[0]), "r"(a[1]), "r"(a[2]), "r"(a[3]), "r"(b[0]), "r"(b[1]));
    }
}
__device__ __forceinline__ void splitv(float v, __nv_bfloat16& h, __nv_bfloat16& l){
    h = __float2bfloat16(v);
    l = __float2bfloat16(v - __bfloat162float(h));
}
__device__ __forceinline__ void splitv(float v, __half& h, __half& l){
    h = __float2half_rn(v);
    l = __float2half_rn(v - __half2float(h));
}
__device__ __forceinline__ uint16_t u16of(__half v){ return *(uint16_t*)&v; }
__device__ __forceinline__ uint16_t u16of(__nv_bfloat16 v){ return *(uint16_t*)&v; }

// ---------------------------------------------------------------------------
// split GEMM core via mma.sync (proven round-9 structure)
// ---------------------------------------------------------------------------
#define NSTAGE    4
#define STG_ARR   6144                 // 128 rows * 48B
#define STG_BYTES 24576                // 4 arrays
#define HG_SMEM   (NSTAGE * STG_BYTES) // 98304

template<bool FP16, typename OT>
__device__ __forceinline__ void hg_core(
    const uint16_t* __restrict__ Ah, const uint16_t* __restrict__ Al,
    const uint16_t* __restrict__ Bh, const uint16_t* __restrict__ Bl,
    float* __restrict__ Cp, OT* __restrict__ Ch, OT* __restrict__ Cl,
    const float* __restrict__ e0,
    int N, int K, int lda, int ldb, int m0, int n0, int epi, char* sm)
{
    int tid = threadIdx.x, lane = tid & 31, wid = tid >> 5;
    int wy = wid & 1, wx = wid >> 1;
    uint32_t sb = sm2u32(sm);

    int arr0 = tid >> 7;
    int rowa = tid & 127;
    const uint16_t* p0 = ((arr0 == 0) ? Ah : Al) + (size_t)(m0 + rowa) * lda;
    const uint16_t* p1 = ((arr0 == 0) ? Bh : Bl) + (size_t)(n0 + rowa) * ldb;
    uint32_t so0 = (uint32_t)(arr0 * STG_ARR + rowa * 48);
    uint32_t so1 = so0 + 2 * STG_ARR;

    float acc[4][4][4];
    #pragma unroll
    for (int i = 0; i < 4; i++)
        #pragma unroll
        for (int j = 0; j < 4; j++)
            #pragma unroll
            for (int q = 0; q < 4; q++) acc[i][j][q] = 0.f;

    uint32_t a_row = (uint32_t)(wy * 64 + (lane & 15));
    uint32_t a_kh  = (uint32_t)((lane >> 4) * 8);
    uint32_t b_row0 = (uint32_t)(wx * 32 + (lane & 7) + ((lane >> 4) * 8));
    uint32_t b_kh   = (uint32_t)(((lane >> 3) & 1) * 8);

    const int NC = K >> 4;

    #pragma unroll
    for (int s = 0; s < 3; s++){
        uint32_t d = sb + (uint32_t)s * STG_BYTES;
        int kk = s * 16;
        cpa16(d + so0,      p0 + kk);  cpa16(d + so0 + 16, p0 + kk + 8);
        cpa16(d + so1,      p1 + kk);  cpa16(d + so1 + 16, p1 + kk + 8);
        cpa_commit();
    }

    #pragma unroll 4
    for (int c = 0; c < NC; c++){
        cpa_wait<2>();
        __syncthreads();
        if (c + 3 < NC){
            uint32_t d = sb + (uint32_t)((c + 3) & 3) * STG_BYTES;
            int kk = (c + 3) << 4;
            cpa16(d + so0,      p0 + kk);  cpa16(d + so0 + 16, p0 + kk + 8);
            cpa16(d + so1,      p1 + kk);  cpa16(d + so1 + 16, p1 + kk + 8);
        }
        cpa_commit();

        uint32_t base = sb + (uint32_t)(c & 3) * STG_BYTES;

        uint32_t bh[2][4], bl[2][4];
        #pragma unroll
        for (int bi = 0; bi < 2; bi++){
            uint32_t bo = base + 2*STG_ARR + (b_row0 + bi * 16) * 48 + b_kh * 2;
            ldsm_x4(bh[bi], bo);
            ldsm_x4(bl[bi], bo + STG_ARR);
        }
        #pragma unroll
        for (int mf = 0; mf < 4; mf++){
            uint32_t ah[4], al[4];
            uint32_t ao = base + (a_row + mf * 16) * 48 + a_kh * 2;
            ldsm_x4(ah, ao);
            ldsm_x4(al, ao + STG_ARR);
            #pragma unroll
            for (int nf = 0; nf < 4; nf++){
                const uint32_t* bhp = &bh[nf >> 1][(nf & 1) * 2];
                const uint32_t* blp = &bl[nf >> 1][(nf & 1) * 2];
                mma_any<FP16>(acc[mf][nf], ah, bhp);
                mma_any<FP16>(acc[mf][nf], ah, blp);
                mma_any<FP16>(acc[mf][nf], al, bhp);
            }
        }
    }

    #pragma unroll
    for (int mf = 0; mf < 4; mf++){
        int row0 = m0 + wy * 64 + mf * 16 + (lane >> 2);
        #pragma unroll
        for (int nf = 0; nf < 4; nf++){
            int col = n0 + wx * 32 + nf * 8 + (lane & 3) * 2;
            float v[4] = {acc[mf][nf][0], acc[mf][nf][1], acc[mf][nf][2], acc[mf][nf][3]};
            if (epi == 1){
                #pragma unroll
                for (int q = 0; q < 4; q++) v[q] = v[q] / (1.f + expf(-v[q]));
            } else if (epi == 2 || epi == 3){
                #pragma unroll
                for (int q = 0; q < 4; q++) v[q] = tanhf(v[q]);
            } else if (epi == 4){
                v[0] += e0[col]; v[1] += e0[col+1];
                v[2] += e0[col]; v[3] += e0[col+1];
            }
            size_t i01 = (size_t)row0 * N + col;
            size_t i23 = (size_t)(row0 + 8) * N + col;
            if (epi == 3){
                OT h[4], l[4];
                #pragma unroll
                for (int q = 0; q < 4; q++) splitv(v[q], h[q], l[q]);
                *(uint32_t*)(Ch + i01) = (uint32_t)u16of(h[0]) | ((uint32_t)u16of(h[1]) << 16);
                *(uint32_t*)(Cl + i01) = (uint32_t)u16of(l[0]) | ((uint32_t)u16of(l[1]) << 16);
                *(uint32_t*)(Ch + i23) = (uint32_t)u16of(h[2]) | ((uint32_t)u16of(h[3]) << 16);
                *(uint32_t*)(Cl + i23) = (uint32_t)u16of(l[2]) | ((uint32_t)u16of(l[3]) << 16);
            } else {
                *(float2*)(Cp + i01) = make_float2(v[0], v[1]);
                *(float2*)(Cp + i23) = make_float2(v[2], v[3]);
            }
        }
    }
}

__global__ void __launch_bounds__(256, 2) hgemm_one(
    const __nv_bfloat16* __restrict__ Ah, const __nv_bfloat16* __restrict__ Al,
    const __nv_bfloat16* __restrict__ Bh, const __nv_bfloat16* __restrict__ Bl,
    float* __restrict__ Cp, int N, int K, int epi)
{
    extern __shared__ char sm[];
    hg_core<false, __nv_bfloat16>((const uint16_t*)Ah, (const uint16_t*)Al,
        (const uint16_t*)Bh, (const uint16_t*)Bl,
        Cp, (__nv_bfloat16*)nullptr, (__nv_bfloat16*)nullptr, nullptr,
        N, K, K, K, blockIdx.y * 128, blockIdx.x * 128, epi, sm);
}

__global__ void __launch_bounds__(256, 2) hgemm_kvrg(
    const __nv_bfloat16* __restrict__ abh, const __nv_bfloat16* __restrict__ abl,
    const __nv_bfloat16* __restrict__ wbh, const __nv_bfloat16* __restrict__ wbl,
    float* __restrict__ C0, float* __restrict__ C1,
    float* __restrict__ C2, float* __restrict__ C3)
{
    extern __shared__ char sm[];
    int z = blockIdx.z;
    float* Cp = (z == 0) ? C0 : (z == 1) ? C1 : (z == 2) ? C2 : C3;
    hg_core<false, __nv_bfloat16>(
        (const uint16_t*)(abh + (size_t)z * SZq), (const uint16_t*)(abl + (size_t)z * SZq),
        (const uint16_t*)(wbh + (size_t)z * WWq), (const uint16_t*)(wbl + (size_t)z * WWq),
        Cp, (__nv_bfloat16*)nullptr, (__nv_bfloat16*)nullptr, nullptr,
        Cq, Cq, Cq, Cq, blockIdx.y * 128, blockIdx.x * 128, (z == 3) ? 1 : 0, sm);
}

__global__ void __launch_bounds__(256, 2) hgemm_h(
    const __half* __restrict__ Ah, const __half* __restrict__ Al,
    const __half* __restrict__ Bh, const __half* __restrict__ Bl,
    float* __restrict__ Cp, __half* __restrict__ Ch, __half* __restrict__ Cl,
    const float* __restrict__ e0, int N, int K, int lda, int ldb, int epi)
{
    extern __shared__ char sm[];
    hg_core<true, __half>((const uint16_t*)Ah, (const uint16_t*)Al,
        (const uint16_t*)Bh, (const uint16_t*)Bl,
        Cp, Ch, Cl, e0,
        N, K, lda, ldb, blockIdx.y * 128, blockIdx.x * 128, epi, sm);
}

// ---------------------------------------------------------------------------
// FFMA2 helpers
// ---------------------------------------------------------------------------
__device__ __forceinline__ void fma2(ull& d, ull a, ull b){
    asm("fma.rn.f32x2 %0, %1, %2, %0;" : "+l"(d) : "l"(a), "l"(b));
}
__device__ __forceinline__ float2 unp(ull v){
    float2 r; asm("mov.b64 {%0, %1}, %2;" : "=f"(r.x), "=f"(r.y) : "l"(v)); return r;
}
__device__ __forceinline__ ull pack2(float v){
    ull r; asm("mov.b64 %0, {%1, %1};" : "=l"(r) : "f"(v)); return r;
}

// ---------------------------------------------------------------------------
// ddlerp MIX GEMM (K=32), SINGLE load phase, ONE barrier.
// A stored NON-duplicated (fp32) — (a,a) pairs built in registers, cutting
// per-k-step LDS from 96B to 64B and smem from 48KB to 32KB.
// f = blockIdx.x (fastest) for L2 reuse of x/dxa.
// f=0 -> fp16 hi/lo xx0 (w_in); f=1..4 -> bf16 hi/lo slots 0..3 (k,v,r,g).
// ---------------------------------------------------------------------------
__global__ void __launch_bounds__(256) mix_gemm(
    const float* __restrict__ lorap, const float* __restrict__ BloraT,
    const float* __restrict__ x, const float* __restrict__ dxa,
    const float* __restrict__ lam,
    __half* __restrict__ xx0h, __half* __restrict__ xx0l,
    __nv_bfloat16* __restrict__ abh, __nv_bfloat16* __restrict__ abl)
{
    __shared__ __align__(16) float As[32][128];    // 16 KB (non-duplicated)
    __shared__ __align__(16) float Bs[32][128];    // 16 KB

    int f = blockIdx.x;
    const float* A  = lorap  + f*32;
    const float* Bm = BloraT + f*32768;
    const float* e2 = lam    + f*Cq;

    int tid  = threadIdx.x;
    int m0   = blockIdx.y * 128, n0 = blockIdx.z * 128;
    int ty = tid >> 4, tx = tid & 15;

    // single load phase: 4 float4 of A + 4 float4 of B per thread
    #pragma unroll
    for (int t2 = 0; t2 < 4; t2++){
        int i = t2 * 256 + tid;          // 0..1023
        int row = i >> 3, q = (i & 7) * 4;
        float4 av = *(const float4*)(A + (size_t)(m0 + row) * 256 + q);
        As[q+0][row] = av.x;
        As[q+1][row] = av.y;
        As[q+2][row] = av.z;
        As[q+3][row] = av.w;
        float4 bv = *(const float4*)(Bm + (size_t)(n0 + row) * 32 + q);
        Bs[q+0][row] = bv.x;
        Bs[q+1][row] = bv.y;
        Bs[q+2][row] = bv.z;
        Bs[q+3][row] = bv.w;
    }
    __syncthreads();

    ull acc[8][4];
    #pragma unroll
    for (int i = 0; i < 8; i++)
        #pragma unroll
        for (int p = 0; p < 4; p++) acc[i][p] = 0ull;

    #pragma unroll 8
    for (int kk = 0; kk < 32; kk++) {
        const float* ar = As[kk];
        const ull*  br = (const ull*)Bs[kk];
        ull a_[8], b_[4];
        #pragma unroll
        for (int i = 0; i < 8; i++) a_[i] = pack2(ar[ty*8 + i]);
        #pragma unroll
        for (int p = 0; p < 4; p++) b_[p] = br[tx*4 + p];
        #pragma unroll
        for (int i = 0; i < 8; i++)
            #pragma unroll
            for (int p = 0; p < 4; p++) fma2(acc[i][p], a_[i], b_[p]);
    }

    #pragma unroll
    for (int i = 0; i < 8; i++) {
        size_t m = (size_t)(m0 + ty*8 + i);
        #pragma unroll
        for (int p = 0; p < 4; p++) {
            float2 vv = unp(acc[i][p]);
            int n = n0 + tx*8 + 2*p;
            size_t idx = m * (size_t)Cq + n;
            float vx = x[idx]   + dxa[idx]   * (e2[n]   + vv.x);
            float vy = x[idx+1] + dxa[idx+1] * (e2[n+1] + vv.y);
            if (f == 0) {
                __half hx, lx, hy, ly;
                splitv(vx, hx, lx); splitv(vy, hy, ly);
                __half2 hp; hp.x = hx; hp.y = hy;
                __half2 lp; lp.x = lx; lp.y = ly;
                *(__half2*)(xx0h + idx) = hp;
                *(__half2*)(xx0l + idx) = lp;
            } else {
                size_t o = (size_t)(f-1) * SZq + idx;
                __nv_bfloat162 hp, lp;
                splitv(vx, hp.x, lp.x);
                splitv(vy, hp.y, lp.y);
                *(__nv_bfloat162*)(abh + o) = hp;
                *(__nv_bfloat162*)(abl + o) = lp;
            }
        }
    }
}

// ---------------------------------------------------------------------------
// prep: dxa = shift(x) - x (fp32) ; xm = x + dxa * miu_x -> bf16 hi/lo
// ---------------------------------------------------------------------------
__global__ void __launch_bounds__(256) prep_kernel(
    const float4* __restrict__ x4, const float4* __restrict__ mu4,
    float4* __restrict__ dxa4,
    __nv_bfloat16* __restrict__ xmh, __nv_bfloat16* __restrict__ xml)
{
    size_t i = (size_t)blockIdx.x * 256 + threadIdx.x;
    int m = (int)(i >> 8);
    int t = m & (Tq - 1);
    float4 xv = x4[i];
    float4 xl = make_float4(0.f, 0.f, 0.f, 0.f);
    if (t) xl = x4[i - 256];
    float4 mu = mu4[i & 255];
    float4 d  = make_float4(xl.x - xv.x, xl.y - xv.y, xl.z - xv.z, xl.w - xv.w);
    float xm0 = fmaf(d.x, mu.x, xv.x), xm1 = fmaf(d.y, mu.y, xv.y);
    float xm2 = fmaf(d.z, mu.z, xv.z), xm3 = fmaf(d.w, mu.w, xv.w);
    dxa4[i] = d;
    __nv_bfloat162 h0, l0, h1, l1;
    splitv(xm0, h0.x, l0.x); splitv(xm1, h0.y, l0.y);
    splitv(xm2, h1.x, l1.x); splitv(xm3, h1.y, l1.y);
    ((__nv_bfloat162*)xmh)[i*2]   = h0;
    ((__nv_bfloat162*)xmh)[i*2+1] = h1;
    ((__nv_bfloat162*)xml)[i*2]   = l0;
    ((__nv_bfloat162*)xml)[i*2+1] = l1;
}

// ---------------------------------------------------------------------------
// transposes: AloraT -> bf16 hi/lo; tdAT, tdBT -> fp16 hi/lo; BloraT fp32
// ---------------------------------------------------------------------------
__global__ void __launch_bounds__(256) transpose_all(
    __nv_bfloat16* __restrict__ AloraTh, __nv_bfloat16* __restrict__ AloraTl,
    const float* __restrict__ A_lora,
    __half* __restrict__ tdATh, __half* __restrict__ tdATl,
    const float* __restrict__ td_A,
    __half* __restrict__ tdBTh, __half* __restrict__ tdBTl,
    const float* __restrict__ td_B,
    float* __restrict__ BloraT, const float* __restrict__ B_lora)
{
    int i = blockIdx.x * 256 + threadIdx.x;
    if (i < 262144) {
        int n = i >> 10, k = i & 1023;
        float v = (n < 160) ? A_lora[k*160 + n] : 0.f;
        __nv_bfloat16 h, l; splitv(v, h, l);
        AloraTh[i] = h; AloraTl[i] = l;
    } else if (i < 393216) {
        int j = i - 262144; int n = j >> 10, k = j & 1023;
        float v = (n < 64) ? td_A[k*64 + n] : 0.f;
        __half h, l; splitv(v, h, l);
        tdATh[j] = h; tdATl[j] = l;
    } else if (i < 458752) {
        int j = i - 393216; int n = j >> 6, k = j & 63;
        float v = td_B[k*1024 + n];
        __half h, l; splitv(v, h, l);
        tdBTh[j] = h; tdBTl[j] = l;
    } else if (i < 622592) {
        int j = i - 458752;
        int f = j >> 15, rr = j & 32767, n = rr >> 5, k = rr & 31;
        BloraT[j] = B_lora[(f*32 + k)*1024 + n];
    }
}

// ---------------------------------------------------------------------------
// Weight bf16 hi/lo conversion (Wk,Wv,Wr,Wg,Wo)
// ---------------------------------------------------------------------------
__global__ void __launch_bounds__(256) wconv_kernel(
    const float* __restrict__ w0, const float* __restrict__ w1,
    const float* __restrict__ w2, const float* __restrict__ w3,
    const float* __restrict__ w4,
    __nv_bfloat16* __restrict__ h, __nv_bfloat16* __restrict__ l)
{
    int i = blockIdx.x * 256 + threadIdx.x;
    int w = i >> 20;
    int j = i & 1048575;
    const float* src = (w == 0) ? w0 : (w == 1) ? w1 : (w == 2) ? w2 : (w == 3) ? w3 : w4;
    float x = src[j];
    __nv_bfloat16 hh, ll; splitv(x, hh, ll);
    h[i] = hh;
    l[i] = ll;
}

// ---------------------------------------------------------------------------
// WKV6 scan — 4-buffer ring, ONE barrier per TWO timesteps; t+2/t+3 loads
// overlap compute of t/t+1.
// ---------------------------------------------------------------------------
__global__ void __launch_bounds__(256) wkv6_kernel(
    const float* __restrict__ rp, const float* __restrict__ kp,
    const float* __restrict__ vp, const float* __restrict__ wp,
    const float* __restrict__ up, float* __restrict__ yp)
{
    __shared__ float4 pk[4][4][17];
    __shared__ float  sv[4][64];
    int bh = blockIdx.x;
    int b = bh >> 4, h = bh & 15;
    size_t base = ((size_t)b * Tq) * Cq + h * 64;
    int tid = threadIdx.x;
    int j = tid >> 2, rg = tid & 3;
    float uu = 0.f;
    if (tid < 64) uu = up[h * 64 + tid];
    float S[16];
    #pragma unroll
    for (int i = 0; i < 16; i++) S[i] = 0.f;

    float lk0 = 0.f, lr0 = 0.f, lw0 = 0.f, lv0 = 0.f;
    float lk1 = 0.f, lr1 = 0.f, lw1 = 0.f, lv1 = 0.f;
    if (tid < 64){
        size_t o0 = base + tid;
        lk0 = kp[o0]; lr0 = rp[o0]; lw0 = wp[o0]; lv0 = vp[o0];
        size_t o1 = o0 + Cq;
        lk1 = kp[o1]; lr1 = rp[o1]; lw1 = wp[o1]; lv1 = vp[o1];
    }

    for (int t = 0; t < Tq; t += 2) {
        int b0 = t & 3, b1 = (t + 1) & 3;
        size_t off = base + (size_t)t * Cq;
        if (tid < 64) {
            sv[b0][tid] = lv0;
            pk[b0][tid >> 4][tid & 15] = make_float4(lk0, uu * lk0, lr0, expf(-expf(lw0)));
            sv[b1][tid] = lv1;
            pk[b1][tid >> 4][tid & 15] = make_float4(lk1, uu * lk1, lr1, expf(-expf(lw1)));
        }
        __syncthreads();
        if (t + 2 < Tq && tid < 64){
            size_t o2 = off + 2 * Cq + tid;
            lk0 = kp[o2]; lr0 = rp[o2]; lw0 = wp[o2]; lv0 = vp[o2];
            size_t o3 = o2 + Cq;
            lk1 = kp[o3]; lr1 = rp[o3]; lw1 = wp[o3]; lv1 = vp[o3];
        }
        // step t
        {
            float vj = sv[b0][j];
            float yv = 0.f;
            #pragma unroll
            for (int ii = 0; ii < 16; ii++) {
                float4 p = pk[b0][rg][ii];
                float s = S[ii];
                yv = fmaf(p.z, fmaf(p.y, vj, s), yv);
                S[ii] = fmaf(p.w, s, p.x * vj);
            }
            yv += __shfl_xor_sync(0xffffffffu, yv, 1);
            yv += __shfl_xor_sync(0xffffffffu, yv, 2);
            if (rg == 0) yp[off + j] = yv;
        }
        // step t+1
        {
            float vj = sv[b1][j];
            float yv = 0.f;
            #pragma unroll
            for (int ii = 0; ii < 16; ii++) {
                float4 p = pk[b1][rg][ii];
                float s = S[ii];
                yv = fmaf(p.z, fmaf(p.y, vj, s), yv);
                S[ii] = fmaf(p.w, s, p.x * vj);
            }
            yv += __shfl_xor_sync(0xffffffffu, yv, 1);
            yv += __shfl_xor_sync(0xffffffffu, yv, 2);
            if (rg == 0) yp[off + Cq + j] = yv;
        }
    }
}

// ---------------------------------------------------------------------------
// GroupNorm * gate -> bf16 hi/lo
// ---------------------------------------------------------------------------
__global__ void __launch_bounds__(256) gnorm_kernel(
    const float* __restrict__ y, const float* __restrict__ g,
    const float* __restrict__ gamma, const float* __restrict__ beta,
    __nv_bfloat16* __restrict__ ygh, __nv_bfloat16* __restrict__ ygl)
{
    int m = blockIdx.x, tid = threadIdx.x;
    size_t i4 = (size_t)m * 256 + tid;
    float4 yv = ((const float4*)y)[i4];
    float s  = yv.x + yv.y + yv.z + yv.w;
    float ss = yv.x*yv.x + yv.y*yv.y + yv.z*yv.z + yv.w*yv.w;
    #pragma unroll
    for (int o = 1; o < 16; o <<= 1) {
        s  += __shfl_xor_sync(0xffffffffu, s,  o);
        ss += __shfl_xor_sync(0xffffffffu, ss, o);
    }
    float mean = s * (1.f / 64.f);
    float var  = ss * (1.f / 64.f) - mean * mean;
    float rstd = rsqrtf(fmaxf(var, 0.f) + 1.6e-4f);
    float4 ga = ((const float4*)gamma)[tid];
    float4 be = ((const float4*)beta)[tid];
    float4 gv = ((const float4*)g)[i4];
    float o0 = ((yv.x - mean) * rstd * ga.x + be.x) * gv.x;
    float o1 = ((yv.y - mean) * rstd * ga.y + be.y) * gv.y;
    float o2 = ((yv.z - mean) * rstd * ga.z + be.z) * gv.z;
    float o3 = ((yv.w - mean) * rstd * ga.w + be.w) * gv.w;

    __nv_bfloat162 hp0, lp0, hp1, lp1;
    splitv(o0, hp0.x, lp0.x); splitv(o1, hp0.y, lp0.y);
    splitv(o2, hp1.x, lp1.x); splitv(o3, hp1.y, lp1.y);
    ((__nv_bfloat162*)ygh)[i4*2]   = hp0;
    ((__nv_bfloat162*)ygh)[i4*2+1] = hp1;
    ((__nv_bfloat162*)ygl)[i4*2]   = lp0;
    ((__nv_bfloat162*)ygl)[i4*2+1] = lp1;
}

// ---------------------------------------------------------------------------
// Launch
// ---------------------------------------------------------------------------
extern "C" void kernel_launch(void* const* d_in, const int* in_sizes, int n_in,
                              void* d_out, int out_size)
{
    (void)in_sizes; (void)n_in; (void)out_size;
    const float* x       = (const float*)d_in[0];
    const float* miu_x   = (const float*)d_in[1];
    const float* lambda_ = (const float*)d_in[2];
    const float* A_lora  = (const float*)d_in[3];
    const float* B_lora  = (const float*)d_in[4];
    const float* td_miu  = (const float*)d_in[5];
    const float* td_A    = (const float*)d_in[6];
    const float* td_B    = (const float*)d_in[7];
    const float* u       = (const float*)d_in[8];
    const float* Wr      = (const float*)d_in[9];
    const float* Wk      = (const float*)d_in[10];
    const float* Wv      = (const float*)d_in[11];
    const float* Wg      = (const float*)d_in[12];
    const float* Wo      = (const float*)d_in[13];
    const float* gamma   = (const float*)d_in[14];
    const float* beta    = (const float*)d_in[15];
    float* out = (float*)d_out;

    float *p_dxa,*p_k,*p_v,*p_r,*p_g,*p_w,*p_y,*p_lorap,*p_BloraT;
    __nv_bfloat16 *p_xmh,*p_xml,*p_abh,*p_abl,*p_ygh,*p_ygl,*p_wbh,*p_wbl,
                  *p_AloraTh,*p_AloraTl;
    __half *p_xx0h,*p_xx0l,*p_tdhh,*p_tdhl,*p_tdATh,*p_tdATl,*p_tdBTh,*p_tdBTl;
    { void* t;
      cudaGetSymbolAddress(&t, g_dxa);     p_dxa     = (float*)t;
      cudaGetSymbolAddress(&t, g_k);       p_k       = (float*)t;
      cudaGetSymbolAddress(&t, g_v);       p_v       = (float*)t;
      cudaGetSymbolAddress(&t, g_r);       p_r       = (float*)t;
      cudaGetSymbolAddress(&t, g_g);       p_g       = (float*)t;
      cudaGetSymbolAddress(&t, g_w);       p_w       = (float*)t;
      cudaGetSymbolAddress(&t, g_y);       p_y       = (float*)t;
      cudaGetSymbolAddress(&t, g_lorap);   p_lorap   = (float*)t;
      cudaGetSymbolAddress(&t, g_BloraT);  p_BloraT  = (float*)t;
      cudaGetSymbolAddress(&t, g_xmh);     p_xmh     = (__nv_bfloat16*)t;
      cudaGetSymbolAddress(&t, g_xml);     p_xml     = (__nv_bfloat16*)t;
      cudaGetSymbolAddress(&t, g_abh);     p_abh     = (__nv_bfloat16*)t;
      cudaGetSymbolAddress(&t, g_abl);     p_abl     = (__nv_bfloat16*)t;
      cudaGetSymbolAddress(&t, g_ygh);     p_ygh     = (__nv_bfloat16*)t;
      cudaGetSymbolAddress(&t, g_ygl);     p_ygl     = (__nv_bfloat16*)t;
      cudaGetSymbolAddress(&t, g_wbh);     p_wbh     = (__nv_bfloat16*)t;
      cudaGetSymbolAddress(&t, g_wbl);     p_wbl     = (__nv_bfloat16*)t;
      cudaGetSymbolAddress(&t, g_AloraTh); p_AloraTh = (__nv_bfloat16*)t;
      cudaGetSymbolAddress(&t, g_AloraTl); p_AloraTl = (__nv_bfloat16*)t;
      cudaGetSymbolAddress(&t, g_xx0h);    p_xx0h    = (__half*)t;
      cudaGetSymbolAddress(&t, g_xx0l);    p_xx0l    = (__half*)t;
      cudaGetSymbolAddress(&t, g_tdhh);    p_tdhh    = (__half*)t;
      cudaGetSymbolAddress(&t, g_tdhl);    p_tdhl    = (__half*)t;
      cudaGetSymbolAddress(&t, g_tdATh);   p_tdATh   = (__half*)t;
      cudaGetSymbolAddress(&t, g_tdATl);   p_tdATl   = (__half*)t;
      cudaGetSymbolAddress(&t, g_tdBTh);   p_tdBTh   = (__half*)t;
      cudaGetSymbolAddress(&t, g_tdBTl);   p_tdBTl   = (__half*)t;
    }

    cudaFuncSetAttribute(hgemm_one,  cudaFuncAttributeMaxDynamicSharedMemorySize, HG_SMEM);
    cudaFuncSetAttribute(hgemm_kvrg, cudaFuncAttributeMaxDynamicSharedMemorySize, HG_SMEM);
    cudaFuncSetAttribute(hgemm_h,    cudaFuncAttributeMaxDynamicSharedMemorySize, HG_SMEM);

    // 0: token shift + static lerp (xm -> bf16 hi/lo)
    prep_kernel<<<BTq * Cq / 4 / 256, 256>>>((const float4*)x, (const float4*)miu_x,
                                             (float4*)p_dxa, p_xmh, p_xml);
    // 1: weight transposes
    transpose_all<<<(622592 + 255) / 256, 256>>>(p_AloraTh, p_AloraTl, A_lora,
                                                 p_tdATh, p_tdATl, td_A,
                                                 p_tdBTh, p_tdBTl, td_B,
                                                 p_BloraT, B_lora);
    // 2: lora_h = tanh(xm @ A_lora)
    hgemm_one<<<dim3(2, 128), 256, HG_SMEM>>>(p_xmh, p_xml, p_AloraTh, p_AloraTl,
                                              p_lorap, 256, Cq, 2);
    // 3: ddlerp mix (f=0 -> fp16 hi/lo xx0; f=1..4 -> bf16 hi/lo k,v,r,g)
    mix_gemm<<<dim3(5, 128, 8), 256>>>(p_lorap, p_BloraT, x, p_dxa, lambda_,
                                       p_xx0h, p_xx0l, p_abh, p_abl);
    // 4: big weight hi/lo
    wconv_kernel<<<5 * 1048576 / 256, 256>>>(Wk, Wv, Wr, Wg, Wo, p_wbh, p_wbl);
    // 5: merged projections k, v, r, g
    hgemm_kvrg<<<dim3(8, 128, 4), 256, HG_SMEM>>>(p_abh, p_abl, p_wbh, p_wbl,
                                                  p_k, p_v, p_r, p_g);
    // 6: tdh = tanh(w_in @ td_A) -> fp16 hi/lo (padded N=128)
    hgemm_h<<<dim3(1, 128), 256, HG_SMEM>>>(p_xx0h, p_xx0l, p_tdATh, p_tdATl,
                                            nullptr, p_tdhh, p_tdhl, nullptr,
                                            128, Cq, Cq, Cq, 3);
    // 7: w = td_miu + tdh @ td_B   (A stride 128, K=64)
    hgemm_h<<<dim3(8, 128), 256, HG_SMEM>>>(p_tdhh, p_tdhl, p_tdBTh, p_tdBTl,
                                            p_w, nullptr, nullptr, td_miu,
                                            Cq, 64, 128, 64, 4);
    // 8: WKV6 scan
    wkv6_kernel<<<Bq * Hq, 256>>>(p_r, p_k, p_v, p_w, u, p_y);
    // 9: GroupNorm * gate -> bf16 hi/lo
    gnorm_kernel<<<BTq, 256>>>(p_y, p_g, gamma, beta, p_ygh, p_ygl);
    // 10: output projection
    hgemm_one<<<dim3(8, 128), 256, HG_SMEM>>>(p_ygh, p_ygl, p_wbh + 4*WWq, p_wbl + 4*WWq,
                                              out, Cq, Cq, 0);
}

// round 14
// speedup vs baseline: 1.4999x; 1.0002x over previous
#include <cuda_runtime.h>
#include <cuda_bf16.h>
#include <cuda_fp16.h>
#include <math.h>
#include <stdint.h>

#define Bq 8
#define Tq 2048
#define Cq 1024
#define Hq 16
#define BTq (Bq*Tq)
#define WWq (Cq*Cq)

typedef unsigned long long ull;
static const size_t SZq = (size_t)BTq * Cq;

// ---------------------------------------------------------------------------
// Scratch (static device globals — no runtime allocation)
// ---------------------------------------------------------------------------
__device__ float g_dxa [BTq*Cq];
__device__ float g_k   [BTq*Cq];
__device__ float g_v   [BTq*Cq];
__device__ float g_r   [BTq*Cq];
__device__ float g_g   [BTq*Cq];
__device__ float g_w   [BTq*Cq];
__device__ float g_y   [BTq*Cq];
__device__ float g_lorap [BTq*256];          // tanh(xm @ A_lora) fp32 (padded 256)
__device__ float g_BloraT[5*1024*32];        // B_lora^T per branch, fp32

__device__ __nv_bfloat16 g_xmh[BTq*Cq];      // xm hi/lo (bf16 split)
__device__ __nv_bfloat16 g_xml[BTq*Cq];
__device__ __nv_bfloat16 g_abh[4*BTq*Cq];    // k,v,r,g branch inputs hi
__device__ __nv_bfloat16 g_abl[4*BTq*Cq];    // lo
__device__ __nv_bfloat16 g_ygh[BTq*Cq];
__device__ __nv_bfloat16 g_ygl[BTq*Cq];
__device__ __nv_bfloat16 g_wbh[5*WWq];       // Wk,Wv,Wr,Wg,Wo hi
__device__ __nv_bfloat16 g_wbl[5*WWq];       // lo
__device__ __nv_bfloat16 g_AloraTh[256*1024];
__device__ __nv_bfloat16 g_AloraTl[256*1024];

// fp16-split td path (2^-22 residual — precision-safe for the decay scan)
__device__ __half g_xx0h[BTq*Cq];            // w_in branch hi/lo
__device__ __half g_xx0l[BTq*Cq];
__device__ __half g_tdhh[BTq*128];           // tanh(w_in @ td_A) hi/lo (padded 128)
__device__ __half g_tdhl[BTq*128];
__device__ __half g_tdATh[128*1024];
__device__ __half g_tdATl[128*1024];
__device__ __half g_tdBTh[1024*64];
__device__ __half g_tdBTl[1024*64];

// ---------------------------------------------------------------------------
// PTX helpers (sm_80+ — valid on compute_103 virtual arch)
// ---------------------------------------------------------------------------
__device__ __forceinline__ uint32_t sm2u32(const void* p){
    uint32_t a;
    asm("{ .reg .u64 t; cvta.to.shared.u64 t, %1; cvt.u32.u64 %0, t; }" : "=r"(a) : "l"(p));
    return a;
}
__device__ __forceinline__ void cpa16(uint32_t dst, const void* src){
    asm volatile("cp.async.cg.shared.global [%0], [%1], 16;" :: "r"(dst), "l"(src) : "memory");
}
__device__ __forceinline__ void cpa_commit(){
    asm volatile("cp.async.commit_group;" ::: "memory");
}
template<int N>
__device__ __forceinline__ void cpa_wait(){
    asm volatile("cp.async.wait_group %0;" :: "n"(N) : "memory");
}
__device__ __forceinline__ void ldsm_x4(uint32_t* r, uint32_t addr){
    asm volatile("ldmatrix.sync.aligned.m8n8.x4.shared.b16 {%0,%1,%2,%3}, [%4];"
        : "=r"(r[0]), "=r"(r[1]), "=r"(r[2]), "=r"(r[3]) : "r"(addr));
}
template<bool FP16>
__device__ __forceinline__ void mma_any(float* d, const uint32_t* a, const uint32_t* b){
    if (FP16){
        asm volatile("mma.sync.aligned.m16n8k16.row.col.f32.f16.f16.f32 "
            "{%0,%1,%2,%3}, {%4,%5,%6,%7}, {%8,%9}, {%0,%1,%2,%3};"
            : "+f"(d[0]), "+f"(d[1]), "+f"(d[2]), "+f"(d[3])
            : "r"(a[0]), "r"(a[1]), "r"(a[2]), "r"(a[3]), "r"(b[0]), "r"(b[1]));
    } else {
        asm volatile("mma.sync.aligned.m16n8k16.row.col.f32.bf16.bf16.f32 "
            "{%0,%1,%2,%3}, {%4,%5,%6,%7}, {%8,%9}, {%0,%1,%2,%3};"
            : "+f"(d[0]), "+f"(d[1]), "+f"(d[2]), "+f"(d[3])
            : "r"(a[0]), "r"(a[1]), "r"(a[2]), "r"(a[3]), "r"(b[0]), "r"(b[1]));
    }
}
__device__ __forceinline__ void splitv(float v, __nv_bfloat16& h, __nv_bfloat16& l){
    h = __float2bfloat16(v);
    l = __float2bfloat16(v - __bfloat162float(h));
}
__device__ __forceinline__ void splitv(float v, __half& h, __half& l){
    h = __float2half_rn(v);
    l = __float2half_rn(v - __half2float(h));
}
__device__ __forceinline__ uint16_t u16of(__half v){ return *(uint16_t*)&v; }
__device__ __forceinline__ uint16_t u16of(__nv_bfloat16 v){ return *(uint16_t*)&v; }

// ---------------------------------------------------------------------------
// split GEMM core via mma.sync (proven round-9 structure)
// ---------------------------------------------------------------------------
#define NSTAGE    4
#define STG_ARR   6144                 // 128 rows * 48B
#define STG_BYTES 24576                // 4 arrays
#define HG_SMEM   (NSTAGE * STG_BYTES) // 98304

template<bool FP16, typename OT>
__device__ __forceinline__ void hg_core(
    const uint16_t* __restrict__ Ah, const uint16_t* __restrict__ Al,
    const uint16_t* __restrict__ Bh, const uint16_t* __restrict__ Bl,
    float* __restrict__ Cp, OT* __restrict__ Ch, OT* __restrict__ Cl,
    const float* __restrict__ e0,
    int N, int K, int lda, int ldb, int m0, int n0, int epi, char* sm)
{
    int tid = threadIdx.x, lane = tid & 31, wid = tid >> 5;
    int wy = wid & 1, wx = wid >> 1;
    uint32_t sb = sm2u32(sm);

    int arr0 = tid >> 7;
    int rowa = tid & 127;
    const uint16_t* p0 = ((arr0 == 0) ? Ah : Al) + (size_t)(m0 + rowa) * lda;
    const uint16_t* p1 = ((arr0 == 0) ? Bh : Bl) + (size_t)(n0 + rowa) * ldb;
    uint32_t so0 = (uint32_t)(arr0 * STG_ARR + rowa * 48);
    uint32_t so1 = so0 + 2 * STG_ARR;

    float acc[4][4][4];
    #pragma unroll
    for (int i = 0; i < 4; i++)
        #pragma unroll
        for (int j = 0; j < 4; j++)
            #pragma unroll
            for (int q = 0; q < 4; q++) acc[i][j][q] = 0.f;

    uint32_t a_row = (uint32_t)(wy * 64 + (lane & 15));
    uint32_t a_kh  = (uint32_t)((lane >> 4) * 8);
    uint32_t b_row0 = (uint32_t)(wx * 32 + (lane & 7) + ((lane >> 4) * 8));
    uint32_t b_kh   = (uint32_t)(((lane >> 3) & 1) * 8);

    const int NC = K >> 4;

    #pragma unroll
    for (int s = 0; s < 3; s++){
        uint32_t d = sb + (uint32_t)s * STG_BYTES;
        int kk = s * 16;
        cpa16(d + so0,      p0 + kk);  cpa16(d + so0 + 16, p0 + kk + 8);
        cpa16(d + so1,      p1 + kk);  cpa16(d + so1 + 16, p1 + kk + 8);
        cpa_commit();
    }

    #pragma unroll 4
    for (int c = 0; c < NC; c++){
        cpa_wait<2>();
        __syncthreads();
        if (c + 3 < NC){
            uint32_t d = sb + (uint32_t)((c + 3) & 3) * STG_BYTES;
            int kk = (c + 3) << 4;
            cpa16(d + so0,      p0 + kk);  cpa16(d + so0 + 16, p0 + kk + 8);
            cpa16(d + so1,      p1 + kk);  cpa16(d + so1 + 16, p1 + kk + 8);
        }
        cpa_commit();

        uint32_t base = sb + (uint32_t)(c & 3) * STG_BYTES;

        uint32_t bh[2][4], bl[2][4];
        #pragma unroll
        for (int bi = 0; bi < 2; bi++){
            uint32_t bo = base + 2*STG_ARR + (b_row0 + bi * 16) * 48 + b_kh * 2;
            ldsm_x4(bh[bi], bo);
            ldsm_x4(bl[bi], bo + STG_ARR);
        }
        #pragma unroll
        for (int mf = 0; mf < 4; mf++){
            uint32_t ah[4], al[4];
            uint32_t ao = base + (a_row + mf * 16) * 48 + a_kh * 2;
            ldsm_x4(ah, ao);
            ldsm_x4(al, ao + STG_ARR);
            #pragma unroll
            for (int nf = 0; nf < 4; nf++){
                const uint32_t* bhp = &bh[nf >> 1][(nf & 1) * 2];
                const uint32_t* blp = &bl[nf >> 1][(nf & 1) * 2];
                mma_any<FP16>(acc[mf][nf], ah, bhp);
                mma_any<FP16>(acc[mf][nf], ah, blp);
                mma_any<FP16>(acc[mf][nf], al, bhp);
            }
        }
    }

    #pragma unroll
    for (int mf = 0; mf < 4; mf++){
        int row0 = m0 + wy * 64 + mf * 16 + (lane >> 2);
        #pragma unroll
        for (int nf = 0; nf < 4; nf++){
            int col = n0 + wx * 32 + nf * 8 + (lane & 3) * 2;
            float v[4] = {acc[mf][nf][0], acc[mf][nf][1], acc[mf][nf][2], acc[mf][nf][3]};
            if (epi == 1){
                #pragma unroll
                for (int q = 0; q < 4; q++) v[q] = v[q] / (1.f + expf(-v[q]));
            } else if (epi == 2 || epi == 3){
                #pragma unroll
                for (int q = 0; q < 4; q++) v[q] = tanhf(v[q]);
            } else if (epi == 4){
                v[0] += e0[col]; v[1] += e0[col+1];
                v[2] += e0[col]; v[3] += e0[col+1];
            }
            size_t i01 = (size_t)row0 * N + col;
            size_t i23 = (size_t)(row0 + 8) * N + col;
            if (epi == 3){
                OT h[4], l[4];
                #pragma unroll
                for (int q = 0; q < 4; q++) splitv(v[q], h[q], l[q]);
                *(uint32_t*)(Ch + i01) = (uint32_t)u16of(h[0]) | ((uint32_t)u16of(h[1]) << 16);
                *(uint32_t*)(Cl + i01) = (uint32_t)u16of(l[0]) | ((uint32_t)u16of(l[1]) << 16);
                *(uint32_t*)(Ch + i23) = (uint32_t)u16of(h[2]) | ((uint32_t)u16of(h[3]) << 16);
                *(uint32_t*)(Cl + i23) = (uint32_t)u16of(l[2]) | ((uint32_t)u16of(l[3]) << 16);
            } else {
                *(float2*)(Cp + i01) = make_float2(v[0], v[1]);
                *(float2*)(Cp + i23) = make_float2(v[2], v[3]);
            }
        }
    }
}

__global__ void __launch_bounds__(256, 2) hgemm_one(
    const __nv_bfloat16* __restrict__ Ah, const __nv_bfloat16* __restrict__ Al,
    const __nv_bfloat16* __restrict__ Bh, const __nv_bfloat16* __restrict__ Bl,
    float* __restrict__ Cp, int N, int K, int epi)
{
    extern __shared__ char sm[];
    hg_core<false, __nv_bfloat16>((const uint16_t*)Ah, (const uint16_t*)Al,
        (const uint16_t*)Bh, (const uint16_t*)Bl,
        Cp, (__nv_bfloat16*)nullptr, (__nv_bfloat16*)nullptr, nullptr,
        N, K, K, K, blockIdx.y * 128, blockIdx.x * 128, epi, sm);
}

__global__ void __launch_bounds__(256, 2) hgemm_kvrg(
    const __nv_bfloat16* __restrict__ abh, const __nv_bfloat16* __restrict__ abl,
    const __nv_bfloat16* __restrict__ wbh, const __nv_bfloat16* __restrict__ wbl,
    float* __restrict__ C0, float* __restrict__ C1,
    float* __restrict__ C2, float* __restrict__ C3)
{
    extern __shared__ char sm[];
    int z = blockIdx.z;
    float* Cp = (z == 0) ? C0 : (z == 1) ? C1 : (z == 2) ? C2 : C3;
    hg_core<false, __nv_bfloat16>(
        (const uint16_t*)(abh + (size_t)z * SZq), (const uint16_t*)(abl + (size_t)z * SZq),
        (const uint16_t*)(wbh + (size_t)z * WWq), (const uint16_t*)(wbl + (size_t)z * WWq),
        Cp, (__nv_bfloat16*)nullptr, (__nv_bfloat16*)nullptr, nullptr,
        Cq, Cq, Cq, Cq, blockIdx.y * 128, blockIdx.x * 128, (z == 3) ? 1 : 0, sm);
}

__global__ void __launch_bounds__(256, 2) hgemm_h(
    const __half* __restrict__ Ah, const __half* __restrict__ Al,
    const __half* __restrict__ Bh, const __half* __restrict__ Bl,
    float* __restrict__ Cp, __half* __restrict__ Ch, __half* __restrict__ Cl,
    const float* __restrict__ e0, int N, int K, int lda, int ldb, int epi)
{
    extern __shared__ char sm[];
    hg_core<true, __half>((const uint16_t*)Ah, (const uint16_t*)Al,
        (const uint16_t*)Bh, (const uint16_t*)Bl,
        Cp, Ch, Cl, e0,
        N, K, lda, ldb, blockIdx.y * 128, blockIdx.x * 128, epi, sm);
}

// ---------------------------------------------------------------------------
// FFMA2 helpers
// ---------------------------------------------------------------------------
__device__ __forceinline__ void fma2(ull& d, ull a, ull b){
    asm("fma.rn.f32x2 %0, %1, %2, %0;" : "+l"(d) : "l"(a), "l"(b));
}
__device__ __forceinline__ float2 unp(ull v){
    float2 r; asm("mov.b64 {%0, %1}, %2;" : "=f"(r.x), "=f"(r.y) : "l"(v)); return r;
}
__device__ __forceinline__ ull pack2(float v){
    ull r; asm("mov.b64 %0, {%1, %1};" : "=l"(r) : "f"(v)); return r;
}
__device__ __forceinline__ ull pack2f(float x, float y){
    ull r; asm("mov.b64 %0, {%1, %2};" : "=l"(r) : "f"(x), "f"(y)); return r;
}

// ---------------------------------------------------------------------------
// ddlerp MIX GEMM (K=32), SINGLE load phase, ONE barrier.
// A non-duplicated; compute loop uses 4x LDS.128 total per k-step
// (2 broadcast A + 2 B) — smem issue count cut 3x vs round 13.
// f = blockIdx.x (fastest) for L2 reuse of x/dxa.
// f=0 -> fp16 hi/lo xx0 (w_in); f=1..4 -> bf16 hi/lo slots 0..3 (k,v,r,g).
// ---------------------------------------------------------------------------
__global__ void __launch_bounds__(256) mix_gemm(
    const float* __restrict__ lorap, const float* __restrict__ BloraT,
    const float* __restrict__ x, const float* __restrict__ dxa,
    const float* __restrict__ lam,
    __half* __restrict__ xx0h, __half* __restrict__ xx0l,
    __nv_bfloat16* __restrict__ abh, __nv_bfloat16* __restrict__ abl)
{
    __shared__ __align__(16) float As[32][128];    // 16 KB (non-duplicated)
    __shared__ __align__(16) float Bs[32][128];    // 16 KB

    int f = blockIdx.x;
    const float* A  = lorap  + f*32;
    const float* Bm = BloraT + f*32768;
    const float* e2 = lam    + f*Cq;

    int tid  = threadIdx.x;
    int m0   = blockIdx.y * 128, n0 = blockIdx.z * 128;
    int ty = tid >> 4, tx = tid & 15;

    // single load phase: 4 float4 of A + 4 float4 of B per thread
    #pragma unroll
    for (int t2 = 0; t2 < 4; t2++){
        int i = t2 * 256 + tid;          // 0..1023
        int row = i >> 3, q = (i & 7) * 4;
        float4 av = *(const float4*)(A + (size_t)(m0 + row) * 256 + q);
        As[q+0][row] = av.x;
        As[q+1][row] = av.y;
        As[q+2][row] = av.z;
        As[q+3][row] = av.w;
        float4 bv = *(const float4*)(Bm + (size_t)(n0 + row) * 32 + q);
        Bs[q+0][row] = bv.x;
        Bs[q+1][row] = bv.y;
        Bs[q+2][row] = bv.z;
        Bs[q+3][row] = bv.w;
    }
    __syncthreads();

    ull acc[8][4];
    #pragma unroll
    for (int i = 0; i < 8; i++)
        #pragma unroll
        for (int p = 0; p < 4; p++) acc[i][p] = 0ull;

    #pragma unroll 8
    for (int kk = 0; kk < 32; kk++) {
        const float4* ar4 = (const float4*)As[kk];
        const float4* br4 = (const float4*)Bs[kk];
        float4 av0 = ar4[ty*2], av1 = ar4[ty*2+1];       // 2x LDS.128 (broadcast)
        float4 bv0 = br4[tx*2], bv1 = br4[tx*2+1];       // 2x LDS.128
        ull a_[8], b_[4];
        a_[0] = pack2(av0.x); a_[1] = pack2(av0.y);
        a_[2] = pack2(av0.z); a_[3] = pack2(av0.w);
        a_[4] = pack2(av1.x); a_[5] = pack2(av1.y);
        a_[6] = pack2(av1.z); a_[7] = pack2(av1.w);
        b_[0] = pack2f(bv0.x, bv0.y); b_[1] = pack2f(bv0.z, bv0.w);
        b_[2] = pack2f(bv1.x, bv1.y); b_[3] = pack2f(bv1.z, bv1.w);
        #pragma unroll
        for (int i = 0; i < 8; i++)
            #pragma unroll
            for (int p = 0; p < 4; p++) fma2(acc[i][p], a_[i], b_[p]);
    }

    #pragma unroll
    for (int i = 0; i < 8; i++) {
        size_t m = (size_t)(m0 + ty*8 + i);
        #pragma unroll
        for (int p = 0; p < 4; p++) {
            float2 vv = unp(acc[i][p]);
            int n = n0 + tx*8 + 2*p;
            size_t idx = m * (size_t)Cq + n;
            float vx = x[idx]   + dxa[idx]   * (e2[n]   + vv.x);
            float vy = x[idx+1] + dxa[idx+1] * (e2[n+1] + vv.y);
            if (f == 0) {
                __half hx, lx, hy, ly;
                splitv(vx, hx, lx); splitv(vy, hy, ly);
                __half2 hp; hp.x = hx; hp.y = hy;
                __half2 lp; lp.x = lx; lp.y = ly;
                *(__half2*)(xx0h + idx) = hp;
                *(__half2*)(xx0l + idx) = lp;
            } else {
                size_t o = (size_t)(f-1) * SZq + idx;
                __nv_bfloat162 hp, lp;
                splitv(vx, hp.x, lp.x);
                splitv(vy, hp.y, lp.y);
                *(__nv_bfloat162*)(abh + o) = hp;
                *(__nv_bfloat162*)(abl + o) = lp;
            }
        }
    }
}

// ---------------------------------------------------------------------------
// prep: dxa = shift(x) - x (fp32) ; xm = x + dxa * miu_x -> bf16 hi/lo
// ---------------------------------------------------------------------------
__global__ void __launch_bounds__(256) prep_kernel(
    const float4* __restrict__ x4, const float4* __restrict__ mu4,
    float4* __restrict__ dxa4,
    __nv_bfloat16* __restrict__ xmh, __nv_bfloat16* __restrict__ xml)
{
    size_t i = (size_t)blockIdx.x * 256 + threadIdx.x;
    int m = (int)(i >> 8);
    int t = m & (Tq - 1);
    float4 xv = x4[i];
    float4 xl = make_float4(0.f, 0.f, 0.f, 0.f);
    if (t) xl = x4[i - 256];
    float4 mu = mu4[i & 255];
    float4 d  = make_float4(xl.x - xv.x, xl.y - xv.y, xl.z - xv.z, xl.w - xv.w);
    float xm0 = fmaf(d.x, mu.x, xv.x), xm1 = fmaf(d.y, mu.y, xv.y);
    float xm2 = fmaf(d.z, mu.z, xv.z), xm3 = fmaf(d.w, mu.w, xv.w);
    dxa4[i] = d;
    __nv_bfloat162 h0, l0, h1, l1;
    splitv(xm0, h0.x, l0.x); splitv(xm1, h0.y, l0.y);
    splitv(xm2, h1.x, l1.x); splitv(xm3, h1.y, l1.y);
    ((__nv_bfloat162*)xmh)[i*2]   = h0;
    ((__nv_bfloat162*)xmh)[i*2+1] = h1;
    ((__nv_bfloat162*)xml)[i*2]   = l0;
    ((__nv_bfloat162*)xml)[i*2+1] = l1;
}

// ---------------------------------------------------------------------------
// transposes: AloraT -> bf16 hi/lo; tdAT, tdBT -> fp16 hi/lo; BloraT fp32
// ---------------------------------------------------------------------------
__global__ void __launch_bounds__(256) transpose_all(
    __nv_bfloat16* __restrict__ AloraTh, __nv_bfloat16* __restrict__ AloraTl,
    const float* __restrict__ A_lora,
    __half* __restrict__ tdATh, __half* __restrict__ tdATl,
    const float* __restrict__ td_A,
    __half* __restrict__ tdBTh, __half* __restrict__ tdBTl,
    const float* __restrict__ td_B,
    float* __restrict__ BloraT, const float* __restrict__ B_lora)
{
    int i = blockIdx.x * 256 + threadIdx.x;
    if (i < 262144) {
        int n = i >> 10, k = i & 1023;
        float v = (n < 160) ? A_lora[k*160 + n] : 0.f;
        __nv_bfloat16 h, l; splitv(v, h, l);
        AloraTh[i] = h; AloraTl[i] = l;
    } else if (i < 393216) {
        int j = i - 262144; int n = j >> 10, k = j & 1023;
        float v = (n < 64) ? td_A[k*64 + n] : 0.f;
        __half h, l; splitv(v, h, l);
        tdATh[j] = h; tdATl[j] = l;
    } else if (i < 458752) {
        int j = i - 393216; int n = j >> 6, k = j & 63;
        float v = td_B[k*1024 + n];
        __half h, l; splitv(v, h, l);
        tdBTh[j] = h; tdBTl[j] = l;
    } else if (i < 622592) {
        int j = i - 458752;
        int f = j >> 15, rr = j & 32767, n = rr >> 5, k = rr & 31;
        BloraT[j] = B_lora[(f*32 + k)*1024 + n];
    }
}

// ---------------------------------------------------------------------------
// Weight bf16 hi/lo conversion (Wk,Wv,Wr,Wg,Wo)
// ---------------------------------------------------------------------------
__global__ void __launch_bounds__(256) wconv_kernel(
    const float* __restrict__ w0, const float* __restrict__ w1,
    const float* __restrict__ w2, const float* __restrict__ w3,
    const float* __restrict__ w4,
    __nv_bfloat16* __restrict__ h, __nv_bfloat16* __restrict__ l)
{
    int i = blockIdx.x * 256 + threadIdx.x;
    int w = i >> 20;
    int j = i & 1048575;
    const float* src = (w == 0) ? w0 : (w == 1) ? w1 : (w == 2) ? w2 : (w == 3) ? w3 : w4;
    float x = src[j];
    __nv_bfloat16 hh, ll; splitv(x, hh, ll);
    h[i] = hh;
    l[i] = ll;
}

// ---------------------------------------------------------------------------
// WKV6 scan — 4-buffer ring, ONE barrier per TWO timesteps; t+2/t+3 loads
// overlap compute of t/t+1.
// ---------------------------------------------------------------------------
__global__ void __launch_bounds__(256) wkv6_kernel(
    const float* __restrict__ rp, const float* __restrict__ kp,
    const float* __restrict__ vp, const float* __restrict__ wp,
    const float* __restrict__ up, float* __restrict__ yp)
{
    __shared__ float4 pk[4][4][17];
    __shared__ float  sv[4][64];
    int bh = blockIdx.x;
    int b = bh >> 4, h = bh & 15;
    size_t base = ((size_t)b * Tq) * Cq + h * 64;
    int tid = threadIdx.x;
    int j = tid >> 2, rg = tid & 3;
    float uu = 0.f;
    if (tid < 64) uu = up[h * 64 + tid];
    float S[16];
    #pragma unroll
    for (int i = 0; i < 16; i++) S[i] = 0.f;

    float lk0 = 0.f, lr0 = 0.f, lw0 = 0.f, lv0 = 0.f;
    float lk1 = 0.f, lr1 = 0.f, lw1 = 0.f, lv1 = 0.f;
    if (tid < 64){
        size_t o0 = base + tid;
        lk0 = kp[o0]; lr0 = rp[o0]; lw0 = wp[o0]; lv0 = vp[o0];
        size_t o1 = o0 + Cq;
        lk1 = kp[o1]; lr1 = rp[o1]; lw1 = wp[o1]; lv1 = vp[o1];
    }

    for (int t = 0; t < Tq; t += 2) {
        int b0 = t & 3, b1 = (t + 1) & 3;
        size_t off = base + (size_t)t * Cq;
        if (tid < 64) {
            sv[b0][tid] = lv0;
            pk[b0][tid >> 4][tid & 15] = make_float4(lk0, uu * lk0, lr0, expf(-expf(lw0)));
            sv[b1][tid] = lv1;
            pk[b1][tid >> 4][tid & 15] = make_float4(lk1, uu * lk1, lr1, expf(-expf(lw1)));
        }
        __syncthreads();
        if (t + 2 < Tq && tid < 64){
            size_t o2 = off + 2 * Cq + tid;
            lk0 = kp[o2]; lr0 = rp[o2]; lw0 = wp[o2]; lv0 = vp[o2];
            size_t o3 = o2 + Cq;
            lk1 = kp[o3]; lr1 = rp[o3]; lw1 = wp[o3]; lv1 = vp[o3];
        }
        // step t
        {
            float vj = sv[b0][j];
            float yv = 0.f;
            #pragma unroll
            for (int ii = 0; ii < 16; ii++) {
                float4 p = pk[b0][rg][ii];
                float s = S[ii];
                yv = fmaf(p.z, fmaf(p.y, vj, s), yv);
                S[ii] = fmaf(p.w, s, p.x * vj);
            }
            yv += __shfl_xor_sync(0xffffffffu, yv, 1);
            yv += __shfl_xor_sync(0xffffffffu, yv, 2);
            if (rg == 0) yp[off + j] = yv;
        }
        // step t+1
        {
            float vj = sv[b1][j];
            float yv = 0.f;
            #pragma unroll
            for (int ii = 0; ii < 16; ii++) {
                float4 p = pk[b1][rg][ii];
                float s = S[ii];
                yv = fmaf(p.z, fmaf(p.y, vj, s), yv);
                S[ii] = fmaf(p.w, s, p.x * vj);
            }
            yv += __shfl_xor_sync(0xffffffffu, yv, 1);
            yv += __shfl_xor_sync(0xffffffffu, yv, 2);
            if (rg == 0) yp[off + Cq + j] = yv;
        }
    }
}

// ---------------------------------------------------------------------------
// GroupNorm * gate -> bf16 hi/lo
// ---------------------------------------------------------------------------
__global__ void __launch_bounds__(256) gnorm_kernel(
    const float* __restrict__ y, const float* __restrict__ g,
    const float* __restrict__ gamma, const float* __restrict__ beta,
    __nv_bfloat16* __restrict__ ygh, __nv_bfloat16* __restrict__ ygl)
{
    int m = blockIdx.x, tid = threadIdx.x;
    size_t i4 = (size_t)m * 256 + tid;
    float4 yv = ((const float4*)y)[i4];
    float s  = yv.x + yv.y + yv.z + yv.w;
    float ss = yv.x*yv.x + yv.y*yv.y + yv.z*yv.z + yv.w*yv.w;
    #pragma unroll
    for (int o = 1; o < 16; o <<= 1) {
        s  += __shfl_xor_sync(0xffffffffu, s,  o);
        ss += __shfl_xor_sync(0xffffffffu, ss, o);
    }
    float mean = s * (1.f / 64.f);
    float var  = ss * (1.f / 64.f) - mean * mean;
    float rstd = rsqrtf(fmaxf(var, 0.f) + 1.6e-4f);
    float4 ga = ((const float4*)gamma)[tid];
    float4 be = ((const float4*)beta)[tid];
    float4 gv = ((const float4*)g)[i4];
    float o0 = ((yv.x - mean) * rstd * ga.x + be.x) * gv.x;
    float o1 = ((yv.y - mean) * rstd * ga.y + be.y) * gv.y;
    float o2 = ((yv.z - mean) * rstd * ga.z + be.z) * gv.z;
    float o3 = ((yv.w - mean) * rstd * ga.w + be.w) * gv.w;

    __nv_bfloat162 hp0, lp0, hp1, lp1;
    splitv(o0, hp0.x, lp0.x); splitv(o1, hp0.y, lp0.y);
    splitv(o2, hp1.x, lp1.x); splitv(o3, hp1.y, lp1.y);
    ((__nv_bfloat162*)ygh)[i4*2]   = hp0;
    ((__nv_bfloat162*)ygh)[i4*2+1] = hp1;
    ((__nv_bfloat162*)ygl)[i4*2]   = lp0;
    ((__nv_bfloat162*)ygl)[i4*2+1] = lp1;
}

// ---------------------------------------------------------------------------
// Launch
// ---------------------------------------------------------------------------
extern "C" void kernel_launch(void* const* d_in, const int* in_sizes, int n_in,
                              void* d_out, int out_size)
{
    (void)in_sizes; (void)n_in; (void)out_size;
    const float* x       = (const float*)d_in[0];
    const float* miu_x   = (const float*)d_in[1];
    const float* lambda_ = (const float*)d_in[2];
    const float* A_lora  = (const float*)d_in[3];
    const float* B_lora  = (const float*)d_in[4];
    const float* td_miu  = (const float*)d_in[5];
    const float* td_A    = (const float*)d_in[6];
    const float* td_B    = (const float*)d_in[7];
    const float* u       = (const float*)d_in[8];
    const float* Wr      = (const float*)d_in[9];
    const float* Wk      = (const float*)d_in[10];
    const float* Wv      = (const float*)d_in[11];
    const float* Wg      = (const float*)d_in[12];
    const float* Wo      = (const float*)d_in[13];
    const float* gamma   = (const float*)d_in[14];
    const float* beta    = (const float*)d_in[15];
    float* out = (float*)d_out;

    float *p_dxa,*p_k,*p_v,*p_r,*p_g,*p_w,*p_y,*p_lorap,*p_BloraT;
    __nv_bfloat16 *p_xmh,*p_xml,*p_abh,*p_abl,*p_ygh,*p_ygl,*p_wbh,*p_wbl,
                  *p_AloraTh,*p_AloraTl;
    __half *p_xx0h,*p_xx0l,*p_tdhh,*p_tdhl,*p_tdATh,*p_tdATl,*p_tdBTh,*p_tdBTl;
    { void* t;
      cudaGetSymbolAddress(&t, g_dxa);     p_dxa     = (float*)t;
      cudaGetSymbolAddress(&t, g_k);       p_k       = (float*)t;
      cudaGetSymbolAddress(&t, g_v);       p_v       = (float*)t;
      cudaGetSymbolAddress(&t, g_r);       p_r       = (float*)t;
      cudaGetSymbolAddress(&t, g_g);       p_g       = (float*)t;
      cudaGetSymbolAddress(&t, g_w);       p_w       = (float*)t;
      cudaGetSymbolAddress(&t, g_y);       p_y       = (float*)t;
      cudaGetSymbolAddress(&t, g_lorap);   p_lorap   = (float*)t;
      cudaGetSymbolAddress(&t, g_BloraT);  p_BloraT  = (float*)t;
      cudaGetSymbolAddress(&t, g_xmh);     p_xmh     = (__nv_bfloat16*)t;
      cudaGetSymbolAddress(&t, g_xml);     p_xml     = (__nv_bfloat16*)t;
      cudaGetSymbolAddress(&t, g_abh);     p_abh     = (__nv_bfloat16*)t;
      cudaGetSymbolAddress(&t, g_abl);     p_abl     = (__nv_bfloat16*)t;
      cudaGetSymbolAddress(&t, g_ygh);     p_ygh     = (__nv_bfloat16*)t;
      cudaGetSymbolAddress(&t, g_ygl);     p_ygl     = (__nv_bfloat16*)t;
      cudaGetSymbolAddress(&t, g_wbh);     p_wbh     = (__nv_bfloat16*)t;
      cudaGetSymbolAddress(&t, g_wbl);     p_wbl     = (__nv_bfloat16*)t;
      cudaGetSymbolAddress(&t, g_AloraTh); p_AloraTh = (__nv_bfloat16*)t;
      cudaGetSymbolAddress(&t, g_AloraTl); p_AloraTl = (__nv_bfloat16*)t;
      cudaGetSymbolAddress(&t, g_xx0h);    p_xx0h    = (__half*)t;
      cudaGetSymbolAddress(&t, g_xx0l);    p_xx0l    = (__half*)t;
      cudaGetSymbolAddress(&t, g_tdhh);    p_tdhh    = (__half*)t;
      cudaGetSymbolAddress(&t, g_tdhl);    p_tdhl    = (__half*)t;
      cudaGetSymbolAddress(&t, g_tdATh);   p_tdATh   = (__half*)t;
      cudaGetSymbolAddress(&t, g_tdATl);   p_tdATl   = (__half*)t;
      cudaGetSymbolAddress(&t, g_tdBTh);   p_tdBTh   = (__half*)t;
      cudaGetSymbolAddress(&t, g_tdBTl);   p_tdBTl   = (__half*)t;
    }

    cudaFuncSetAttribute(hgemm_one,  cudaFuncAttributeMaxDynamicSharedMemorySize, HG_SMEM);
    cudaFuncSetAttribute(hgemm_kvrg, cudaFuncAttributeMaxDynamicSharedMemorySize, HG_SMEM);
    cudaFuncSetAttribute(hgemm_h,    cudaFuncAttributeMaxDynamicSharedMemorySize, HG_SMEM);

    // 0: token shift + static lerp (xm -> bf16 hi/lo)
    prep_kernel<<<BTq * Cq / 4 / 256, 256>>>((const float4*)x, (const float4*)miu_x,
                                             (float4*)p_dxa, p_xmh, p_xml);
    // 1: weight transposes
    transpose_all<<<(622592 + 255) / 256, 256>>>(p_AloraTh, p_AloraTl, A_lora,
                                                 p_tdATh, p_tdATl, td_A,
                                                 p_tdBTh, p_tdBTl, td_B,
                                                 p_BloraT, B_lora);
    // 2: lora_h = tanh(xm @ A_lora)
    hgemm_one<<<dim3(2, 128), 256, HG_SMEM>>>(p_xmh, p_xml, p_AloraTh, p_AloraTl,
                                              p_lorap, 256, Cq, 2);
    // 3: ddlerp mix (f=0 -> fp16 hi/lo xx0; f=1..4 -> bf16 hi/lo k,v,r,g)
    mix_gemm<<<dim3(5, 128, 8), 256>>>(p_lorap, p_BloraT, x, p_dxa, lambda_,
                                       p_xx0h, p_xx0l, p_abh, p_abl);
    // 4: big weight hi/lo
    wconv_kernel<<<5 * 1048576 / 256, 256>>>(Wk, Wv, Wr, Wg, Wo, p_wbh, p_wbl);
    // 5: merged projections k, v, r, g
    hgemm_kvrg<<<dim3(8, 128, 4), 256, HG_SMEM>>>(p_abh, p_abl, p_wbh, p_wbl,
                                                  p_k, p_v, p_r, p_g);
    // 6: tdh = tanh(w_in @ td_A) -> fp16 hi/lo (padded N=128)
    hgemm_h<<<dim3(1, 128), 256, HG_SMEM>>>(p_xx0h, p_xx0l, p_tdATh, p_tdATl,
                                            nullptr, p_tdhh, p_tdhl, nullptr,
                                            128, Cq, Cq, Cq, 3);
    // 7: w = td_miu + tdh @ td_B   (A stride 128, K=64)
    hgemm_h<<<dim3(8, 128), 256, HG_SMEM>>>(p_tdhh, p_tdhl, p_tdBTh, p_tdBTl,
                                            p_w, nullptr, nullptr, td_miu,
                                            Cq, 64, 128, 64, 4);
    // 8: WKV6 scan
    wkv6_kernel<<<Bq * Hq, 256>>>(p_r, p_k, p_v, p_w, u, p_y);
    // 9: GroupNorm * gate -> bf16 hi/lo
    gnorm_kernel<<<BTq, 256>>>(p_y, p_g, gamma, beta, p_ygh, p_ygl);
    // 10: output projection
    hgemm_one<<<dim3(8, 128), 256, HG_SMEM>>>(p_ygh, p_ygl, p_wbh + 4*WWq, p_wbl + 4*WWq,
                                              out, Cq, Cq, 0);
}

// round 15
// speedup vs baseline: 1.5593x; 1.0396x over previous
#include <cuda_runtime.h>
#include <cuda_bf16.h>
#include <cuda_fp16.h>
#include <math.h>
#include <stdint.h>

#define Bq 8
#define Tq 2048
#define Cq 1024
#define Hq 16
#define BTq (Bq*Tq)
#define WWq (Cq*Cq)

typedef unsigned long long ull;
static const size_t SZq = (size_t)BTq * Cq;

// ---------------------------------------------------------------------------
// Scratch (static device globals — no runtime allocation)
// ---------------------------------------------------------------------------
__device__ float g_dxa [BTq*Cq];
__device__ float g_k   [BTq*Cq];
__device__ float g_v   [BTq*Cq];
__device__ float g_r   [BTq*Cq];
__device__ float g_g   [BTq*Cq];
__device__ float g_w   [BTq*Cq];
__device__ float g_y   [BTq*Cq];
__device__ float g_lorap [BTq*256];          // tanh(xm @ A_lora) fp32 (padded 256)
__device__ float g_BloraT[5*1024*32];        // B_lora^T per branch, fp32

__device__ __nv_bfloat16 g_xmh[BTq*Cq];      // xm hi/lo (bf16 split)
__device__ __nv_bfloat16 g_xml[BTq*Cq];
__device__ __nv_bfloat16 g_abh[4*BTq*Cq];    // k,v,r,g branch inputs hi
__device__ __nv_bfloat16 g_abl[4*BTq*Cq];    // lo
__device__ __nv_bfloat16 g_ygh[BTq*Cq];
__device__ __nv_bfloat16 g_ygl[BTq*Cq];
__device__ __nv_bfloat16 g_wbh[5*WWq];       // Wk,Wv,Wr,Wg,Wo hi
__device__ __nv_bfloat16 g_wbl[5*WWq];       // lo
__device__ __nv_bfloat16 g_AloraTh[256*1024];
__device__ __nv_bfloat16 g_AloraTl[256*1024];

// fp16-split td path (2^-22 residual — precision-safe for the decay scan)
__device__ __half g_xx0h[BTq*Cq];            // w_in branch hi/lo
__device__ __half g_xx0l[BTq*Cq];
__device__ __half g_tdhh[BTq*128];           // tanh(w_in @ td_A) hi/lo (padded 128)
__device__ __half g_tdhl[BTq*128];
__device__ __half g_tdATh[128*1024];
__device__ __half g_tdATl[128*1024];
__device__ __half g_tdBTh[1024*64];
__device__ __half g_tdBTl[1024*64];

// ---------------------------------------------------------------------------
// PTX helpers (sm_80+ — valid on compute_103 virtual arch)
// ---------------------------------------------------------------------------
__device__ __forceinline__ uint32_t sm2u32(const void* p){
    uint32_t a;
    asm("{ .reg .u64 t; cvta.to.shared.u64 t, %1; cvt.u32.u64 %0, t; }" : "=r"(a) : "l"(p));
    return a;
}
__device__ __forceinline__ void cpa16(uint32_t dst, const void* src){
    asm volatile("cp.async.cg.shared.global [%0], [%1], 16;" :: "r"(dst), "l"(src) : "memory");
}
__device__ __forceinline__ void cpa_commit(){
    asm volatile("cp.async.commit_group;" ::: "memory");
}
template<int N>
__device__ __forceinline__ void cpa_wait(){
    asm volatile("cp.async.wait_group %0;" :: "n"(N) : "memory");
}
__device__ __forceinline__ void ldsm_x4(uint32_t* r, uint32_t addr){
    asm volatile("ldmatrix.sync.aligned.m8n8.x4.shared.b16 {%0,%1,%2,%3}, [%4];"
        : "=r"(r[0]), "=r"(r[1]), "=r"(r[2]), "=r"(r[3]) : "r"(addr));
}
template<bool FP16>
__device__ __forceinline__ void mma_any(float* d, const uint32_t* a, const uint32_t* b){
    if (FP16){
        asm volatile("mma.sync.aligned.m16n8k16.row.col.f32.f16.f16.f32 "
            "{%0,%1,%2,%3}, {%4,%5,%6,%7}, {%8,%9}, {%0,%1,%2,%3};"
            : "+f"(d[0]), "+f"(d[1]), "+f"(d[2]), "+f"(d[3])
            : "r"(a[0]), "r"(a[1]), "r"(a[2]), "r"(a[3]), "r"(b[0]), "r"(b[1]));
    } else {
        asm volatile("mma.sync.aligned.m16n8k16.row.col.f32.bf16.bf16.f32 "
            "{%0,%1,%2,%3}, {%4,%5,%6,%7}, {%8,%9}, {%0,%1,%2,%3};"
            : "+f"(d[0]), "+f"(d[1]), "+f"(d[2]), "+f"(d[3])
            : "r"(a[0]), "r"(a[1]), "r"(a[2]), "r"(a[3]), "r"(b[0]), "r"(b[1]));
    }
}
__device__ __forceinline__ void splitv(float v, __nv_bfloat16& h, __nv_bfloat16& l){
    h = __float2bfloat16(v);
    l = __float2bfloat16(v - __bfloat162float(h));
}
__device__ __forceinline__ void splitv(float v, __half& h, __half& l){
    h = __float2half_rn(v);
    l = __float2half_rn(v - __half2float(h));
}
__device__ __forceinline__ uint16_t u16of(__half v){ return *(uint16_t*)&v; }
__device__ __forceinline__ uint16_t u16of(__nv_bfloat16 v){ return *(uint16_t*)&v; }

// ---------------------------------------------------------------------------
// split GEMM core via mma.sync (proven round-9 structure)
// ---------------------------------------------------------------------------
#define NSTAGE    4
#define STG_ARR   6144                 // 128 rows * 48B
#define STG_BYTES 24576                // 4 arrays
#define HG_SMEM   (NSTAGE * STG_BYTES) // 98304

template<bool FP16, typename OT>
__device__ __forceinline__ void hg_core(
    const uint16_t* __restrict__ Ah, const uint16_t* __restrict__ Al,
    const uint16_t* __restrict__ Bh, const uint16_t* __restrict__ Bl,
    float* __restrict__ Cp, OT* __restrict__ Ch, OT* __restrict__ Cl,
    const float* __restrict__ e0,
    int N, int K, int lda, int ldb, int m0, int n0, int epi, char* sm)
{
    int tid = threadIdx.x, lane = tid & 31, wid = tid >> 5;
    int wy = wid & 1, wx = wid >> 1;
    uint32_t sb = sm2u32(sm);

    int arr0 = tid >> 7;
    int rowa = tid & 127;
    const uint16_t* p0 = ((arr0 == 0) ? Ah : Al) + (size_t)(m0 + rowa) * lda;
    const uint16_t* p1 = ((arr0 == 0) ? Bh : Bl) + (size_t)(n0 + rowa) * ldb;
    uint32_t so0 = (uint32_t)(arr0 * STG_ARR + rowa * 48);
    uint32_t so1 = so0 + 2 * STG_ARR;

    float acc[4][4][4];
    #pragma unroll
    for (int i = 0; i < 4; i++)
        #pragma unroll
        for (int j = 0; j < 4; j++)
            #pragma unroll
            for (int q = 0; q < 4; q++) acc[i][j][q] = 0.f;

    uint32_t a_row = (uint32_t)(wy * 64 + (lane & 15));
    uint32_t a_kh  = (uint32_t)((lane >> 4) * 8);
    uint32_t b_row0 = (uint32_t)(wx * 32 + (lane & 7) + ((lane >> 4) * 8));
    uint32_t b_kh   = (uint32_t)(((lane >> 3) & 1) * 8);

    const int NC = K >> 4;

    #pragma unroll
    for (int s = 0; s < 3; s++){
        uint32_t d = sb + (uint32_t)s * STG_BYTES;
        int kk = s * 16;
        cpa16(d + so0,      p0 + kk);  cpa16(d + so0 + 16, p0 + kk + 8);
        cpa16(d + so1,      p1 + kk);  cpa16(d + so1 + 16, p1 + kk + 8);
        cpa_commit();
    }

    #pragma unroll 4
    for (int c = 0; c < NC; c++){
        cpa_wait<2>();
        __syncthreads();
        if (c + 3 < NC){
            uint32_t d = sb + (uint32_t)((c + 3) & 3) * STG_BYTES;
            int kk = (c + 3) << 4;
            cpa16(d + so0,      p0 + kk);  cpa16(d + so0 + 16, p0 + kk + 8);
            cpa16(d + so1,      p1 + kk);  cpa16(d + so1 + 16, p1 + kk + 8);
        }
        cpa_commit();

        uint32_t base = sb + (uint32_t)(c & 3) * STG_BYTES;

        uint32_t bh[2][4], bl[2][4];
        #pragma unroll
        for (int bi = 0; bi < 2; bi++){
            uint32_t bo = base + 2*STG_ARR + (b_row0 + bi * 16) * 48 + b_kh * 2;
            ldsm_x4(bh[bi], bo);
            ldsm_x4(bl[bi], bo + STG_ARR);
        }
        #pragma unroll
        for (int mf = 0; mf < 4; mf++){
            uint32_t ah[4], al[4];
            uint32_t ao = base + (a_row + mf * 16) * 48 + a_kh * 2;
            ldsm_x4(ah, ao);
            ldsm_x4(al, ao + STG_ARR);
            #pragma unroll
            for (int nf = 0; nf < 4; nf++){
                const uint32_t* bhp = &bh[nf >> 1][(nf & 1) * 2];
                const uint32_t* blp = &bl[nf >> 1][(nf & 1) * 2];
                mma_any<FP16>(acc[mf][nf], ah, bhp);
                mma_any<FP16>(acc[mf][nf], ah, blp);
                mma_any<FP16>(acc[mf][nf], al, bhp);
            }
        }
    }

    #pragma unroll
    for (int mf = 0; mf < 4; mf++){
        int row0 = m0 + wy * 64 + mf * 16 + (lane >> 2);
        #pragma unroll
        for (int nf = 0; nf < 4; nf++){
            int col = n0 + wx * 32 + nf * 8 + (lane & 3) * 2;
            float v[4] = {acc[mf][nf][0], acc[mf][nf][1], acc[mf][nf][2], acc[mf][nf][3]};
            if (epi == 1){
                #pragma unroll
                for (int q = 0; q < 4; q++) v[q] = v[q] / (1.f + expf(-v[q]));
            } else if (epi == 2 || epi == 3){
                #pragma unroll
                for (int q = 0; q < 4; q++) v[q] = tanhf(v[q]);
            } else if (epi == 4){
                v[0] += e0[col]; v[1] += e0[col+1];
                v[2] += e0[col]; v[3] += e0[col+1];
            }
            size_t i01 = (size_t)row0 * N + col;
            size_t i23 = (size_t)(row0 + 8) * N + col;
            if (epi == 3){
                OT h[4], l[4];
                #pragma unroll
                for (int q = 0; q < 4; q++) splitv(v[q], h[q], l[q]);
                *(uint32_t*)(Ch + i01) = (uint32_t)u16of(h[0]) | ((uint32_t)u16of(h[1]) << 16);
                *(uint32_t*)(Cl + i01) = (uint32_t)u16of(l[0]) | ((uint32_t)u16of(l[1]) << 16);
                *(uint32_t*)(Ch + i23) = (uint32_t)u16of(h[2]) | ((uint32_t)u16of(h[3]) << 16);
                *(uint32_t*)(Cl + i23) = (uint32_t)u16of(l[2]) | ((uint32_t)u16of(l[3]) << 16);
            } else {
                *(float2*)(Cp + i01) = make_float2(v[0], v[1]);
                *(float2*)(Cp + i23) = make_float2(v[2], v[3]);
            }
        }
    }
}

__global__ void __launch_bounds__(256, 2) hgemm_one(
    const __nv_bfloat16* __restrict__ Ah, const __nv_bfloat16* __restrict__ Al,
    const __nv_bfloat16* __restrict__ Bh, const __nv_bfloat16* __restrict__ Bl,
    float* __restrict__ Cp, int N, int K, int epi)
{
    extern __shared__ char sm[];
    hg_core<false, __nv_bfloat16>((const uint16_t*)Ah, (const uint16_t*)Al,
        (const uint16_t*)Bh, (const uint16_t*)Bl,
        Cp, (__nv_bfloat16*)nullptr, (__nv_bfloat16*)nullptr, nullptr,
        N, K, K, K, blockIdx.y * 128, blockIdx.x * 128, epi, sm);
}

__global__ void __launch_bounds__(256, 2) hgemm_kvrg(
    const __nv_bfloat16* __restrict__ abh, const __nv_bfloat16* __restrict__ abl,
    const __nv_bfloat16* __restrict__ wbh, const __nv_bfloat16* __restrict__ wbl,
    float* __restrict__ C0, float* __restrict__ C1,
    float* __restrict__ C2, float* __restrict__ C3)
{
    extern __shared__ char sm[];
    int z = blockIdx.z;
    float* Cp = (z == 0) ? C0 : (z == 1) ? C1 : (z == 2) ? C2 : C3;
    hg_core<false, __nv_bfloat16>(
        (const uint16_t*)(abh + (size_t)z * SZq), (const uint16_t*)(abl + (size_t)z * SZq),
        (const uint16_t*)(wbh + (size_t)z * WWq), (const uint16_t*)(wbl + (size_t)z * WWq),
        Cp, (__nv_bfloat16*)nullptr, (__nv_bfloat16*)nullptr, nullptr,
        Cq, Cq, Cq, Cq, blockIdx.y * 128, blockIdx.x * 128, (z == 3) ? 1 : 0, sm);
}

__global__ void __launch_bounds__(256, 2) hgemm_h(
    const __half* __restrict__ Ah, const __half* __restrict__ Al,
    const __half* __restrict__ Bh, const __half* __restrict__ Bl,
    float* __restrict__ Cp, __half* __restrict__ Ch, __half* __restrict__ Cl,
    const float* __restrict__ e0, int N, int K, int lda, int ldb, int epi)
{
    extern __shared__ char sm[];
    hg_core<true, __half>((const uint16_t*)Ah, (const uint16_t*)Al,
        (const uint16_t*)Bh, (const uint16_t*)Bl,
        Cp, Ch, Cl, e0,
        N, K, lda, ldb, blockIdx.y * 128, blockIdx.x * 128, epi, sm);
}

// ---------------------------------------------------------------------------
// FFMA2 helpers
// ---------------------------------------------------------------------------
__device__ __forceinline__ void fma2(ull& d, ull a, ull b){
    asm("fma.rn.f32x2 %0, %1, %2, %0;" : "+l"(d) : "l"(a), "l"(b));
}
__device__ __forceinline__ float2 unp(ull v){
    float2 r; asm("mov.b64 {%0, %1}, %2;" : "=f"(r.x), "=f"(r.y) : "l"(v)); return r;
}
__device__ __forceinline__ ull pack2(float v){
    ull r; asm("mov.b64 %0, {%1, %1};" : "=l"(r) : "f"(v)); return r;
}
__device__ __forceinline__ ull pack2f(float x, float y){
    ull r; asm("mov.b64 %0, {%1, %2};" : "=l"(r) : "f"(x), "f"(y)); return r;
}

// ---------------------------------------------------------------------------
// ddlerp MIX GEMM (K=32), SINGLE load phase, ONE barrier.
// Epilogue fully vectorized: per output row, 4x LDG.128 (x/dxa) and
// 1x STG.128 per h/l array (was 8x LDG.64 + 8x STG.32).
// f = blockIdx.x (fastest) for L2 reuse of x/dxa.
// f=0 -> fp16 hi/lo xx0 (w_in); f=1..4 -> bf16 hi/lo slots 0..3 (k,v,r,g).
// ---------------------------------------------------------------------------
__global__ void __launch_bounds__(256) mix_gemm(
    const float* __restrict__ lorap, const float* __restrict__ BloraT,
    const float* __restrict__ x, const float* __restrict__ dxa,
    const float* __restrict__ lam,
    __half* __restrict__ xx0h, __half* __restrict__ xx0l,
    __nv_bfloat16* __restrict__ abh, __nv_bfloat16* __restrict__ abl)
{
    __shared__ __align__(16) float As[32][128];    // 16 KB (non-duplicated)
    __shared__ __align__(16) float Bs[32][128];    // 16 KB

    int f = blockIdx.x;
    const float* A  = lorap  + f*32;
    const float* Bm = BloraT + f*32768;
    const float* e2 = lam    + f*Cq;

    int tid  = threadIdx.x;
    int m0   = blockIdx.y * 128, n0 = blockIdx.z * 128;
    int ty = tid >> 4, tx = tid & 15;

    // single load phase: 4 float4 of A + 4 float4 of B per thread
    #pragma unroll
    for (int t2 = 0; t2 < 4; t2++){
        int i = t2 * 256 + tid;          // 0..1023
        int row = i >> 3, q = (i & 7) * 4;
        float4 av = *(const float4*)(A + (size_t)(m0 + row) * 256 + q);
        As[q+0][row] = av.x;
        As[q+1][row] = av.y;
        As[q+2][row] = av.z;
        As[q+3][row] = av.w;
        float4 bv = *(const float4*)(Bm + (size_t)(n0 + row) * 32 + q);
        Bs[q+0][row] = bv.x;
        Bs[q+1][row] = bv.y;
        Bs[q+2][row] = bv.z;
        Bs[q+3][row] = bv.w;
    }
    __syncthreads();

    ull acc[8][4];
    #pragma unroll
    for (int i = 0; i < 8; i++)
        #pragma unroll
        for (int p = 0; p < 4; p++) acc[i][p] = 0ull;

    #pragma unroll 8
    for (int kk = 0; kk < 32; kk++) {
        const float4* ar4 = (const float4*)As[kk];
        const float4* br4 = (const float4*)Bs[kk];
        float4 av0 = ar4[ty*2], av1 = ar4[ty*2+1];       // 2x LDS.128 (broadcast)
        float4 bv0 = br4[tx*2], bv1 = br4[tx*2+1];       // 2x LDS.128
        ull a_[8], b_[4];
        a_[0] = pack2(av0.x); a_[1] = pack2(av0.y);
        a_[2] = pack2(av0.z); a_[3] = pack2(av0.w);
        a_[4] = pack2(av1.x); a_[5] = pack2(av1.y);
        a_[6] = pack2(av1.z); a_[7] = pack2(av1.w);
        b_[0] = pack2f(bv0.x, bv0.y); b_[1] = pack2f(bv0.z, bv0.w);
        b_[2] = pack2f(bv1.x, bv1.y); b_[3] = pack2f(bv1.z, bv1.w);
        #pragma unroll
        for (int i = 0; i < 8; i++)
            #pragma unroll
            for (int p = 0; p < 4; p++) fma2(acc[i][p], a_[i], b_[p]);
    }

    // vectorized epilogue: 8 contiguous columns per row per thread
    int n = n0 + tx*8;
    float4 e20 = *(const float4*)(e2 + n);
    float4 e21 = *(const float4*)(e2 + n + 4);
    #pragma unroll
    for (int i = 0; i < 8; i++) {
        size_t idx = (size_t)(m0 + ty*8 + i) * Cq + n;
        float4 x0 = *(const float4*)(x + idx);
        float4 x1 = *(const float4*)(x + idx + 4);
        float4 d0 = *(const float4*)(dxa + idx);
        float4 d1 = *(const float4*)(dxa + idx + 4);
        float2 v0 = unp(acc[i][0]), v1 = unp(acc[i][1]);
        float2 v2 = unp(acc[i][2]), v3 = unp(acc[i][3]);
        float v[8];
        v[0] = x0.x + d0.x * (e20.x + v0.x);
        v[1] = x0.y + d0.y * (e20.y + v0.y);
        v[2] = x0.z + d0.z * (e20.z + v1.x);
        v[3] = x0.w + d0.w * (e20.w + v1.y);
        v[4] = x1.x + d1.x * (e21.x + v2.x);
        v[5] = x1.y + d1.y * (e21.y + v2.y);
        v[6] = x1.z + d1.z * (e21.z + v3.x);
        v[7] = x1.w + d1.w * (e21.w + v3.y);
        if (f == 0) {
            __half h[8], l[8];
            #pragma unroll
            for (int q = 0; q < 8; q++) splitv(v[q], h[q], l[q]);
            uint4 ph, pl;
            ph.x = (uint32_t)u16of(h[0]) | ((uint32_t)u16of(h[1]) << 16);
            ph.y = (uint32_t)u16of(h[2]) | ((uint32_t)u16of(h[3]) << 16);
            ph.z = (uint32_t)u16of(h[4]) | ((uint32_t)u16of(h[5]) << 16);
            ph.w = (uint32_t)u16of(h[6]) | ((uint32_t)u16of(h[7]) << 16);
            pl.x = (uint32_t)u16of(l[0]) | ((uint32_t)u16of(l[1]) << 16);
            pl.y = (uint32_t)u16of(l[2]) | ((uint32_t)u16of(l[3]) << 16);
            pl.z = (uint32_t)u16of(l[4]) | ((uint32_t)u16of(l[5]) << 16);
            pl.w = (uint32_t)u16of(l[6]) | ((uint32_t)u16of(l[7]) << 16);
            *(uint4*)(xx0h + idx) = ph;
            *(uint4*)(xx0l + idx) = pl;
        } else {
            size_t o = (size_t)(f-1) * SZq + idx;
            __nv_bfloat16 h[8], l[8];
            #pragma unroll
            for (int q = 0; q < 8; q++) splitv(v[q], h[q], l[q]);
            uint4 ph, pl;
            ph.x = (uint32_t)u16of(h[0]) | ((uint32_t)u16of(h[1]) << 16);
            ph.y = (uint32_t)u16of(h[2]) | ((uint32_t)u16of(h[3]) << 16);
            ph.z = (uint32_t)u16of(h[4]) | ((uint32_t)u16of(h[5]) << 16);
            ph.w = (uint32_t)u16of(h[6]) | ((uint32_t)u16of(h[7]) << 16);
            pl.x = (uint32_t)u16of(l[0]) | ((uint32_t)u16of(l[1]) << 16);
            pl.y = (uint32_t)u16of(l[2]) | ((uint32_t)u16of(l[3]) << 16);
            pl.z = (uint32_t)u16of(l[4]) | ((uint32_t)u16of(l[5]) << 16);
            pl.w = (uint32_t)u16of(l[6]) | ((uint32_t)u16of(l[7]) << 16);
            *(uint4*)(abh + o) = ph;
            *(uint4*)(abl + o) = pl;
        }
    }
}

// ---------------------------------------------------------------------------
// prep: dxa = shift(x) - x (fp32) ; xm = x + dxa * miu_x -> bf16 hi/lo
// ---------------------------------------------------------------------------
__global__ void __launch_bounds__(256) prep_kernel(
    const float4* __restrict__ x4, const float4* __restrict__ mu4,
    float4* __restrict__ dxa4,
    __nv_bfloat16* __restrict__ xmh, __nv_bfloat16* __restrict__ xml)
{
    size_t i = (size_t)blockIdx.x * 256 + threadIdx.x;
    int m = (int)(i >> 8);
    int t = m & (Tq - 1);
    float4 xv = x4[i];
    float4 xl = make_float4(0.f, 0.f, 0.f, 0.f);
    if (t) xl = x4[i - 256];
    float4 mu = mu4[i & 255];
    float4 d  = make_float4(xl.x - xv.x, xl.y - xv.y, xl.z - xv.z, xl.w - xv.w);
    float xm0 = fmaf(d.x, mu.x, xv.x), xm1 = fmaf(d.y, mu.y, xv.y);
    float xm2 = fmaf(d.z, mu.z, xv.z), xm3 = fmaf(d.w, mu.w, xv.w);
    dxa4[i] = d;
    __nv_bfloat162 h0, l0, h1, l1;
    splitv(xm0, h0.x, l0.x); splitv(xm1, h0.y, l0.y);
    splitv(xm2, h1.x, l1.x); splitv(xm3, h1.y, l1.y);
    ((__nv_bfloat162*)xmh)[i*2]   = h0;
    ((__nv_bfloat162*)xmh)[i*2+1] = h1;
    ((__nv_bfloat162*)xml)[i*2]   = l0;
    ((__nv_bfloat162*)xml)[i*2+1] = l1;
}

// ---------------------------------------------------------------------------
// transposes: AloraT -> bf16 hi/lo; tdAT, tdBT -> fp16 hi/lo; BloraT fp32
// ---------------------------------------------------------------------------
__global__ void __launch_bounds__(256) transpose_all(
    __nv_bfloat16* __restrict__ AloraTh, __nv_bfloat16* __restrict__ AloraTl,
    const float* __restrict__ A_lora,
    __half* __restrict__ tdATh, __half* __restrict__ tdATl,
    const float* __restrict__ td_A,
    __half* __restrict__ tdBTh, __half* __restrict__ tdBTl,
    const float* __restrict__ td_B,
    float* __restrict__ BloraT, const float* __restrict__ B_lora)
{
    int i = blockIdx.x * 256 + threadIdx.x;
    if (i < 262144) {
        int n = i >> 10, k = i & 1023;
        float v = (n < 160) ? A_lora[k*160 + n] : 0.f;
        __nv_bfloat16 h, l; splitv(v, h, l);
        AloraTh[i] = h; AloraTl[i] = l;
    } else if (i < 393216) {
        int j = i - 262144; int n = j >> 10, k = j & 1023;
        float v = (n < 64) ? td_A[k*64 + n] : 0.f;
        __half h, l; splitv(v, h, l);
        tdATh[j] = h; tdATl[j] = l;
    } else if (i < 458752) {
        int j = i - 393216; int n = j >> 6, k = j & 63;
        float v = td_B[k*1024 + n];
        __half h, l; splitv(v, h, l);
        tdBTh[j] = h; tdBTl[j] = l;
    } else if (i < 622592) {
        int j = i - 458752;
        int f = j >> 15, rr = j & 32767, n = rr >> 5, k = rr & 31;
        BloraT[j] = B_lora[(f*32 + k)*1024 + n];
    }
}

// ---------------------------------------------------------------------------
// Weight bf16 hi/lo conversion (Wk,Wv,Wr,Wg,Wo) — float4 vectorized
// ---------------------------------------------------------------------------
__global__ void __launch_bounds__(256) wconv_kernel(
    const float* __restrict__ w0, const float* __restrict__ w1,
    const float* __restrict__ w2, const float* __restrict__ w3,
    const float* __restrict__ w4,
    __nv_bfloat16* __restrict__ h, __nv_bfloat16* __restrict__ l)
{
    int c = blockIdx.x * 256 + threadIdx.x;   // chunk of 4 elements
    int i = c * 4;
    int w = i >> 20;
    int j = i & 1048575;
    const float* src = (w == 0) ? w0 : (w == 1) ? w1 : (w == 2) ? w2 : (w == 3) ? w3 : w4;
    float4 xv = *(const float4*)(src + j);
    __nv_bfloat16 hh[4], ll[4];
    splitv(xv.x, hh[0], ll[0]); splitv(xv.y, hh[1], ll[1]);
    splitv(xv.z, hh[2], ll[2]); splitv(xv.w, hh[3], ll[3]);
    uint2 ph, pl;
    ph.x = (uint32_t)u16of(hh[0]) | ((uint32_t)u16of(hh[1]) << 16);
    ph.y = (uint32_t)u16of(hh[2]) | ((uint32_t)u16of(hh[3]) << 16);
    pl.x = (uint32_t)u16of(ll[0]) | ((uint32_t)u16of(ll[1]) << 16);
    pl.y = (uint32_t)u16of(ll[2]) | ((uint32_t)u16of(ll[3]) << 16);
    *(uint2*)(h + i) = ph;
    *(uint2*)(l + i) = pl;
}

// ---------------------------------------------------------------------------
// WKV6 scan — 4-buffer ring, ONE barrier per TWO timesteps; t+2/t+3 loads
// overlap compute of t/t+1.
// ---------------------------------------------------------------------------
__global__ void __launch_bounds__(256) wkv6_kernel(
    const float* __restrict__ rp, const float* __restrict__ kp,
    const float* __restrict__ vp, const float* __restrict__ wp,
    const float* __restrict__ up, float* __restrict__ yp)
{
    __shared__ float4 pk[4][4][17];
    __shared__ float  sv[4][64];
    int bh = blockIdx.x;
    int b = bh >> 4, h = bh & 15;
    size_t base = ((size_t)b * Tq) * Cq + h * 64;
    int tid = threadIdx.x;
    int j = tid >> 2, rg = tid & 3;
    float uu = 0.f;
    if (tid < 64) uu = up[h * 64 + tid];
    float S[16];
    #pragma unroll
    for (int i = 0; i < 16; i++) S[i] = 0.f;

    float lk0 = 0.f, lr0 = 0.f, lw0 = 0.f, lv0 = 0.f;
    float lk1 = 0.f, lr1 = 0.f, lw1 = 0.f, lv1 = 0.f;
    if (tid < 64){
        size_t o0 = base + tid;
        lk0 = kp[o0]; lr0 = rp[o0]; lw0 = wp[o0]; lv0 = vp[o0];
        size_t o1 = o0 + Cq;
        lk1 = kp[o1]; lr1 = rp[o1]; lw1 = wp[o1]; lv1 = vp[o1];
    }

    for (int t = 0; t < Tq; t += 2) {
        int b0 = t & 3, b1 = (t + 1) & 3;
        size_t off = base + (size_t)t * Cq;
        if (tid < 64) {
            sv[b0][tid] = lv0;
            pk[b0][tid >> 4][tid & 15] = make_float4(lk0, uu * lk0, lr0, expf(-expf(lw0)));
            sv[b1][tid] = lv1;
            pk[b1][tid >> 4][tid & 15] = make_float4(lk1, uu * lk1, lr1, expf(-expf(lw1)));
        }
        __syncthreads();
        if (t + 2 < Tq && tid < 64){
            size_t o2 = off + 2 * Cq + tid;
            lk0 = kp[o2]; lr0 = rp[o2]; lw0 = wp[o2]; lv0 = vp[o2];
            size_t o3 = o2 + Cq;
            lk1 = kp[o3]; lr1 = rp[o3]; lw1 = wp[o3]; lv1 = vp[o3];
        }
        // step t
        {
            float vj = sv[b0][j];
            float yv = 0.f;
            #pragma unroll
            for (int ii = 0; ii < 16; ii++) {
                float4 p = pk[b0][rg][ii];
                float s = S[ii];
                yv = fmaf(p.z, fmaf(p.y, vj, s), yv);
                S[ii] = fmaf(p.w, s, p.x * vj);
            }
            yv += __shfl_xor_sync(0xffffffffu, yv, 1);
            yv += __shfl_xor_sync(0xffffffffu, yv, 2);
            if (rg == 0) yp[off + j] = yv;
        }
        // step t+1
        {
            float vj = sv[b1][j];
            float yv = 0.f;
            #pragma unroll
            for (int ii = 0; ii < 16; ii++) {
                float4 p = pk[b1][rg][ii];
                float s = S[ii];
                yv = fmaf(p.z, fmaf(p.y, vj, s), yv);
                S[ii] = fmaf(p.w, s, p.x * vj);
            }
            yv += __shfl_xor_sync(0xffffffffu, yv, 1);
            yv += __shfl_xor_sync(0xffffffffu, yv, 2);
            if (rg == 0) yp[off + Cq + j] = yv;
        }
    }
}

// ---------------------------------------------------------------------------
// GroupNorm * gate -> bf16 hi/lo
// ---------------------------------------------------------------------------
__global__ void __launch_bounds__(256) gnorm_kernel(
    const float* __restrict__ y, const float* __restrict__ g,
    const float* __restrict__ gamma, const float* __restrict__ beta,
    __nv_bfloat16* __restrict__ ygh, __nv_bfloat16* __restrict__ ygl)
{
    int m = blockIdx.x, tid = threadIdx.x;
    size_t i4 = (size_t)m * 256 + tid;
    float4 yv = ((const float4*)y)[i4];
    float s  = yv.x + yv.y + yv.z + yv.w;
    float ss = yv.x*yv.x + yv.y*yv.y + yv.z*yv.z + yv.w*yv.w;
    #pragma unroll
    for (int o = 1; o < 16; o <<= 1) {
        s  += __shfl_xor_sync(0xffffffffu, s,  o);
        ss += __shfl_xor_sync(0xffffffffu, ss, o);
    }
    float mean = s * (1.f / 64.f);
    float var  = ss * (1.f / 64.f) - mean * mean;
    float rstd = rsqrtf(fmaxf(var, 0.f) + 1.6e-4f);
    float4 ga = ((const float4*)gamma)[tid];
    float4 be = ((const float4*)beta)[tid];
    float4 gv = ((const float4*)g)[i4];
    float o0 = ((yv.x - mean) * rstd * ga.x + be.x) * gv.x;
    float o1 = ((yv.y - mean) * rstd * ga.y + be.y) * gv.y;
    float o2 = ((yv.z - mean) * rstd * ga.z + be.z) * gv.z;
    float o3 = ((yv.w - mean) * rstd * ga.w + be.w) * gv.w;

    __nv_bfloat162 hp0, lp0, hp1, lp1;
    splitv(o0, hp0.x, lp0.x); splitv(o1, hp0.y, lp0.y);
    splitv(o2, hp1.x, lp1.x); splitv(o3, hp1.y, lp1.y);
    ((__nv_bfloat162*)ygh)[i4*2]   = hp0;
    ((__nv_bfloat162*)ygh)[i4*2+1] = hp1;
    ((__nv_bfloat162*)ygl)[i4*2]   = lp0;
    ((__nv_bfloat162*)ygl)[i4*2+1] = lp1;
}

// ---------------------------------------------------------------------------
// Launch
// ---------------------------------------------------------------------------
extern "C" void kernel_launch(void* const* d_in, const int* in_sizes, int n_in,
                              void* d_out, int out_size)
{
    (void)in_sizes; (void)n_in; (void)out_size;
    const float* x       = (const float*)d_in[0];
    const float* miu_x   = (const float*)d_in[1];
    const float* lambda_ = (const float*)d_in[2];
    const float* A_lora  = (const float*)d_in[3];
    const float* B_lora  = (const float*)d_in[4];
    const float* td_miu  = (const float*)d_in[5];
    const float* td_A    = (const float*)d_in[6];
    const float* td_B    = (const float*)d_in[7];
    const float* u       = (const float*)d_in[8];
    const float* Wr      = (const float*)d_in[9];
    const float* Wk      = (const float*)d_in[10];
    const float* Wv      = (const float*)d_in[11];
    const float* Wg      = (const float*)d_in[12];
    const float* Wo      = (const float*)d_in[13];
    const float* gamma   = (const float*)d_in[14];
    const float* beta    = (const float*)d_in[15];
    float* out = (float*)d_out;

    float *p_dxa,*p_k,*p_v,*p_r,*p_g,*p_w,*p_y,*p_lorap,*p_BloraT;
    __nv_bfloat16 *p_xmh,*p_xml,*p_abh,*p_abl,*p_ygh,*p_ygl,*p_wbh,*p_wbl,
                  *p_AloraTh,*p_AloraTl;
    __half *p_xx0h,*p_xx0l,*p_tdhh,*p_tdhl,*p_tdATh,*p_tdATl,*p_tdBTh,*p_tdBTl;
    { void* t;
      cudaGetSymbolAddress(&t, g_dxa);     p_dxa     = (float*)t;
      cudaGetSymbolAddress(&t, g_k);       p_k       = (float*)t;
      cudaGetSymbolAddress(&t, g_v);       p_v       = (float*)t;
      cudaGetSymbolAddress(&t, g_r);       p_r       = (float*)t;
      cudaGetSymbolAddress(&t, g_g);       p_g       = (float*)t;
      cudaGetSymbolAddress(&t, g_w);       p_w       = (float*)t;
      cudaGetSymbolAddress(&t, g_y);       p_y       = (float*)t;
      cudaGetSymbolAddress(&t, g_lorap);   p_lorap   = (float*)t;
      cudaGetSymbolAddress(&t, g_BloraT);  p_BloraT  = (float*)t;
      cudaGetSymbolAddress(&t, g_xmh);     p_xmh     = (__nv_bfloat16*)t;
      cudaGetSymbolAddress(&t, g_xml);     p_xml     = (__nv_bfloat16*)t;
      cudaGetSymbolAddress(&t, g_abh);     p_abh     = (__nv_bfloat16*)t;
      cudaGetSymbolAddress(&t, g_abl);     p_abl     = (__nv_bfloat16*)t;
      cudaGetSymbolAddress(&t, g_ygh);     p_ygh     = (__nv_bfloat16*)t;
      cudaGetSymbolAddress(&t, g_ygl);     p_ygl     = (__nv_bfloat16*)t;
      cudaGetSymbolAddress(&t, g_wbh);     p_wbh     = (__nv_bfloat16*)t;
      cudaGetSymbolAddress(&t, g_wbl);     p_wbl     = (__nv_bfloat16*)t;
      cudaGetSymbolAddress(&t, g_AloraTh); p_AloraTh = (__nv_bfloat16*)t;
      cudaGetSymbolAddress(&t, g_AloraTl); p_AloraTl = (__nv_bfloat16*)t;
      cudaGetSymbolAddress(&t, g_xx0h);    p_xx0h    = (__half*)t;
      cudaGetSymbolAddress(&t, g_xx0l);    p_xx0l    = (__half*)t;
      cudaGetSymbolAddress(&t, g_tdhh);    p_tdhh    = (__half*)t;
      cudaGetSymbolAddress(&t, g_tdhl);    p_tdhl    = (__half*)t;
      cudaGetSymbolAddress(&t, g_tdATh);   p_tdATh   = (__half*)t;
      cudaGetSymbolAddress(&t, g_tdATl);   p_tdATl   = (__half*)t;
      cudaGetSymbolAddress(&t, g_tdBTh);   p_tdBTh   = (__half*)t;
      cudaGetSymbolAddress(&t, g_tdBTl);   p_tdBTl   = (__half*)t;
    }

    cudaFuncSetAttribute(hgemm_one,  cudaFuncAttributeMaxDynamicSharedMemorySize, HG_SMEM);
    cudaFuncSetAttribute(hgemm_kvrg, cudaFuncAttributeMaxDynamicSharedMemorySize, HG_SMEM);
    cudaFuncSetAttribute(hgemm_h,    cudaFuncAttributeMaxDynamicSharedMemorySize, HG_SMEM);

    // 0: token shift + static lerp (xm -> bf16 hi/lo)
    prep_kernel<<<BTq * Cq / 4 / 256, 256>>>((const float4*)x, (const float4*)miu_x,
                                             (float4*)p_dxa, p_xmh, p_xml);
    // 1: weight transposes
    transpose_all<<<(622592 + 255) / 256, 256>>>(p_AloraTh, p_AloraTl, A_lora,
                                                 p_tdATh, p_tdATl, td_A,
                                                 p_tdBTh, p_tdBTl, td_B,
                                                 p_BloraT, B_lora);
    // 2: lora_h = tanh(xm @ A_lora)
    hgemm_one<<<dim3(2, 128), 256, HG_SMEM>>>(p_xmh, p_xml, p_AloraTh, p_AloraTl,
                                              p_lorap, 256, Cq, 2);
    // 3: ddlerp mix (f=0 -> fp16 hi/lo xx0; f=1..4 -> bf16 hi/lo k,v,r,g)
    mix_gemm<<<dim3(5, 128, 8), 256>>>(p_lorap, p_BloraT, x, p_dxa, lambda_,
                                       p_xx0h, p_xx0l, p_abh, p_abl);
    // 4: big weight hi/lo (float4 vectorized)
    wconv_kernel<<<5 * 1048576 / 1024, 256>>>(Wk, Wv, Wr, Wg, Wo, p_wbh, p_wbl);
    // 5: merged projections k, v, r, g
    hgemm_kvrg<<<dim3(8, 128, 4), 256, HG_SMEM>>>(p_abh, p_abl, p_wbh, p_wbl,
                                                  p_k, p_v, p_r, p_g);
    // 6: tdh = tanh(w_in @ td_A) -> fp16 hi/lo (padded N=128)
    hgemm_h<<<dim3(1, 128), 256, HG_SMEM>>>(p_xx0h, p_xx0l, p_tdATh, p_tdATl,
                                            nullptr, p_tdhh, p_tdhl, nullptr,
                                            128, Cq, Cq, Cq, 3);
    // 7: w = td_miu + tdh @ td_B   (A stride 128, K=64)
    hgemm_h<<<dim3(8, 128), 256, HG_SMEM>>>(p_tdhh, p_tdhl, p_tdBTh, p_tdBTl,
                                            p_w, nullptr, nullptr, td_miu,
                                            Cq, 64, 128, 64, 4);
    // 8: WKV6 scan
    wkv6_kernel<<<Bq * Hq, 256>>>(p_r, p_k, p_v, p_w, u, p_y);
    // 9: GroupNorm * gate -> bf16 hi/lo
    gnorm_kernel<<<BTq, 256>>>(p_y, p_g, gamma, beta, p_ygh, p_ygl);
    // 10: output projection
    hgemm_one<<<dim3(8, 128), 256, HG_SMEM>>>(p_ygh, p_ygl, p_wbh + 4*WWq, p_wbl + 4*WWq,
                                              out, Cq, Cq, 0);
}

// round 16
// speedup vs baseline: 1.5604x; 1.0007x over previous
#include <cuda_runtime.h>
#include <cuda_bf16.h>
#include <cuda_fp16.h>
#include <math.h>
#include <stdint.h>

#define Bq 8
#define Tq 2048
#define Cq 1024
#define Hq 16
#define BTq (Bq*Tq)
#define WWq (Cq*Cq)

typedef unsigned long long ull;
static const size_t SZq = (size_t)BTq * Cq;

// ---------------------------------------------------------------------------
// Scratch (static device globals — no runtime allocation)
// ---------------------------------------------------------------------------
__device__ float g_dxa [BTq*Cq];
__device__ float g_k   [BTq*Cq];
__device__ float g_v   [BTq*Cq];
__device__ float g_r   [BTq*Cq];
__device__ float g_g   [BTq*Cq];
__device__ float g_w   [BTq*Cq];
__device__ float g_y   [BTq*Cq];
__device__ float g_lorap [BTq*256];          // tanh(xm @ A_lora) fp32 (padded 256)
__device__ float g_BloraT[5*1024*32];        // B_lora^T per branch, fp32

__device__ __nv_bfloat16 g_xmh[BTq*Cq];      // xm hi/lo (bf16 split)
__device__ __nv_bfloat16 g_xml[BTq*Cq];
__device__ __nv_bfloat16 g_abh[4*BTq*Cq];    // k,v,r,g branch inputs hi
__device__ __nv_bfloat16 g_abl[4*BTq*Cq];    // lo
__device__ __nv_bfloat16 g_ygh[BTq*Cq];
__device__ __nv_bfloat16 g_ygl[BTq*Cq];
__device__ __nv_bfloat16 g_wbh[5*WWq];       // Wk,Wv,Wr,Wg,Wo hi
__device__ __nv_bfloat16 g_wbl[5*WWq];       // lo
__device__ __nv_bfloat16 g_AloraTh[256*1024];
__device__ __nv_bfloat16 g_AloraTl[256*1024];

// fp16-split td path (2^-22 residual — precision-safe for the decay scan)
__device__ __half g_xx0h[BTq*Cq];            // w_in branch hi/lo
__device__ __half g_xx0l[BTq*Cq];
__device__ __half g_tdhh[BTq*128];           // tanh(w_in @ td_A) hi/lo (padded 128)
__device__ __half g_tdhl[BTq*128];
__device__ __half g_tdATh[128*1024];
__device__ __half g_tdATl[128*1024];
__device__ __half g_tdBTh[1024*64];
__device__ __half g_tdBTl[1024*64];

// ---------------------------------------------------------------------------
// PTX helpers (sm_80+ — valid on compute_103 virtual arch)
// ---------------------------------------------------------------------------
__device__ __forceinline__ uint32_t sm2u32(const void* p){
    uint32_t a;
    asm("{ .reg .u64 t; cvta.to.shared.u64 t, %1; cvt.u32.u64 %0, t; }" : "=r"(a) : "l"(p));
    return a;
}
__device__ __forceinline__ void cpa16(uint32_t dst, const void* src){
    asm volatile("cp.async.cg.shared.global [%0], [%1], 16;" :: "r"(dst), "l"(src) : "memory");
}
__device__ __forceinline__ void cpa_commit(){
    asm volatile("cp.async.commit_group;" ::: "memory");
}
template<int N>
__device__ __forceinline__ void cpa_wait(){
    asm volatile("cp.async.wait_group %0;" :: "n"(N) : "memory");
}
__device__ __forceinline__ void ldsm_x4(uint32_t* r, uint32_t addr){
    asm volatile("ldmatrix.sync.aligned.m8n8.x4.shared.b16 {%0,%1,%2,%3}, [%4];"
        : "=r"(r[0]), "=r"(r[1]), "=r"(r[2]), "=r"(r[3]) : "r"(addr));
}
template<bool FP16>
__device__ __forceinline__ void mma_any(float* d, const uint32_t* a, const uint32_t* b){
    if (FP16){
        asm volatile("mma.sync.aligned.m16n8k16.row.col.f32.f16.f16.f32 "
            "{%0,%1,%2,%3}, {%4,%5,%6,%7}, {%8,%9}, {%0,%1,%2,%3};"
            : "+f"(d[0]), "+f"(d[1]), "+f"(d[2]), "+f"(d[3])
            : "r"(a[0]), "r"(a[1]), "r"(a[2]), "r"(a[3]), "r"(b[0]), "r"(b[1]));
    } else {
        asm volatile("mma.sync.aligned.m16n8k16.row.col.f32.bf16.bf16.f32 "
            "{%0,%1,%2,%3}, {%4,%5,%6,%7}, {%8,%9}, {%0,%1,%2,%3};"
            : "+f"(d[0]), "+f"(d[1]), "+f"(d[2]), "+f"(d[3])
            : "r"(a[0]), "r"(a[1]), "r"(a[2]), "r"(a[3]), "r"(b[0]), "r"(b[1]));
    }
}
__device__ __forceinline__ void splitv(float v, __nv_bfloat16& h, __nv_bfloat16& l){
    h = __float2bfloat16(v);
    l = __float2bfloat16(v - __bfloat162float(h));
}
__device__ __forceinline__ void splitv(float v, __half& h, __half& l){
    h = __float2half_rn(v);
    l = __float2half_rn(v - __half2float(h));
}
__device__ __forceinline__ uint16_t u16of(__half v){ return *(uint16_t*)&v; }
__device__ __forceinline__ uint16_t u16of(__nv_bfloat16 v){ return *(uint16_t*)&v; }

// ---------------------------------------------------------------------------
// split GEMM core via mma.sync (proven round-9 structure)
// ---------------------------------------------------------------------------
#define NSTAGE    4
#define STG_ARR   6144                 // 128 rows * 48B
#define STG_BYTES 24576                // 4 arrays
#define HG_SMEM   (NSTAGE * STG_BYTES) // 98304

template<bool FP16, typename OT>
__device__ __forceinline__ void hg_core(
    const uint16_t* __restrict__ Ah, const uint16_t* __restrict__ Al,
    const uint16_t* __restrict__ Bh, const uint16_t* __restrict__ Bl,
    float* __restrict__ Cp, OT* __restrict__ Ch, OT* __restrict__ Cl,
    const float* __restrict__ e0,
    int N, int K, int lda, int ldb, int m0, int n0, int epi, char* sm)
{
    int tid = threadIdx.x, lane = tid & 31, wid = tid >> 5;
    int wy = wid & 1, wx = wid >> 1;
    uint32_t sb = sm2u32(sm);

    int arr0 = tid >> 7;
    int rowa = tid & 127;
    const uint16_t* p0 = ((arr0 == 0) ? Ah : Al) + (size_t)(m0 + rowa) * lda;
    const uint16_t* p1 = ((arr0 == 0) ? Bh : Bl) + (size_t)(n0 + rowa) * ldb;
    uint32_t so0 = (uint32_t)(arr0 * STG_ARR + rowa * 48);
    uint32_t so1 = so0 + 2 * STG_ARR;

    float acc[4][4][4];
    #pragma unroll
    for (int i = 0; i < 4; i++)
        #pragma unroll
        for (int j = 0; j < 4; j++)
            #pragma unroll
            for (int q = 0; q < 4; q++) acc[i][j][q] = 0.f;

    uint32_t a_row = (uint32_t)(wy * 64 + (lane & 15));
    uint32_t a_kh  = (uint32_t)((lane >> 4) * 8);
    uint32_t b_row0 = (uint32_t)(wx * 32 + (lane & 7) + ((lane >> 4) * 8));
    uint32_t b_kh   = (uint32_t)(((lane >> 3) & 1) * 8);

    const int NC = K >> 4;

    #pragma unroll
    for (int s = 0; s < 3; s++){
        uint32_t d = sb + (uint32_t)s * STG_BYTES;
        int kk = s * 16;
        cpa16(d + so0,      p0 + kk);  cpa16(d + so0 + 16, p0 + kk + 8);
        cpa16(d + so1,      p1 + kk);  cpa16(d + so1 + 16, p1 + kk + 8);
        cpa_commit();
    }

    #pragma unroll 4
    for (int c = 0; c < NC; c++){
        cpa_wait<2>();
        __syncthreads();
        if (c + 3 < NC){
            uint32_t d = sb + (uint32_t)((c + 3) & 3) * STG_BYTES;
            int kk = (c + 3) << 4;
            cpa16(d + so0,      p0 + kk);  cpa16(d + so0 + 16, p0 + kk + 8);
            cpa16(d + so1,      p1 + kk);  cpa16(d + so1 + 16, p1 + kk + 8);
        }
        cpa_commit();

        uint32_t base = sb + (uint32_t)(c & 3) * STG_BYTES;

        uint32_t bh[2][4], bl[2][4];
        #pragma unroll
        for (int bi = 0; bi < 2; bi++){
            uint32_t bo = base + 2*STG_ARR + (b_row0 + bi * 16) * 48 + b_kh * 2;
            ldsm_x4(bh[bi], bo);
            ldsm_x4(bl[bi], bo + STG_ARR);
        }
        #pragma unroll
        for (int mf = 0; mf < 4; mf++){
            uint32_t ah[4], al[4];
            uint32_t ao = base + (a_row + mf * 16) * 48 + a_kh * 2;
            ldsm_x4(ah, ao);
            ldsm_x4(al, ao + STG_ARR);
            #pragma unroll
            for (int nf = 0; nf < 4; nf++){
                const uint32_t* bhp = &bh[nf >> 1][(nf & 1) * 2];
                const uint32_t* blp = &bl[nf >> 1][(nf & 1) * 2];
                mma_any<FP16>(acc[mf][nf], ah, bhp);
                mma_any<FP16>(acc[mf][nf], ah, blp);
                mma_any<FP16>(acc[mf][nf], al, bhp);
            }
        }
    }

    #pragma unroll
    for (int mf = 0; mf < 4; mf++){
        int row0 = m0 + wy * 64 + mf * 16 + (lane >> 2);
        #pragma unroll
        for (int nf = 0; nf < 4; nf++){
            int col = n0 + wx * 32 + nf * 8 + (lane & 3) * 2;
            float v[4] = {acc[mf][nf][0], acc[mf][nf][1], acc[mf][nf][2], acc[mf][nf][3]};
            if (epi == 1){
                #pragma unroll
                for (int q = 0; q < 4; q++) v[q] = v[q] / (1.f + expf(-v[q]));
            } else if (epi == 2 || epi == 3){
                #pragma unroll
                for (int q = 0; q < 4; q++) v[q] = tanhf(v[q]);
            } else if (epi == 4){
                v[0] += e0[col]; v[1] += e0[col+1];
                v[2] += e0[col]; v[3] += e0[col+1];
            }
            size_t i01 = (size_t)row0 * N + col;
            size_t i23 = (size_t)(row0 + 8) * N + col;
            if (epi == 3){
                OT h[4], l[4];
                #pragma unroll
                for (int q = 0; q < 4; q++) splitv(v[q], h[q], l[q]);
                *(uint32_t*)(Ch + i01) = (uint32_t)u16of(h[0]) | ((uint32_t)u16of(h[1]) << 16);
                *(uint32_t*)(Cl + i01) = (uint32_t)u16of(l[0]) | ((uint32_t)u16of(l[1]) << 16);
                *(uint32_t*)(Ch + i23) = (uint32_t)u16of(h[2]) | ((uint32_t)u16of(h[3]) << 16);
                *(uint32_t*)(Cl + i23) = (uint32_t)u16of(l[2]) | ((uint32_t)u16of(l[3]) << 16);
            } else {
                *(float2*)(Cp + i01) = make_float2(v[0], v[1]);
                *(float2*)(Cp + i23) = make_float2(v[2], v[3]);
            }
        }
    }
}

__global__ void __launch_bounds__(256, 2) hgemm_one(
    const __nv_bfloat16* __restrict__ Ah, const __nv_bfloat16* __restrict__ Al,
    const __nv_bfloat16* __restrict__ Bh, const __nv_bfloat16* __restrict__ Bl,
    float* __restrict__ Cp, int N, int K, int epi)
{
    extern __shared__ char sm[];
    hg_core<false, __nv_bfloat16>((const uint16_t*)Ah, (const uint16_t*)Al,
        (const uint16_t*)Bh, (const uint16_t*)Bl,
        Cp, (__nv_bfloat16*)nullptr, (__nv_bfloat16*)nullptr, nullptr,
        N, K, K, K, blockIdx.y * 128, blockIdx.x * 128, epi, sm);
}

__global__ void __launch_bounds__(256, 2) hgemm_kvrg(
    const __nv_bfloat16* __restrict__ abh, const __nv_bfloat16* __restrict__ abl,
    const __nv_bfloat16* __restrict__ wbh, const __nv_bfloat16* __restrict__ wbl,
    float* __restrict__ C0, float* __restrict__ C1,
    float* __restrict__ C2, float* __restrict__ C3)
{
    extern __shared__ char sm[];
    int z = blockIdx.z;
    float* Cp = (z == 0) ? C0 : (z == 1) ? C1 : (z == 2) ? C2 : C3;
    hg_core<false, __nv_bfloat16>(
        (const uint16_t*)(abh + (size_t)z * SZq), (const uint16_t*)(abl + (size_t)z * SZq),
        (const uint16_t*)(wbh + (size_t)z * WWq), (const uint16_t*)(wbl + (size_t)z * WWq),
        Cp, (__nv_bfloat16*)nullptr, (__nv_bfloat16*)nullptr, nullptr,
        Cq, Cq, Cq, Cq, blockIdx.y * 128, blockIdx.x * 128, (z == 3) ? 1 : 0, sm);
}

__global__ void __launch_bounds__(256, 2) hgemm_h(
    const __half* __restrict__ Ah, const __half* __restrict__ Al,
    const __half* __restrict__ Bh, const __half* __restrict__ Bl,
    float* __restrict__ Cp, __half* __restrict__ Ch, __half* __restrict__ Cl,
    const float* __restrict__ e0, int N, int K, int lda, int ldb, int epi)
{
    extern __shared__ char sm[];
    hg_core<true, __half>((const uint16_t*)Ah, (const uint16_t*)Al,
        (const uint16_t*)Bh, (const uint16_t*)Bl,
        Cp, Ch, Cl, e0,
        N, K, lda, ldb, blockIdx.y * 128, blockIdx.x * 128, epi, sm);
}

// ---------------------------------------------------------------------------
// FFMA2 helpers
// ---------------------------------------------------------------------------
__device__ __forceinline__ void fma2(ull& d, ull a, ull b){
    asm("fma.rn.f32x2 %0, %1, %2, %0;" : "+l"(d) : "l"(a), "l"(b));
}
__device__ __forceinline__ float2 unp(ull v){
    float2 r; asm("mov.b64 {%0, %1}, %2;" : "=f"(r.x), "=f"(r.y) : "l"(v)); return r;
}
__device__ __forceinline__ ull pack2(float v){
    ull r; asm("mov.b64 %0, {%1, %1};" : "=l"(r) : "f"(v)); return r;
}
__device__ __forceinline__ ull pack2f(float x, float y){
    ull r; asm("mov.b64 %0, {%1, %2};" : "=l"(r) : "f"(x), "f"(y)); return r;
}

// ---------------------------------------------------------------------------
// ddlerp MIX GEMM (K=32), SINGLE load phase, ONE barrier, vectorized epilogue.
// (proven round-15 structure)
// ---------------------------------------------------------------------------
__global__ void __launch_bounds__(256) mix_gemm(
    const float* __restrict__ lorap, const float* __restrict__ BloraT,
    const float* __restrict__ x, const float* __restrict__ dxa,
    const float* __restrict__ lam,
    __half* __restrict__ xx0h, __half* __restrict__ xx0l,
    __nv_bfloat16* __restrict__ abh, __nv_bfloat16* __restrict__ abl)
{
    __shared__ __align__(16) float As[32][128];    // 16 KB (non-duplicated)
    __shared__ __align__(16) float Bs[32][128];    // 16 KB

    int f = blockIdx.x;
    const float* A  = lorap  + f*32;
    const float* Bm = BloraT + f*32768;
    const float* e2 = lam    + f*Cq;

    int tid  = threadIdx.x;
    int m0   = blockIdx.y * 128, n0 = blockIdx.z * 128;
    int ty = tid >> 4, tx = tid & 15;

    #pragma unroll
    for (int t2 = 0; t2 < 4; t2++){
        int i = t2 * 256 + tid;
        int row = i >> 3, q = (i & 7) * 4;
        float4 av = *(const float4*)(A + (size_t)(m0 + row) * 256 + q);
        As[q+0][row] = av.x;
        As[q+1][row] = av.y;
        As[q+2][row] = av.z;
        As[q+3][row] = av.w;
        float4 bv = *(const float4*)(Bm + (size_t)(n0 + row) * 32 + q);
        Bs[q+0][row] = bv.x;
        Bs[q+1][row] = bv.y;
        Bs[q+2][row] = bv.z;
        Bs[q+3][row] = bv.w;
    }
    __syncthreads();

    ull acc[8][4];
    #pragma unroll
    for (int i = 0; i < 8; i++)
        #pragma unroll
        for (int p = 0; p < 4; p++) acc[i][p] = 0ull;

    #pragma unroll 8
    for (int kk = 0; kk < 32; kk++) {
        const float4* ar4 = (const float4*)As[kk];
        const float4* br4 = (const float4*)Bs[kk];
        float4 av0 = ar4[ty*2], av1 = ar4[ty*2+1];
        float4 bv0 = br4[tx*2], bv1 = br4[tx*2+1];
        ull a_[8], b_[4];
        a_[0] = pack2(av0.x); a_[1] = pack2(av0.y);
        a_[2] = pack2(av0.z); a_[3] = pack2(av0.w);
        a_[4] = pack2(av1.x); a_[5] = pack2(av1.y);
        a_[6] = pack2(av1.z); a_[7] = pack2(av1.w);
        b_[0] = pack2f(bv0.x, bv0.y); b_[1] = pack2f(bv0.z, bv0.w);
        b_[2] = pack2f(bv1.x, bv1.y); b_[3] = pack2f(bv1.z, bv1.w);
        #pragma unroll
        for (int i = 0; i < 8; i++)
            #pragma unroll
            for (int p = 0; p < 4; p++) fma2(acc[i][p], a_[i], b_[p]);
    }

    int n = n0 + tx*8;
    float4 e20 = *(const float4*)(e2 + n);
    float4 e21 = *(const float4*)(e2 + n + 4);
    #pragma unroll
    for (int i = 0; i < 8; i++) {
        size_t idx = (size_t)(m0 + ty*8 + i) * Cq + n;
        float4 x0 = *(const float4*)(x + idx);
        float4 x1 = *(const float4*)(x + idx + 4);
        float4 d0 = *(const float4*)(dxa + idx);
        float4 d1 = *(const float4*)(dxa + idx + 4);
        float2 v0 = unp(acc[i][0]), v1 = unp(acc[i][1]);
        float2 v2 = unp(acc[i][2]), v3 = unp(acc[i][3]);
        float v[8];
        v[0] = x0.x + d0.x * (e20.x + v0.x);
        v[1] = x0.y + d0.y * (e20.y + v0.y);
        v[2] = x0.z + d0.z * (e20.z + v1.x);
        v[3] = x0.w + d0.w * (e20.w + v1.y);
        v[4] = x1.x + d1.x * (e21.x + v2.x);
        v[5] = x1.y + d1.y * (e21.y + v2.y);
        v[6] = x1.z + d1.z * (e21.z + v3.x);
        v[7] = x1.w + d1.w * (e21.w + v3.y);
        if (f == 0) {
            __half h[8], l[8];
            #pragma unroll
            for (int q = 0; q < 8; q++) splitv(v[q], h[q], l[q]);
            uint4 ph, pl;
            ph.x = (uint32_t)u16of(h[0]) | ((uint32_t)u16of(h[1]) << 16);
            ph.y = (uint32_t)u16of(h[2]) | ((uint32_t)u16of(h[3]) << 16);
            ph.z = (uint32_t)u16of(h[4]) | ((uint32_t)u16of(h[5]) << 16);
            ph.w = (uint32_t)u16of(h[6]) | ((uint32_t)u16of(h[7]) << 16);
            pl.x = (uint32_t)u16of(l[0]) | ((uint32_t)u16of(l[1]) << 16);
            pl.y = (uint32_t)u16of(l[2]) | ((uint32_t)u16of(l[3]) << 16);
            pl.z = (uint32_t)u16of(l[4]) | ((uint32_t)u16of(l[5]) << 16);
            pl.w = (uint32_t)u16of(l[6]) | ((uint32_t)u16of(l[7]) << 16);
            *(uint4*)(xx0h + idx) = ph;
            *(uint4*)(xx0l + idx) = pl;
        } else {
            size_t o = (size_t)(f-1) * SZq + idx;
            __nv_bfloat16 h[8], l[8];
            #pragma unroll
            for (int q = 0; q < 8; q++) splitv(v[q], h[q], l[q]);
            uint4 ph, pl;
            ph.x = (uint32_t)u16of(h[0]) | ((uint32_t)u16of(h[1]) << 16);
            ph.y = (uint32_t)u16of(h[2]) | ((uint32_t)u16of(h[3]) << 16);
            ph.z = (uint32_t)u16of(h[4]) | ((uint32_t)u16of(h[5]) << 16);
            ph.w = (uint32_t)u16of(h[6]) | ((uint32_t)u16of(h[7]) << 16);
            pl.x = (uint32_t)u16of(l[0]) | ((uint32_t)u16of(l[1]) << 16);
            pl.y = (uint32_t)u16of(l[2]) | ((uint32_t)u16of(l[3]) << 16);
            pl.z = (uint32_t)u16of(l[4]) | ((uint32_t)u16of(l[5]) << 16);
            pl.w = (uint32_t)u16of(l[6]) | ((uint32_t)u16of(l[7]) << 16);
            *(uint4*)(abh + o) = ph;
            *(uint4*)(abl + o) = pl;
        }
    }
}

// ---------------------------------------------------------------------------
// prep: dxa = shift(x) - x (fp32) ; xm = x + dxa * miu_x -> bf16 hi/lo
// (stores vectorized to STG.64)
// ---------------------------------------------------------------------------
__global__ void __launch_bounds__(256) prep_kernel(
    const float4* __restrict__ x4, const float4* __restrict__ mu4,
    float4* __restrict__ dxa4,
    __nv_bfloat16* __restrict__ xmh, __nv_bfloat16* __restrict__ xml)
{
    size_t i = (size_t)blockIdx.x * 256 + threadIdx.x;
    int m = (int)(i >> 8);
    int t = m & (Tq - 1);
    float4 xv = x4[i];
    float4 xl = make_float4(0.f, 0.f, 0.f, 0.f);
    if (t) xl = x4[i - 256];
    float4 mu = mu4[i & 255];
    float4 d  = make_float4(xl.x - xv.x, xl.y - xv.y, xl.z - xv.z, xl.w - xv.w);
    float xm0 = fmaf(d.x, mu.x, xv.x), xm1 = fmaf(d.y, mu.y, xv.y);
    float xm2 = fmaf(d.z, mu.z, xv.z), xm3 = fmaf(d.w, mu.w, xv.w);
    dxa4[i] = d;
    __nv_bfloat16 h[4], l[4];
    splitv(xm0, h[0], l[0]); splitv(xm1, h[1], l[1]);
    splitv(xm2, h[2], l[2]); splitv(xm3, h[3], l[3]);
    uint2 ph, pl;
    ph.x = (uint32_t)u16of(h[0]) | ((uint32_t)u16of(h[1]) << 16);
    ph.y = (uint32_t)u16of(h[2]) | ((uint32_t)u16of(h[3]) << 16);
    pl.x = (uint32_t)u16of(l[0]) | ((uint32_t)u16of(l[1]) << 16);
    pl.y = (uint32_t)u16of(l[2]) | ((uint32_t)u16of(l[3]) << 16);
    ((uint2*)xmh)[i] = ph;
    ((uint2*)xml)[i] = pl;
}

// ---------------------------------------------------------------------------
// transposes: AloraT -> bf16 hi/lo; tdAT, tdBT -> fp16 hi/lo; BloraT fp32
// ---------------------------------------------------------------------------
__global__ void __launch_bounds__(256) transpose_all(
    __nv_bfloat16* __restrict__ AloraTh, __nv_bfloat16* __restrict__ AloraTl,
    const float* __restrict__ A_lora,
    __half* __restrict__ tdATh, __half* __restrict__ tdATl,
    const float* __restrict__ td_A,
    __half* __restrict__ tdBTh, __half* __restrict__ tdBTl,
    const float* __restrict__ td_B,
    float* __restrict__ BloraT, const float* __restrict__ B_lora)
{
    int i = blockIdx.x * 256 + threadIdx.x;
    if (i < 262144) {
        int n = i >> 10, k = i & 1023;
        float v = (n < 160) ? A_lora[k*160 + n] : 0.f;
        __nv_bfloat16 h, l; splitv(v, h, l);
        AloraTh[i] = h; AloraTl[i] = l;
    } else if (i < 393216) {
        int j = i - 262144; int n = j >> 10, k = j & 1023;
        float v = (n < 64) ? td_A[k*64 + n] : 0.f;
        __half h, l; splitv(v, h, l);
        tdATh[j] = h; tdATl[j] = l;
    } else if (i < 458752) {
        int j = i - 393216; int n = j >> 6, k = j & 63;
        float v = td_B[k*1024 + n];
        __half h, l; splitv(v, h, l);
        tdBTh[j] = h; tdBTl[j] = l;
    } else if (i < 622592) {
        int j = i - 458752;
        int f = j >> 15, rr = j & 32767, n = rr >> 5, k = rr & 31;
        BloraT[j] = B_lora[(f*32 + k)*1024 + n];
    }
}

// ---------------------------------------------------------------------------
// Weight bf16 hi/lo conversion (Wk,Wv,Wr,Wg,Wo) — float4 vectorized
// ---------------------------------------------------------------------------
__global__ void __launch_bounds__(256) wconv_kernel(
    const float* __restrict__ w0, const float* __restrict__ w1,
    const float* __restrict__ w2, const float* __restrict__ w3,
    const float* __restrict__ w4,
    __nv_bfloat16* __restrict__ h, __nv_bfloat16* __restrict__ l)
{
    int c = blockIdx.x * 256 + threadIdx.x;
    int i = c * 4;
    int w = i >> 20;
    int j = i & 1048575;
    const float* src = (w == 0) ? w0 : (w == 1) ? w1 : (w == 2) ? w2 : (w == 3) ? w3 : w4;
    float4 xv = *(const float4*)(src + j);
    __nv_bfloat16 hh[4], ll[4];
    splitv(xv.x, hh[0], ll[0]); splitv(xv.y, hh[1], ll[1]);
    splitv(xv.z, hh[2], ll[2]); splitv(xv.w, hh[3], ll[3]);
    uint2 ph, pl;
    ph.x = (uint32_t)u16of(hh[0]) | ((uint32_t)u16of(hh[1]) << 16);
    ph.y = (uint32_t)u16of(hh[2]) | ((uint32_t)u16of(hh[3]) << 16);
    pl.x = (uint32_t)u16of(ll[0]) | ((uint32_t)u16of(ll[1]) << 16);
    pl.y = (uint32_t)u16of(ll[2]) | ((uint32_t)u16of(ll[3]) << 16);
    *(uint2*)(h + i) = ph;
    *(uint2*)(l + i) = pl;
}

// ---------------------------------------------------------------------------
// WKV6 scan — 4-buffer ring, ONE barrier per TWO timesteps.
// yv accumulated in TWO partial sums (dependency chain 16 -> 8).
// ---------------------------------------------------------------------------
__global__ void __launch_bounds__(256) wkv6_kernel(
    const float* __restrict__ rp, const float* __restrict__ kp,
    const float* __restrict__ vp, const float* __restrict__ wp,
    const float* __restrict__ up, float* __restrict__ yp)
{
    __shared__ float4 pk[4][4][17];
    __shared__ float  sv[4][64];
    int bh = blockIdx.x;
    int b = bh >> 4, h = bh & 15;
    size_t base = ((size_t)b * Tq) * Cq + h * 64;
    int tid = threadIdx.x;
    int j = tid >> 2, rg = tid & 3;
    float uu = 0.f;
    if (tid < 64) uu = up[h * 64 + tid];
    float S[16];
    #pragma unroll
    for (int i = 0; i < 16; i++) S[i] = 0.f;

    float lk0 = 0.f, lr0 = 0.f, lw0 = 0.f, lv0 = 0.f;
    float lk1 = 0.f, lr1 = 0.f, lw1 = 0.f, lv1 = 0.f;
    if (tid < 64){
        size_t o0 = base + tid;
        lk0 = kp[o0]; lr0 = rp[o0]; lw0 = wp[o0]; lv0 = vp[o0];
        size_t o1 = o0 + Cq;
        lk1 = kp[o1]; lr1 = rp[o1]; lw1 = wp[o1]; lv1 = vp[o1];
    }

    for (int t = 0; t < Tq; t += 2) {
        int b0 = t & 3, b1 = (t + 1) & 3;
        size_t off = base + (size_t)t * Cq;
        if (tid < 64) {
            sv[b0][tid] = lv0;
            pk[b0][tid >> 4][tid & 15] = make_float4(lk0, uu * lk0, lr0, expf(-expf(lw0)));
            sv[b1][tid] = lv1;
            pk[b1][tid >> 4][tid & 15] = make_float4(lk1, uu * lk1, lr1, expf(-expf(lw1)));
        }
        __syncthreads();
        if (t + 2 < Tq && tid < 64){
            size_t o2 = off + 2 * Cq + tid;
            lk0 = kp[o2]; lr0 = rp[o2]; lw0 = wp[o2]; lv0 = vp[o2];
            size_t o3 = o2 + Cq;
            lk1 = kp[o3]; lr1 = rp[o3]; lw1 = wp[o3]; lv1 = vp[o3];
        }
        // step t
        {
            float vj = sv[b0][j];
            float yv0 = 0.f, yv1 = 0.f;
            #pragma unroll
            for (int ii = 0; ii < 8; ii++) {
                float4 p = pk[b0][rg][ii];
                float s = S[ii];
                yv0 = fmaf(p.z, fmaf(p.y, vj, s), yv0);
                S[ii] = fmaf(p.w, s, p.x * vj);
            }
            #pragma unroll
            for (int ii = 8; ii < 16; ii++) {
                float4 p = pk[b0][rg][ii];
                float s = S[ii];
                yv1 = fmaf(p.z, fmaf(p.y, vj, s), yv1);
                S[ii] = fmaf(p.w, s, p.x * vj);
            }
            float yv = yv0 + yv1;
            yv += __shfl_xor_sync(0xffffffffu, yv, 1);
            yv += __shfl_xor_sync(0xffffffffu, yv, 2);
            if (rg == 0) yp[off + j] = yv;
        }
        // step t+1
        {
            float vj = sv[b1][j];
            float yv0 = 0.f, yv1 = 0.f;
            #pragma unroll
            for (int ii = 0; ii < 8; ii++) {
                float4 p = pk[b1][rg][ii];
                float s = S[ii];
                yv0 = fmaf(p.z, fmaf(p.y, vj, s), yv0);
                S[ii] = fmaf(p.w, s, p.x * vj);
            }
            #pragma unroll
            for (int ii = 8; ii < 16; ii++) {
                float4 p = pk[b1][rg][ii];
                float s = S[ii];
                yv1 = fmaf(p.z, fmaf(p.y, vj, s), yv1);
                S[ii] = fmaf(p.w, s, p.x * vj);
            }
            float yv = yv0 + yv1;
            yv += __shfl_xor_sync(0xffffffffu, yv, 1);
            yv += __shfl_xor_sync(0xffffffffu, yv, 2);
            if (rg == 0) yp[off + Cq + j] = yv;
        }
    }
}

// ---------------------------------------------------------------------------
// GroupNorm * gate -> bf16 hi/lo (stores vectorized to STG.64)
// ---------------------------------------------------------------------------
__global__ void __launch_bounds__(256) gnorm_kernel(
    const float* __restrict__ y, const float* __restrict__ g,
    const float* __restrict__ gamma, const float* __restrict__ beta,
    __nv_bfloat16* __restrict__ ygh, __nv_bfloat16* __restrict__ ygl)
{
    int m = blockIdx.x, tid = threadIdx.x;
    size_t i4 = (size_t)m * 256 + tid;
    float4 yv = ((const float4*)y)[i4];
    float s  = yv.x + yv.y + yv.z + yv.w;
    float ss = yv.x*yv.x + yv.y*yv.y + yv.z*yv.z + yv.w*yv.w;
    #pragma unroll
    for (int o = 1; o < 16; o <<= 1) {
        s  += __shfl_xor_sync(0xffffffffu, s,  o);
        ss += __shfl_xor_sync(0xffffffffu, ss, o);
    }
    float mean = s * (1.f / 64.f);
    float var  = ss * (1.f / 64.f) - mean * mean;
    float rstd = rsqrtf(fmaxf(var, 0.f) + 1.6e-4f);
    float4 ga = ((const float4*)gamma)[tid];
    float4 be = ((const float4*)beta)[tid];
    float4 gv = ((const float4*)g)[i4];
    float o0 = ((yv.x - mean) * rstd * ga.x + be.x) * gv.x;
    float o1 = ((yv.y - mean) * rstd * ga.y + be.y) * gv.y;
    float o2 = ((yv.z - mean) * rstd * ga.z + be.z) * gv.z;
    float o3 = ((yv.w - mean) * rstd * ga.w + be.w) * gv.w;

    __nv_bfloat16 h[4], l[4];
    splitv(o0, h[0], l[0]); splitv(o1, h[1], l[1]);
    splitv(o2, h[2], l[2]); splitv(o3, h[3], l[3]);
    uint2 ph, pl;
    ph.x = (uint32_t)u16of(h[0]) | ((uint32_t)u16of(h[1]) << 16);
    ph.y = (uint32_t)u16of(h[2]) | ((uint32_t)u16of(h[3]) << 16);
    pl.x = (uint32_t)u16of(l[0]) | ((uint32_t)u16of(l[1]) << 16);
    pl.y = (uint32_t)u16of(l[2]) | ((uint32_t)u16of(l[3]) << 16);
    ((uint2*)ygh)[i4] = ph;
    ((uint2*)ygl)[i4] = pl;
}

// ---------------------------------------------------------------------------
// Launch
// ---------------------------------------------------------------------------
extern "C" void kernel_launch(void* const* d_in, const int* in_sizes, int n_in,
                              void* d_out, int out_size)
{
    (void)in_sizes; (void)n_in; (void)out_size;
    const float* x       = (const float*)d_in[0];
    const float* miu_x   = (const float*)d_in[1];
    const float* lambda_ = (const float*)d_in[2];
    const float* A_lora  = (const float*)d_in[3];
    const float* B_lora  = (const float*)d_in[4];
    const float* td_miu  = (const float*)d_in[5];
    const float* td_A    = (const float*)d_in[6];
    const float* td_B    = (const float*)d_in[7];
    const float* u       = (const float*)d_in[8];
    const float* Wr      = (const float*)d_in[9];
    const float* Wk      = (const float*)d_in[10];
    const float* Wv      = (const float*)d_in[11];
    const float* Wg      = (const float*)d_in[12];
    const float* Wo      = (const float*)d_in[13];
    const float* gamma   = (const float*)d_in[14];
    const float* beta    = (const float*)d_in[15];
    float* out = (float*)d_out;

    float *p_dxa,*p_k,*p_v,*p_r,*p_g,*p_w,*p_y,*p_lorap,*p_BloraT;
    __nv_bfloat16 *p_xmh,*p_xml,*p_abh,*p_abl,*p_ygh,*p_ygl,*p_wbh,*p_wbl,
                  *p_AloraTh,*p_AloraTl;
    __half *p_xx0h,*p_xx0l,*p_tdhh,*p_tdhl,*p_tdATh,*p_tdATl,*p_tdBTh,*p_tdBTl;
    { void* t;
      cudaGetSymbolAddress(&t, g_dxa);     p_dxa     = (float*)t;
      cudaGetSymbolAddress(&t, g_k);       p_k       = (float*)t;
      cudaGetSymbolAddress(&t, g_v);       p_v       = (float*)t;
      cudaGetSymbolAddress(&t, g_r);       p_r       = (float*)t;
      cudaGetSymbolAddress(&t, g_g);       p_g       = (float*)t;
      cudaGetSymbolAddress(&t, g_w);       p_w       = (float*)t;
      cudaGetSymbolAddress(&t, g_y);       p_y       = (float*)t;
      cudaGetSymbolAddress(&t, g_lorap);   p_lorap   = (float*)t;
      cudaGetSymbolAddress(&t, g_BloraT);  p_BloraT  = (float*)t;
      cudaGetSymbolAddress(&t, g_xmh);     p_xmh     = (__nv_bfloat16*)t;
      cudaGetSymbolAddress(&t, g_xml);     p_xml     = (__nv_bfloat16*)t;
      cudaGetSymbolAddress(&t, g_abh);     p_abh     = (__nv_bfloat16*)t;
      cudaGetSymbolAddress(&t, g_abl);     p_abl     = (__nv_bfloat16*)t;
      cudaGetSymbolAddress(&t, g_ygh);     p_ygh     = (__nv_bfloat16*)t;
      cudaGetSymbolAddress(&t, g_ygl);     p_ygl     = (__nv_bfloat16*)t;
      cudaGetSymbolAddress(&t, g_wbh);     p_wbh     = (__nv_bfloat16*)t;
      cudaGetSymbolAddress(&t, g_wbl);     p_wbl     = (__nv_bfloat16*)t;
      cudaGetSymbolAddress(&t, g_AloraTh); p_AloraTh = (__nv_bfloat16*)t;
      cudaGetSymbolAddress(&t, g_AloraTl); p_AloraTl = (__nv_bfloat16*)t;
      cudaGetSymbolAddress(&t, g_xx0h);    p_xx0h    = (__half*)t;
      cudaGetSymbolAddress(&t, g_xx0l);    p_xx0l    = (__half*)t;
      cudaGetSymbolAddress(&t, g_tdhh);    p_tdhh    = (__half*)t;
      cudaGetSymbolAddress(&t, g_tdhl);    p_tdhl    = (__half*)t;
      cudaGetSymbolAddress(&t, g_tdATh);   p_tdATh   = (__half*)t;
      cudaGetSymbolAddress(&t, g_tdATl);   p_tdATl   = (__half*)t;
      cudaGetSymbolAddress(&t, g_tdBTh);   p_tdBTh   = (__half*)t;
      cudaGetSymbolAddress(&t, g_tdBTl);   p_tdBTl   = (__half*)t;
    }

    cudaFuncSetAttribute(hgemm_one,  cudaFuncAttributeMaxDynamicSharedMemorySize, HG_SMEM);
    cudaFuncSetAttribute(hgemm_kvrg, cudaFuncAttributeMaxDynamicSharedMemorySize, HG_SMEM);
    cudaFuncSetAttribute(hgemm_h,    cudaFuncAttributeMaxDynamicSharedMemorySize, HG_SMEM);

    // 0: token shift + static lerp (xm -> bf16 hi/lo)
    prep_kernel<<<BTq * Cq / 4 / 256, 256>>>((const float4*)x, (const float4*)miu_x,
                                             (float4*)p_dxa, p_xmh, p_xml);
    // 1: weight transposes
    transpose_all<<<(622592 + 255) / 256, 256>>>(p_AloraTh, p_AloraTl, A_lora,
                                                 p_tdATh, p_tdATl, td_A,
                                                 p_tdBTh, p_tdBTl, td_B,
                                                 p_BloraT, B_lora);
    // 2: lora_h = tanh(xm @ A_lora)
    hgemm_one<<<dim3(2, 128), 256, HG_SMEM>>>(p_xmh, p_xml, p_AloraTh, p_AloraTl,
                                              p_lorap, 256, Cq, 2);
    // 3: ddlerp mix (f=0 -> fp16 hi/lo xx0; f=1..4 -> bf16 hi/lo k,v,r,g)
    mix_gemm<<<dim3(5, 128, 8), 256>>>(p_lorap, p_BloraT, x, p_dxa, lambda_,
                                       p_xx0h, p_xx0l, p_abh, p_abl);
    // 4: big weight hi/lo (float4 vectorized)
    wconv_kernel<<<5 * 1048576 / 1024, 256>>>(Wk, Wv, Wr, Wg, Wo, p_wbh, p_wbl);
    // 5: merged projections k, v, r, g
    hgemm_kvrg<<<dim3(8, 128, 4), 256, HG_SMEM>>>(p_abh, p_abl, p_wbh, p_wbl,
                                                  p_k, p_v, p_r, p_g);
    // 6: tdh = tanh(w_in @ td_A) -> fp16 hi/lo (padded N=128)
    hgemm_h<<<dim3(1, 128), 256, HG_SMEM>>>(p_xx0h, p_xx0l, p_tdATh, p_tdATl,
                                            nullptr, p_tdhh, p_tdhl, nullptr,
                                            128, Cq, Cq, Cq, 3);
    // 7: w = td_miu + tdh @ td_B   (A stride 128, K=64)
    hgemm_h<<<dim3(8, 128), 256, HG_SMEM>>>(p_tdhh, p_tdhl, p_tdBTh, p_tdBTl,
                                            p_w, nullptr, nullptr, td_miu,
                                            Cq, 64, 128, 64, 4);
    // 8: WKV6 scan
    wkv6_kernel<<<Bq * Hq, 256>>>(p_r, p_k, p_v, p_w, u, p_y);
    // 9: GroupNorm * gate -> bf16 hi/lo
    gnorm_kernel<<<BTq, 256>>>(p_y, p_g, gamma, beta, p_ygh, p_ygl);
    // 10: output projection
    hgemm_one<<<dim3(8, 128), 256, HG_SMEM>>>(p_ygh, p_ygl, p_wbh + 4*WWq, p_wbl + 4*WWq,
                                              out, Cq, Cq, 0);
}